// round 8
// baseline (speedup 1.0000x reference)
#include <cuda_runtime.h>
#include <cuda_bf16.h>
#include <math.h>
#include <stdint.h>

// Problem dims
#define S_  2048
#define B_  2
#define D_  1024
#define H_  16
#define DK_ 64
#define E_  8
#define F_  4096
#define T_  (S_*B_)          // 4096 tokens
#define OUT_TOTAL (T_*D_ + E_ + E_ + 1 + T_)

// ---------------- scratch (device globals) ----------------
__device__ float g_z1[T_*D_];
__device__ float g_qkv[(size_t)T_*3072];
__device__ float g_o [T_*D_];
__device__ float g_x2[T_*D_];
__device__ float g_z2[T_*D_];
__device__ __nv_bfloat16 g_z2b[T_*D_];
__device__ __nv_bfloat16 g_hb[(size_t)T_*F_];
__device__ uint32_t g_w1b[(size_t)E_*(D_/2)*F_];   // pair-interleaved bf16 words
__device__ uint32_t g_w2b[(size_t)E_*(F_/2)*D_];
__device__ float g_probs[T_*E_];
__device__ float g_pmax[T_];
__device__ int   g_etok[E_*T_];
__device__ int   g_ecount[E_];

__device__ __forceinline__ uint32_t f2tf32(float f) {
    uint32_t r; asm("cvt.rna.tf32.f32 %0, %1;" : "=r"(r) : "f"(f)); return r;
}
__device__ __forceinline__ uint32_t packbf(float lo, float hi) {
    __nv_bfloat162 t = __floats2bfloat162_rn(lo, hi);
    return *(uint32_t*)&t;
}
__device__ __forceinline__ float ex2f(float x) {
    float y; asm("ex2.approx.f32 %0, %1;" : "=f"(y) : "f"(x)); return y;
}
__device__ __forceinline__ void mma_bf16(float* c, const uint32_t* a, uint32_t b0, uint32_t b1) {
    asm volatile("mma.sync.aligned.m16n8k16.row.col.f32.bf16.bf16.f32 "
        "{%0,%1,%2,%3}, {%4,%5,%6,%7}, {%8,%9}, {%0,%1,%2,%3};"
        : "+f"(c[0]), "+f"(c[1]), "+f"(c[2]), "+f"(c[3])
        : "r"(a[0]), "r"(a[1]), "r"(a[2]), "r"(a[3]), "r"(b0), "r"(b1));
}
__device__ __forceinline__ void mma_tf32(float* c, const uint32_t* a, uint32_t b0, uint32_t b1) {
    asm volatile("mma.sync.aligned.m16n8k8.row.col.f32.tf32.tf32.f32 "
        "{%0,%1,%2,%3}, {%4,%5,%6,%7}, {%8,%9}, {%0,%1,%2,%3};"
        : "+f"(c[0]), "+f"(c[1]), "+f"(c[2]), "+f"(c[3])
        : "r"(a[0]), "r"(a[1]), "r"(a[2]), "r"(a[3]), "r"(b0), "r"(b1));
}
__device__ __forceinline__ uint32_t lds32(const char* p) {
    return *(const uint32_t*)p;
}
__device__ __forceinline__ uint32_t smem_u32(const void* p) {
    uint32_t a;
    asm("{ .reg .u64 t; cvta.to.shared.u64 t, %1; cvt.u32.u64 %0, t; }" : "=r"(a) : "l"(p));
    return a;
}
__device__ __forceinline__ void cpa16(uint32_t dst, const void* src) {
    asm volatile("cp.async.cg.shared.global [%0], [%1], 16;" :: "r"(dst), "l"(src));
}
__device__ __forceinline__ void cpa16p(uint32_t dst, const void* src, int sz) {
    asm volatile("cp.async.cg.shared.global [%0], [%1], 16, %2;" :: "r"(dst), "l"(src), "r"(sz));
}
#define CP_COMMIT() asm volatile("cp.async.commit_group;" ::: "memory")
#define CP_WAIT0()  asm volatile("cp.async.wait_group 0;" ::: "memory")
#define CP_WAIT1()  asm volatile("cp.async.wait_group 1;" ::: "memory")

// ---------------- init ----------------
__global__ void init_kernel() {
    int i = threadIdx.x;
    if (i < E_) g_ecount[i] = 0;
}

// ---------------- weight prep: fp32 [E][Kd][Nd] -> words [E][Kd/2][Nd] ----------------
__global__ void prep_w(const float* __restrict__ w, uint32_t* __restrict__ out,
                       int Kd, int Nd) {
    size_t total = (size_t)E_ * (Kd / 2) * Nd;
    size_t stride = (size_t)gridDim.x * blockDim.x;
    for (size_t i = (size_t)blockIdx.x * blockDim.x + threadIdx.x; i < total; i += stride) {
        size_t per_e = (size_t)(Kd / 2) * Nd;
        int e = (int)(i / per_e);
        size_t rem = i - (size_t)e * per_e;
        int kp = (int)(rem / Nd);
        int n  = (int)(rem - (size_t)kp * Nd);
        size_t in0 = ((size_t)e * Kd + 2 * kp) * Nd + n;
        out[i] = packbf(w[in0], w[in0 + Nd]);
    }
}

// ---------------- LayerNorm (fp32 out + optional bf16 out) ----------------
__global__ void ln_kernel(const float* __restrict__ x,
                          const float* __restrict__ gam,
                          const float* __restrict__ bet,
                          float* __restrict__ z,
                          __nv_bfloat16* __restrict__ zb) {
    int t = blockIdx.x;
    const float* row = x + (size_t)t * D_;
    __shared__ float red[256];
    __shared__ float stats[2];
    float s = 0.f, sq = 0.f;
    for (int i = threadIdx.x; i < D_; i += 256) {
        float v = row[i]; s += v; sq += v * v;
    }
    red[threadIdx.x] = s; __syncthreads();
    for (int o = 128; o; o >>= 1) { if (threadIdx.x < o) red[threadIdx.x] += red[threadIdx.x+o]; __syncthreads(); }
    if (threadIdx.x == 0) stats[0] = red[0];
    __syncthreads();
    red[threadIdx.x] = sq; __syncthreads();
    for (int o = 128; o; o >>= 1) { if (threadIdx.x < o) red[threadIdx.x] += red[threadIdx.x+o]; __syncthreads(); }
    if (threadIdx.x == 0) stats[1] = red[0];
    __syncthreads();
    float mean = stats[0] * (1.f / D_);
    float var  = stats[1] * (1.f / D_) - mean * mean;
    float inv  = rsqrtf(var + 1e-5f);
    for (int i = threadIdx.x; i < D_; i += 256) {
        float v = (row[i] - mean) * inv * gam[i] + bet[i];
        z[(size_t)t * D_ + i] = v;
        if (zb) zb[(size_t)t * D_ + i] = __float2bfloat16(v);
    }
}

// ---------------- unified 3-stage cp.async mma GEMM ----------------
// EB=4: A fp32 (tf32 truncation in MMA), B fp32 [K][Nb] raw words.
// EB=2: A bf16, B pair-interleaved bf16 words [K/2][Nb].
#define RB 80   // smem A row bytes
#define GEMM_SMEM (3*128*RB + 3*16*136*4)
template<int EB>
__global__ void __launch_bounds__(256, 2)
mma_gemm(const char* __restrict__ A,
         const uint32_t* __restrict__ W0, const uint32_t* __restrict__ W1, const uint32_t* __restrict__ W2,
         const float* __restrict__ bias0, const float* __restrict__ bias1, const float* __restrict__ bias2,
         const float* __restrict__ res, const float* __restrict__ rowscale,
         float* __restrict__ Cf, __nv_bfloat16* __restrict__ Cb,
         int M, int N, int Nb, int K,
         const int* __restrict__ gather, const int* __restrict__ gcount,
         int relu_flag) {
    constexpr int KC = (EB == 4) ? 16 : 32;   // k elems per chunk (64 A-bytes)
    extern __shared__ char dsm[];
    char* smA = dsm;                                   // [3][128][RB]
    uint32_t* smB = (uint32_t*)(dsm + 3 * 128 * RB);   // [3][16][136]

    int e  = blockIdx.z;
    int m0 = blockIdx.y * 128, n0 = blockIdx.x * 128;
    const uint32_t* W; const float* bias; int nb0;
    if (W1) {
        int part = n0 >> 10; nb0 = n0 & 1023;
        W    = part == 0 ? W0 : (part == 1 ? W1 : W2);
        bias = part == 0 ? bias0 : (part == 1 ? bias1 : bias2);
    } else { W = W0; bias = bias0; nb0 = n0; }
    const int* glist = nullptr; int mcnt = M;
    if (gather) {
        glist = gather + (size_t)e * T_;
        mcnt  = gcount[e];
        if (m0 >= mcnt) return;
        W    += (size_t)e * (K / 2) * Nb;   // gather path is always EB==2
        bias += (size_t)e * Nb;
    }
    int tid = threadIdx.x;
    int wid = tid >> 5, lane = tid & 31;

    int srow = tid >> 2, c4 = tid & 3;
    int rows[2] = { srow, srow + 64 };
    const char* aptr[2]; int asz[2];
    #pragma unroll
    for (int u = 0; u < 2; u++) {
        int rr = m0 + rows[u]; int tok = rr; asz[u] = 16;
        if (gather) { if (rr < mcnt) tok = glist[rr]; else { asz[u] = 0; tok = 0; } }
        aptr[u] = A + (size_t)tok * K * EB + c4 * 16;
    }
    const uint32_t* bbase = W + nb0 + lane * 4;

    int wm = wid & 3, wn = wid >> 2;
    int wr = wm * 32, wc = wn * 64;
    int gid = lane >> 2, tig = lane & 3;

    float acc[2][8][4];
    #pragma unroll
    for (int mt = 0; mt < 2; mt++)
        #pragma unroll
        for (int nt = 0; nt < 8; nt++)
            #pragma unroll
            for (int j = 0; j < 4; j++) acc[mt][nt][j] = 0.f;

    int nch = K / KC;
    uint32_t sA_a = smem_u32(smA), sB_a = smem_u32(smB);

    auto prefetch = [&](int i) {
        int buf = i % 3;
        size_t kb = (size_t)i * 64;
        uint32_t dA = sA_a + buf * 128 * RB;
        cpa16p(dA + rows[0] * RB + c4 * 16, aptr[0] + kb, asz[0]);
        cpa16p(dA + rows[1] * RB + c4 * 16, aptr[1] + kb, asz[1]);
        uint32_t dB = sB_a + buf * 16 * 136 * 4;
        const uint32_t* bs = bbase + (size_t)(i * 16 + wid) * Nb;
        cpa16(dB + (wid * 136 + lane * 4) * 4, bs);
        cpa16(dB + ((wid + 8) * 136 + lane * 4) * 4, bs + (size_t)8 * Nb);
        CP_COMMIT();
    };

    prefetch(0); prefetch(1);
    CP_WAIT1(); __syncthreads();

    for (int i = 0; i < nch; i++) {
        int buf = i % 3;
        if (i + 2 < nch) prefetch(i + 2);
        const uint32_t* bb = smB + buf * 16 * 136;
        const char* ab = smA + buf * 128 * RB;
        #pragma unroll
        for (int ks = 0; ks < 2; ks++) {
            uint32_t afr[2][4];
            int kb0 = (EB == 2) ? (ks * 16 + tig * 2) * 2 : (ks * 8 + tig) * 4;
            #pragma unroll
            for (int mt = 0; mt < 2; mt++) {
                const char* ap = &ab[(wr + mt * 16 + gid) * RB + kb0];
                afr[mt][0] = lds32(ap);
                afr[mt][1] = lds32(ap + 8 * RB);
                afr[mt][2] = lds32(ap + 16);
                afr[mt][3] = lds32(ap + 8 * RB + 16);
            }
            int krow = ks * 8 + tig;
            #pragma unroll
            for (int nt = 0; nt < 8; nt++) {
                uint32_t b0 = bb[krow * 136 + wc + nt * 8 + gid];
                uint32_t b1 = bb[(krow + 4) * 136 + wc + nt * 8 + gid];
                if (EB == 2) { mma_bf16(acc[0][nt], afr[0], b0, b1); mma_bf16(acc[1][nt], afr[1], b0, b1); }
                else         { mma_tf32(acc[0][nt], afr[0], b0, b1); mma_tf32(acc[1][nt], afr[1], b0, b1); }
            }
        }
        if (i + 1 < nch) {
            if (i + 2 < nch) { CP_WAIT1(); } else { CP_WAIT0(); }
            __syncthreads();
        }
    }

    // epilogue
    #pragma unroll
    for (int mt = 0; mt < 2; mt++) {
        #pragma unroll
        for (int half = 0; half < 2; half++) {
            int r = m0 + wr + mt * 16 + gid + half * 8;
            int tok = r; bool valid = true;
            if (gather) { if (r < mcnt) tok = glist[r]; else valid = false; }
            if (!valid) continue;
            float sc = rowscale ? rowscale[tok] : 1.f;
            size_t ob = (size_t)tok * N;
            #pragma unroll
            for (int nt = 0; nt < 8; nt++) {
                int c  = n0 + wc + nt * 8 + tig * 2;
                int cb = nb0 + wc + nt * 8 + tig * 2;
                float v0 = acc[mt][nt][half * 2 + 0] + bias[cb];
                float v1 = acc[mt][nt][half * 2 + 1] + bias[cb + 1];
                if (relu_flag) { v0 = fmaxf(v0, 0.f); v1 = fmaxf(v1, 0.f); }
                v0 *= sc; v1 *= sc;
                if (res) { v0 += res[ob + c]; v1 += res[ob + c + 1]; }
                if (Cb) {
                    Cb[ob + c]     = __float2bfloat16(v0);
                    Cb[ob + c + 1] = __float2bfloat16(v1);
                } else {
                    Cf[ob + c]     = v0;
                    Cf[ob + c + 1] = v1;
                }
            }
        }
    }
}

// ---------------- flash attention: tf32 mma, no-max softmax, cp.async K/V ----------------
#define QS_  68
#define VS_  72
#define ATTN_SMEM ((128*QS_ + 2*64*QS_ + 2*64*VS_) * 4)
__global__ void __launch_bounds__(256, 2)
attn_mma(const float* __restrict__ qkv, float* __restrict__ o) {
    extern __shared__ uint32_t sm[];
    uint32_t* pS = sm;                    // [128][QS_] (Q staging, then P)
    uint32_t* kS = pS + 128 * QS_;        // [2][64][QS_]
    uint32_t* vS = kS + 2 * 64 * QS_;     // [2][64][VS_]

    int bh = blockIdx.y;
    int b = bh % B_, h = bh / B_;
    int s0 = blockIdx.x * 128;
    int tid = threadIdx.x, lane = tid & 31, wid = tid >> 5;
    int gid = lane >> 2, tig = lane & 3;
    int wr = wid * 16;
    const float SC2 = 0.125f * 1.44269504f;   // scale * log2(e); p = 2^(s*SC2)

    uint32_t pS_a = smem_u32(pS), kS_a = smem_u32(kS), vS_a = smem_u32(vS);

    // prologue: cp.async Q + K/V tile 0
    {
        int qr = tid >> 1, qseg = tid & 1;
        const float* qp = qkv + (size_t)((s0 + qr) * B_ + b) * 3072 + h * DK_ + qseg * 32;
        #pragma unroll
        for (int j = 0; j < 8; j++)
            cpa16(pS_a + (qr * QS_ + qseg * 32 + j * 4) * 4, qp + j * 4);
    }
    int kr = tid >> 2, kseg = tid & 3;
    auto prefetchKV = [&](int i) {
        int buf = i & 1;
        const float* base = qkv + (size_t)((i * 64 + kr) * B_ + b) * 3072 + h * DK_ + kseg * 16;
        #pragma unroll
        for (int j = 0; j < 4; j++) {
            cpa16(kS_a + ((buf * 64 + kr) * QS_ + kseg * 16 + j * 4) * 4, base + 1024 + j * 4);
            cpa16(vS_a + ((buf * 64 + kr) * VS_ + kseg * 16 + j * 4) * 4, base + 2048 + j * 4);
        }
        CP_COMMIT();
    };
    prefetchKV(0);
    CP_WAIT0(); __syncthreads();

    // extract Q fragments (rna tf32)
    uint32_t qf[8][4];
    #pragma unroll
    for (int kk = 0; kk < 8; kk++) {
        const uint32_t* ar = &pS[(wr + gid) * QS_ + kk * 8 + tig];
        qf[kk][0] = f2tf32(__uint_as_float(ar[0]));
        qf[kk][1] = f2tf32(__uint_as_float(ar[8 * QS_]));
        qf[kk][2] = f2tf32(__uint_as_float(ar[4]));
        qf[kk][3] = f2tf32(__uint_as_float(ar[8 * QS_ + 4]));
    }

    float oacc[8][4];
    #pragma unroll
    for (int dt = 0; dt < 8; dt++)
        #pragma unroll
        for (int j = 0; j < 4; j++) oacc[dt][j] = 0.f;
    float l0 = 0.f, l1 = 0.f;    // per-thread partial softmax denominators
    uint32_t* pw = pS + wid * 16 * QS_;

    const int NT = S_ / 64;
    for (int i = 0; i < NT; i++) {
        int buf = i & 1;
        bool more = (i + 1 < NT);
        if (more) prefetchKV(i + 1);
        const uint32_t* kb = kS + buf * 64 * QS_;
        const uint32_t* vb = vS + buf * 64 * VS_;

        // scores 16x64
        float sc[8][4];
        #pragma unroll
        for (int nt = 0; nt < 8; nt++)
            #pragma unroll
            for (int j = 0; j < 4; j++) sc[nt][j] = 0.f;
        #pragma unroll
        for (int kk = 0; kk < 8; kk++) {
            #pragma unroll
            for (int nt = 0; nt < 8; nt++) {
                const uint32_t* br = &kb[(nt * 8 + gid) * QS_ + kk * 8 + tig];
                mma_tf32(sc[nt], qf[kk], br[0], br[4]);
            }
        }

        // no-max softmax: p = 2^(s*SC2); accumulate per-thread l
        #pragma unroll
        for (int nt = 0; nt < 8; nt++) {
            float p0 = ex2f(sc[nt][0] * SC2);
            float p1 = ex2f(sc[nt][1] * SC2);
            float p2 = ex2f(sc[nt][2] * SC2);
            float p3 = ex2f(sc[nt][3] * SC2);
            l0 += p0 + p1; l1 += p2 + p3;
            int c = nt * 8 + tig * 2;
            *(uint2*)&pw[gid * QS_ + c]       = make_uint2(f2tf32(p0), f2tf32(p1));
            *(uint2*)&pw[(gid + 8) * QS_ + c] = make_uint2(f2tf32(p2), f2tf32(p3));
        }
        __syncwarp();

        // P @ V
        #pragma unroll
        for (int kk = 0; kk < 8; kk++) {
            uint32_t a[4];
            const uint32_t* ar = &pw[gid * QS_ + kk * 8 + tig];
            a[0] = ar[0]; a[1] = ar[8 * QS_]; a[2] = ar[4]; a[3] = ar[8 * QS_ + 4];
            int krow = kk * 8 + tig;
            #pragma unroll
            for (int dt = 0; dt < 8; dt++) {
                uint32_t b0 = vb[krow * VS_ + dt * 8 + gid];
                uint32_t b1 = vb[(krow + 4) * VS_ + dt * 8 + gid];
                mma_tf32(oacc[dt], a, b0, b1);
            }
        }
        if (more) { CP_WAIT0(); __syncthreads(); }
        else __syncwarp();
    }

    // final l reduction (4 threads per row share tig)
    l0 += __shfl_xor_sync(0xffffffffu, l0, 1);
    l0 += __shfl_xor_sync(0xffffffffu, l0, 2);
    l1 += __shfl_xor_sync(0xffffffffu, l1, 1);
    l1 += __shfl_xor_sync(0xffffffffu, l1, 2);

    // write O
    float inv0 = 1.f / l0, inv1 = 1.f / l1;
    int r0 = s0 + wr + gid, r1 = r0 + 8;
    size_t o0 = (size_t)(r0 * B_ + b) * D_ + h * DK_;
    size_t o1 = (size_t)(r1 * B_ + b) * D_ + h * DK_;
    #pragma unroll
    for (int dt = 0; dt < 8; dt++) {
        int c = dt * 8 + tig * 2;
        o[o0 + c]     = oacc[dt][0] * inv0;
        o[o0 + c + 1] = oacc[dt][1] * inv0;
        o[o1 + c]     = oacc[dt][2] * inv1;
        o[o1 + c + 1] = oacc[dt][3] * inv1;
    }
}

// ---------------- gate / routing ----------------
__global__ void gate_kernel(const float* __restrict__ z,
                            const float* __restrict__ wg,
                            const float* __restrict__ bg) {
    int t = blockIdx.x;
    int tid = threadIdx.x;
    int w = tid >> 5, lane = tid & 31;
    __shared__ float lg[E_];
    const float* row = z + (size_t)t * D_;
    float s = 0.f;
    for (int i = lane; i < D_; i += 32) s += row[i] * wg[i * E_ + w];
    #pragma unroll
    for (int off = 16; off; off >>= 1) s += __shfl_down_sync(0xffffffffu, s, off);
    if (lane == 0) lg[w] = s + bg[w];
    __syncthreads();
    if (tid == 0) {
        float mx = lg[0]; int am = 0;
        #pragma unroll
        for (int e = 1; e < E_; e++) if (lg[e] > mx) { mx = lg[e]; am = e; }
        float pr[E_], sum = 0.f;
        #pragma unroll
        for (int e = 0; e < E_; e++) { pr[e] = expf(lg[e] - mx); sum += pr[e]; }
        float inv = 1.f / sum;
        #pragma unroll
        for (int e = 0; e < E_; e++) g_probs[t * E_ + e] = pr[e] * inv;
        g_pmax[t] = pr[am] * inv;
        int pos = atomicAdd(&g_ecount[am], 1);
        g_etok[am * T_ + pos] = t;
    }
}

// ---------------- route_prob_sum (deterministic) ----------------
__global__ void rps_kernel(float* __restrict__ dout, int out_size) {
    int e = blockIdx.x;
    __shared__ float red[256];
    float s = 0.f;
    for (int t = threadIdx.x; t < T_; t += 256) s += g_probs[t * E_ + e];
    red[threadIdx.x] = s; __syncthreads();
    for (int o = 128; o; o >>= 1) { if (threadIdx.x < o) red[threadIdx.x] += red[threadIdx.x+o]; __syncthreads(); }
    if (threadIdx.x == 0 && out_size >= OUT_TOTAL) dout[(size_t)T_ * D_ + E_ + e] = red[0];
}

// ---------------- tail outputs ----------------
__global__ void tail_kernel(float* __restrict__ dout, int out_size) {
    if (out_size < OUT_TOTAL) return;
    int i = blockIdx.x * blockDim.x + threadIdx.x;
    size_t base = (size_t)T_ * D_;
    if (i < E_) dout[base + i] = (float)g_ecount[i];
    if (i == 0) dout[base + 2 * E_] = 0.f;
    if (i < T_) dout[base + 2 * E_ + 1 + i] = g_pmax[i];
}

// ---------------- launch ----------------
extern "C" void kernel_launch(void* const* d_in, const int* in_sizes, int n_in,
                              void* d_out, int out_size) {
    const float* x      = (const float*)d_in[0];
    const float* ln1_g  = (const float*)d_in[1];
    const float* ln1_b  = (const float*)d_in[2];
    const float* ln2_g  = (const float*)d_in[3];
    const float* ln2_b  = (const float*)d_in[4];
    const float* wq     = (const float*)d_in[5];
    const float* bq     = (const float*)d_in[6];
    const float* wk     = (const float*)d_in[7];
    const float* bk     = (const float*)d_in[8];
    const float* wv     = (const float*)d_in[9];
    const float* bv     = (const float*)d_in[10];
    const float* wo     = (const float*)d_in[11];
    const float* bo     = (const float*)d_in[12];
    const float* w_gate = (const float*)d_in[13];
    const float* b_gate = (const float*)d_in[14];
    const float* w1     = (const float*)d_in[15];
    const float* b1     = (const float*)d_in[16];
    const float* w2     = (const float*)d_in[17];
    const float* b2     = (const float*)d_in[18];
    float* out = (float*)d_out;

    float *z1, *qkv, *o, *x2, *z2, *pmaxp;
    __nv_bfloat16 *z2b, *hb;
    uint32_t *w1b, *w2b;
    int *etok, *ecount;
    cudaGetSymbolAddress((void**)&z1,  g_z1);
    cudaGetSymbolAddress((void**)&qkv, g_qkv);
    cudaGetSymbolAddress((void**)&o,   g_o);
    cudaGetSymbolAddress((void**)&x2,  g_x2);
    cudaGetSymbolAddress((void**)&z2,  g_z2);
    cudaGetSymbolAddress((void**)&z2b, g_z2b);
    cudaGetSymbolAddress((void**)&hb,  g_hb);
    cudaGetSymbolAddress((void**)&w1b, g_w1b);
    cudaGetSymbolAddress((void**)&w2b, g_w2b);
    cudaGetSymbolAddress((void**)&etok,   g_etok);
    cudaGetSymbolAddress((void**)&ecount, g_ecount);
    cudaGetSymbolAddress((void**)&pmaxp,  g_pmax);

    cudaFuncSetAttribute(attn_mma, cudaFuncAttributeMaxDynamicSharedMemorySize, ATTN_SMEM);
    cudaFuncSetAttribute(mma_gemm<4>, cudaFuncAttributeMaxDynamicSharedMemorySize, GEMM_SMEM);
    cudaFuncSetAttribute(mma_gemm<2>, cudaFuncAttributeMaxDynamicSharedMemorySize, GEMM_SMEM);

    init_kernel<<<1, 32>>>();

    // MoE weight prep (fp32 -> pair-interleaved bf16 words)
    prep_w<<<4096, 256>>>(w1, w1b, D_, F_);
    prep_w<<<4096, 256>>>(w2, w2b, F_, D_);

    // LN1
    ln_kernel<<<T_, 256>>>(x, ln1_g, ln1_b, z1, nullptr);

    // fused QKV projection (tf32 cp.async)
    mma_gemm<4><<<dim3(3072/128, T_/128, 1), 256, GEMM_SMEM>>>(
        (const char*)z1, (const uint32_t*)wq, (const uint32_t*)wk, (const uint32_t*)wv,
        bq, bk, bv, nullptr, nullptr, qkv, nullptr, T_, 3072, D_, D_, nullptr, nullptr, 0);

    // attention
    attn_mma<<<dim3(S_/128, B_*H_), 256, ATTN_SMEM>>>(qkv, o);

    // output projection + residual (tf32 cp.async)
    mma_gemm<4><<<dim3(D_/128, T_/128, 1), 256, GEMM_SMEM>>>(
        (const char*)o, (const uint32_t*)wo, nullptr, nullptr,
        bo, nullptr, nullptr, x, nullptr, x2, nullptr, T_, D_, D_, D_, nullptr, nullptr, 0);

    // LN2
    ln_kernel<<<T_, 256>>>(x2, ln2_g, ln2_b, z2, z2b);

    // gate + routing
    gate_kernel<<<T_, 256>>>(z2, w_gate, b_gate);

    // MoE FFN (grouped by expert, bf16 cp.async)
    mma_gemm<2><<<dim3(F_/128, T_/128, E_), 256, GEMM_SMEM>>>(
        (const char*)z2b, w1b, nullptr, nullptr, b1, nullptr, nullptr,
        nullptr, nullptr, nullptr, hb, T_, F_, F_, D_, etok, ecount, 1);
    mma_gemm<2><<<dim3(D_/128, T_/128, E_), 256, GEMM_SMEM>>>(
        (const char*)hb, w2b, nullptr, nullptr, b2, nullptr, nullptr,
        x2, pmaxp, out, nullptr, T_, D_, D_, F_, etok, ecount, 0);

    // aux outputs
    rps_kernel<<<E_, 256>>>(out, out_size);
    tail_kernel<<<(T_ + 255) / 256, 256>>>(out, out_size);
}

// round 9
// speedup vs baseline: 1.1008x; 1.1008x over previous
#include <cuda_runtime.h>
#include <cuda_bf16.h>
#include <math.h>
#include <stdint.h>

// Problem dims
#define S_  2048
#define B_  2
#define D_  1024
#define H_  16
#define DK_ 64
#define E_  8
#define F_  4096
#define T_  (S_*B_)          // 4096 tokens
#define OUT_TOTAL (T_*D_ + E_ + E_ + 1 + T_)

// ---------------- scratch (device globals) ----------------
__device__ float g_z1[T_*D_];
__device__ float g_qkv[(size_t)T_*3072];
__device__ float g_o [T_*D_];
__device__ float g_x2[T_*D_];
__device__ float g_z2[T_*D_];
__device__ __nv_bfloat16 g_z2b[T_*D_];
__device__ __nv_bfloat16 g_hb[(size_t)T_*F_];
__device__ float g_probs[T_*E_];
__device__ float g_pmax[T_];
__device__ int   g_etok[E_*T_];
__device__ int   g_ecount[E_];

__device__ __forceinline__ uint32_t f2tf32(float f) {
    uint32_t r; asm("cvt.rna.tf32.f32 %0, %1;" : "=r"(r) : "f"(f)); return r;
}
__device__ __forceinline__ uint32_t packbf(float lo, float hi) {
    __nv_bfloat162 t = __floats2bfloat162_rn(lo, hi);
    return *(uint32_t*)&t;
}
__device__ __forceinline__ float ex2f(float x) {
    float y; asm("ex2.approx.f32 %0, %1;" : "=f"(y) : "f"(x)); return y;
}
__device__ __forceinline__ void mma_bf16(float* c, const uint32_t* a, uint32_t b0, uint32_t b1) {
    asm volatile("mma.sync.aligned.m16n8k16.row.col.f32.bf16.bf16.f32 "
        "{%0,%1,%2,%3}, {%4,%5,%6,%7}, {%8,%9}, {%0,%1,%2,%3};"
        : "+f"(c[0]), "+f"(c[1]), "+f"(c[2]), "+f"(c[3])
        : "r"(a[0]), "r"(a[1]), "r"(a[2]), "r"(a[3]), "r"(b0), "r"(b1));
}
__device__ __forceinline__ void mma_tf32(float* c, const uint32_t* a, uint32_t b0, uint32_t b1) {
    asm volatile("mma.sync.aligned.m16n8k8.row.col.f32.tf32.tf32.f32 "
        "{%0,%1,%2,%3}, {%4,%5,%6,%7}, {%8,%9}, {%0,%1,%2,%3};"
        : "+f"(c[0]), "+f"(c[1]), "+f"(c[2]), "+f"(c[3])
        : "r"(a[0]), "r"(a[1]), "r"(a[2]), "r"(a[3]), "r"(b0), "r"(b1));
}
__device__ __forceinline__ uint32_t lds32(const char* p) {
    return *(const uint32_t*)p;
}
__device__ __forceinline__ uint32_t smem_u32(const void* p) {
    uint32_t a;
    asm("{ .reg .u64 t; cvta.to.shared.u64 t, %1; cvt.u32.u64 %0, t; }" : "=r"(a) : "l"(p));
    return a;
}
__device__ __forceinline__ void cpa16(uint32_t dst, const void* src) {
    asm volatile("cp.async.cg.shared.global [%0], [%1], 16;" :: "r"(dst), "l"(src));
}
#define CP_COMMIT() asm volatile("cp.async.commit_group;" ::: "memory")
#define CP_WAIT0()  asm volatile("cp.async.wait_group 0;" ::: "memory")

// ---------------- init ----------------
__global__ void init_kernel() {
    int i = threadIdx.x;
    if (i < E_) g_ecount[i] = 0;
}

// ---------------- LayerNorm (warp-shuffle reduction) ----------------
__global__ void ln_kernel(const float* __restrict__ x,
                          const float* __restrict__ gam,
                          const float* __restrict__ bet,
                          float* __restrict__ z,
                          __nv_bfloat16* __restrict__ zb) {
    int t = blockIdx.x;
    const float* row = x + (size_t)t * D_;
    __shared__ float wsum[8], wsq[8];
    int tid = threadIdx.x, lane = tid & 31, wid = tid >> 5;
    float s = 0.f, sq = 0.f;
    #pragma unroll
    for (int i = 0; i < 4; i++) {
        float v = row[tid + i * 256];
        s += v; sq += v * v;
    }
    #pragma unroll
    for (int off = 16; off; off >>= 1) {
        s  += __shfl_xor_sync(0xffffffffu, s,  off);
        sq += __shfl_xor_sync(0xffffffffu, sq, off);
    }
    if (lane == 0) { wsum[wid] = s; wsq[wid] = sq; }
    __syncthreads();
    float ts = 0.f, tq = 0.f;
    #pragma unroll
    for (int w = 0; w < 8; w++) { ts += wsum[w]; tq += wsq[w]; }
    float mean = ts * (1.f / D_);
    float var  = tq * (1.f / D_) - mean * mean;
    float inv  = rsqrtf(var + 1e-5f);
    #pragma unroll
    for (int i = 0; i < 4; i++) {
        int c = tid + i * 256;
        float v = (row[c] - mean) * inv * gam[c] + bet[c];
        z[(size_t)t * D_ + c] = v;
        if (zb) zb[(size_t)t * D_ + c] = __float2bfloat16(v);
    }
}

// ---------------- mma.sync GEMM (R7-proven) ----------------
#define RB 80   // smem A row bytes
template<int EB>
__global__ void __launch_bounds__(256)
mma_gemm(const char* __restrict__ A,
         const float* __restrict__ B0, const float* __restrict__ B1, const float* __restrict__ B2,
         const float* __restrict__ bias0, const float* __restrict__ bias1, const float* __restrict__ bias2,
         const float* __restrict__ res, const float* __restrict__ rowscale,
         float* __restrict__ Cf, __nv_bfloat16* __restrict__ Cb,
         int M, int N, int Nb, int K,
         const int* __restrict__ gather, const int* __restrict__ gcount,
         int relu_flag) {
    constexpr int KC = (EB == 4) ? 16 : 32;
    __shared__ __align__(16) char smA[2][128 * RB];
    __shared__ __align__(16) uint32_t smB[2][16 * 136];

    int e  = blockIdx.z;
    int m0 = blockIdx.y * 128, n0 = blockIdx.x * 128;
    const float* Bsrc; const float* bias; int nb0;
    if (B1) {
        int part = n0 >> 10; nb0 = n0 & 1023;
        Bsrc = part == 0 ? B0 : (part == 1 ? B1 : B2);
        bias = part == 0 ? bias0 : (part == 1 ? bias1 : bias2);
    } else { Bsrc = B0; bias = bias0; nb0 = n0; }
    const int* glist = nullptr; int mcnt = M;
    if (gather) {
        glist = gather + (size_t)e * T_;
        mcnt  = gcount[e];
        if (m0 >= mcnt) return;
        Bsrc += (size_t)e * K * Nb;
        bias += (size_t)e * Nb;
    }
    int tid = threadIdx.x;
    int wid = tid >> 5, lane = tid & 31;

    int srow = tid >> 2, c4 = tid & 3;
    int rows[2] = { srow, srow + 64 };
    const char* aptr[2]; bool aval[2];
    #pragma unroll
    for (int u = 0; u < 2; u++) {
        int rr = m0 + rows[u]; int tok = rr; aval[u] = true;
        if (gather) { if (rr < mcnt) tok = glist[rr]; else { aval[u] = false; tok = 0; } }
        aptr[u] = A + (size_t)tok * K * EB + c4 * 16;
    }
    const float* bbase = Bsrc + nb0 + lane * 4;

    int wm = wid & 3, wn = wid >> 2;
    int wr = wm * 32, wc = wn * 64;
    int gid = lane >> 2, tig = lane & 3;

    float acc[2][8][4];
    #pragma unroll
    for (int mt = 0; mt < 2; mt++)
        #pragma unroll
        for (int nt = 0; nt < 8; nt++)
            #pragma unroll
            for (int j = 0; j < 4; j++) acc[mt][nt][j] = 0.f;

    int nch = K / KC;

    if (EB == 4) {
        uint32_t sA[2], sB[2];
        sA[0] = smem_u32(&smA[0][0]); sA[1] = smem_u32(&smA[1][0]);
        sB[0] = smem_u32(&smB[0][0]); sB[1] = smem_u32(&smB[1][0]);
        auto prefetch = [&](int i) {
            int buf = i & 1;
            size_t kb = (size_t)i * 64;
            cpa16(sA[buf] + rows[0] * RB + c4 * 16, aptr[0] + kb);
            cpa16(sA[buf] + rows[1] * RB + c4 * 16, aptr[1] + kb);
            int k0 = i * KC;
            cpa16(sB[buf] + (wid * 136 + lane * 4) * 4,       bbase + (size_t)(k0 + wid) * Nb);
            cpa16(sB[buf] + ((wid + 8) * 136 + lane * 4) * 4, bbase + (size_t)(k0 + wid + 8) * Nb);
            CP_COMMIT();
        };
        prefetch(0);
        CP_WAIT0(); __syncthreads();
        for (int i = 0; i < nch; i++) {
            int buf = i & 1;
            bool more = (i + 1 < nch);
            if (more) prefetch(i + 1);
            const uint32_t* bb = smB[buf];
            #pragma unroll
            for (int ks = 0; ks < 2; ks++) {
                uint32_t afr[2][4];
                int kb0 = (ks * 8 + tig) * 4;
                #pragma unroll
                for (int mt = 0; mt < 2; mt++) {
                    const char* ap = &smA[buf][(wr + mt * 16 + gid) * RB + kb0];
                    afr[mt][0] = lds32(ap);
                    afr[mt][1] = lds32(ap + 8 * RB);
                    afr[mt][2] = lds32(ap + 16);
                    afr[mt][3] = lds32(ap + 8 * RB + 16);
                }
                int krow = ks * 8 + tig;
                #pragma unroll
                for (int nt = 0; nt < 8; nt++) {
                    uint32_t b0 = bb[krow * 136 + wc + nt * 8 + gid];
                    uint32_t b1 = bb[(krow + 4) * 136 + wc + nt * 8 + gid];
                    mma_tf32(acc[0][nt], afr[0], b0, b1);
                    mma_tf32(acc[1][nt], afr[1], b0, b1);
                }
            }
            if (more) { CP_WAIT0(); __syncthreads(); }
        }
    } else {
        uint4 ra[2]; float4 rb[4];
        auto loadA = [&](int i) {
            size_t kb = (size_t)i * 64;
            #pragma unroll
            for (int u = 0; u < 2; u++)
                ra[u] = aval[u] ? *(const uint4*)(aptr[u] + kb) : make_uint4(0,0,0,0);
        };
        auto loadB = [&](int i) {
            int k0 = i * KC;
            rb[0] = *(const float4*)(bbase + (size_t)(k0 + 2*wid) * Nb);
            rb[1] = *(const float4*)(bbase + (size_t)(k0 + 2*wid + 1) * Nb);
            rb[2] = *(const float4*)(bbase + (size_t)(k0 + 2*(wid+8)) * Nb);
            rb[3] = *(const float4*)(bbase + (size_t)(k0 + 2*(wid+8) + 1) * Nb);
        };
        auto storeAB = [&](int buf) {
            #pragma unroll
            for (int u = 0; u < 2; u++)
                *(uint4*)&smA[buf][rows[u] * RB + c4 * 16] = ra[u];
            *(uint4*)&smB[buf][wid * 136 + lane * 4] =
                make_uint4(packbf(rb[0].x, rb[1].x), packbf(rb[0].y, rb[1].y),
                           packbf(rb[0].z, rb[1].z), packbf(rb[0].w, rb[1].w));
            *(uint4*)&smB[buf][(wid + 8) * 136 + lane * 4] =
                make_uint4(packbf(rb[2].x, rb[3].x), packbf(rb[2].y, rb[3].y),
                           packbf(rb[2].z, rb[3].z), packbf(rb[2].w, rb[3].w));
        };
        loadA(0); loadB(0); storeAB(0);
        __syncthreads();
        for (int i = 0; i < nch; i++) {
            int buf = i & 1;
            bool more = (i + 1 < nch);
            if (more) { loadA(i + 1); loadB(i + 1); }
            const uint32_t* bb = smB[buf];
            #pragma unroll
            for (int ks = 0; ks < 2; ks++) {
                uint32_t afr[2][4];
                int kb0 = (ks * 16 + tig * 2) * 2;
                #pragma unroll
                for (int mt = 0; mt < 2; mt++) {
                    const char* ap = &smA[buf][(wr + mt * 16 + gid) * RB + kb0];
                    afr[mt][0] = lds32(ap);
                    afr[mt][1] = lds32(ap + 8 * RB);
                    afr[mt][2] = lds32(ap + 16);
                    afr[mt][3] = lds32(ap + 8 * RB + 16);
                }
                int krow = ks * 8 + tig;
                #pragma unroll
                for (int nt = 0; nt < 8; nt++) {
                    uint32_t b0 = bb[krow * 136 + wc + nt * 8 + gid];
                    uint32_t b1 = bb[(krow + 4) * 136 + wc + nt * 8 + gid];
                    mma_bf16(acc[0][nt], afr[0], b0, b1);
                    mma_bf16(acc[1][nt], afr[1], b0, b1);
                }
            }
            if (more) storeAB(buf ^ 1);
            __syncthreads();
        }
    }

    // epilogue
    #pragma unroll
    for (int mt = 0; mt < 2; mt++) {
        #pragma unroll
        for (int half = 0; half < 2; half++) {
            int r = m0 + wr + mt * 16 + gid + half * 8;
            int tok = r; bool valid = true;
            if (gather) { if (r < mcnt) tok = glist[r]; else valid = false; }
            if (!valid) continue;
            float sc = rowscale ? rowscale[tok] : 1.f;
            size_t ob = (size_t)tok * N;
            #pragma unroll
            for (int nt = 0; nt < 8; nt++) {
                int c  = n0 + wc + nt * 8 + tig * 2;
                int cb = nb0 + wc + nt * 8 + tig * 2;
                float v0 = acc[mt][nt][half * 2 + 0] + bias[cb];
                float v1 = acc[mt][nt][half * 2 + 1] + bias[cb + 1];
                if (relu_flag) { v0 = fmaxf(v0, 0.f); v1 = fmaxf(v1, 0.f); }
                v0 *= sc; v1 *= sc;
                if (res) { v0 += res[ob + c]; v1 += res[ob + c + 1]; }
                if (Cb) {
                    Cb[ob + c]     = __float2bfloat16(v0);
                    Cb[ob + c + 1] = __float2bfloat16(v1);
                } else {
                    Cf[ob + c]     = v0;
                    Cf[ob + c + 1] = v1;
                }
            }
        }
    }
}

// ---------------- flash attention: tf32 mma, no-max softmax, cp.async K/V ----------------
#define QS_  68
#define VS_  72
#define ATTN_SMEM ((128*QS_ + 2*64*QS_ + 2*64*VS_) * 4)
__global__ void __launch_bounds__(256, 2)
attn_mma(const float* __restrict__ qkv, float* __restrict__ o) {
    extern __shared__ uint32_t sm[];
    uint32_t* pS = sm;                    // [128][QS_] (Q staging, then P)
    uint32_t* kS = pS + 128 * QS_;        // [2][64][QS_]
    uint32_t* vS = kS + 2 * 64 * QS_;     // [2][64][VS_]

    int bh = blockIdx.y;
    int b = bh % B_, h = bh / B_;
    int s0 = blockIdx.x * 128;
    int tid = threadIdx.x, lane = tid & 31, wid = tid >> 5;
    int gid = lane >> 2, tig = lane & 3;
    int wr = wid * 16;
    const float SC2 = 0.125f * 1.44269504f;   // scale * log2(e)

    uint32_t pS_a = smem_u32(pS), kS_a = smem_u32(kS), vS_a = smem_u32(vS);

    // prologue: cp.async Q + K/V tile 0
    {
        int qr = tid >> 1, qseg = tid & 1;
        const float* qp = qkv + (size_t)((s0 + qr) * B_ + b) * 3072 + h * DK_ + qseg * 32;
        #pragma unroll
        for (int j = 0; j < 8; j++)
            cpa16(pS_a + (qr * QS_ + qseg * 32 + j * 4) * 4, qp + j * 4);
    }
    int kr = tid >> 2, kseg = tid & 3;
    auto prefetchKV = [&](int i) {
        int buf = i & 1;
        const float* base = qkv + (size_t)((i * 64 + kr) * B_ + b) * 3072 + h * DK_ + kseg * 16;
        #pragma unroll
        for (int j = 0; j < 4; j++) {
            cpa16(kS_a + ((buf * 64 + kr) * QS_ + kseg * 16 + j * 4) * 4, base + 1024 + j * 4);
            cpa16(vS_a + ((buf * 64 + kr) * VS_ + kseg * 16 + j * 4) * 4, base + 2048 + j * 4);
        }
        CP_COMMIT();
    };
    prefetchKV(0);
    CP_WAIT0(); __syncthreads();

    // extract Q fragments (rna tf32)
    uint32_t qf[8][4];
    #pragma unroll
    for (int kk = 0; kk < 8; kk++) {
        const uint32_t* ar = &pS[(wr + gid) * QS_ + kk * 8 + tig];
        qf[kk][0] = f2tf32(__uint_as_float(ar[0]));
        qf[kk][1] = f2tf32(__uint_as_float(ar[8 * QS_]));
        qf[kk][2] = f2tf32(__uint_as_float(ar[4]));
        qf[kk][3] = f2tf32(__uint_as_float(ar[8 * QS_ + 4]));
    }

    float oacc[8][4];
    #pragma unroll
    for (int dt = 0; dt < 8; dt++)
        #pragma unroll
        for (int j = 0; j < 4; j++) oacc[dt][j] = 0.f;
    float l0 = 0.f, l1 = 0.f;    // per-thread partial denominators
    uint32_t* pw = pS + wid * 16 * QS_;

    const int NT = S_ / 64;
    for (int i = 0; i < NT; i++) {
        int buf = i & 1;
        bool more = (i + 1 < NT);
        if (more) prefetchKV(i + 1);
        const uint32_t* kb = kS + buf * 64 * QS_;
        const uint32_t* vb = vS + buf * 64 * VS_;

        // scores 16x64
        float sc[8][4];
        #pragma unroll
        for (int nt = 0; nt < 8; nt++)
            #pragma unroll
            for (int j = 0; j < 4; j++) sc[nt][j] = 0.f;
        #pragma unroll
        for (int kk = 0; kk < 8; kk++) {
            #pragma unroll
            for (int nt = 0; nt < 8; nt++) {
                const uint32_t* br = &kb[(nt * 8 + gid) * QS_ + kk * 8 + tig];
                mma_tf32(sc[nt], qf[kk], br[0], br[4]);
            }
        }

        // no-max softmax: p = 2^(s*SC2)
        #pragma unroll
        for (int nt = 0; nt < 8; nt++) {
            float p0 = ex2f(sc[nt][0] * SC2);
            float p1 = ex2f(sc[nt][1] * SC2);
            float p2 = ex2f(sc[nt][2] * SC2);
            float p3 = ex2f(sc[nt][3] * SC2);
            l0 += p0 + p1; l1 += p2 + p3;
            int c = nt * 8 + tig * 2;
            *(uint2*)&pw[gid * QS_ + c]       = make_uint2(f2tf32(p0), f2tf32(p1));
            *(uint2*)&pw[(gid + 8) * QS_ + c] = make_uint2(f2tf32(p2), f2tf32(p3));
        }
        __syncwarp();

        // P @ V
        #pragma unroll
        for (int kk = 0; kk < 8; kk++) {
            uint32_t a[4];
            const uint32_t* ar = &pw[gid * QS_ + kk * 8 + tig];
            a[0] = ar[0]; a[1] = ar[8 * QS_]; a[2] = ar[4]; a[3] = ar[8 * QS_ + 4];
            int krow = kk * 8 + tig;
            #pragma unroll
            for (int dt = 0; dt < 8; dt++) {
                uint32_t b0 = vb[krow * VS_ + dt * 8 + gid];
                uint32_t b1 = vb[(krow + 4) * VS_ + dt * 8 + gid];
                mma_tf32(oacc[dt], a, b0, b1);
            }
        }
        if (more) { CP_WAIT0(); __syncthreads(); }
        else __syncwarp();
    }

    // final l reduction (4 threads per row)
    l0 += __shfl_xor_sync(0xffffffffu, l0, 1);
    l0 += __shfl_xor_sync(0xffffffffu, l0, 2);
    l1 += __shfl_xor_sync(0xffffffffu, l1, 1);
    l1 += __shfl_xor_sync(0xffffffffu, l1, 2);

    // write O
    float inv0 = 1.f / l0, inv1 = 1.f / l1;
    int r0 = s0 + wr + gid, r1 = r0 + 8;
    size_t o0 = (size_t)(r0 * B_ + b) * D_ + h * DK_;
    size_t o1 = (size_t)(r1 * B_ + b) * D_ + h * DK_;
    #pragma unroll
    for (int dt = 0; dt < 8; dt++) {
        int c = dt * 8 + tig * 2;
        o[o0 + c]     = oacc[dt][0] * inv0;
        o[o0 + c + 1] = oacc[dt][1] * inv0;
        o[o1 + c]     = oacc[dt][2] * inv1;
        o[o1 + c + 1] = oacc[dt][3] * inv1;
    }
}

// ---------------- gate / routing ----------------
__global__ void gate_kernel(const float* __restrict__ z,
                            const float* __restrict__ wg,
                            const float* __restrict__ bg) {
    int t = blockIdx.x;
    int tid = threadIdx.x;
    int w = tid >> 5, lane = tid & 31;
    __shared__ float lg[E_];
    const float* row = z + (size_t)t * D_;
    float s = 0.f;
    for (int i = lane; i < D_; i += 32) s += row[i] * wg[i * E_ + w];
    #pragma unroll
    for (int off = 16; off; off >>= 1) s += __shfl_down_sync(0xffffffffu, s, off);
    if (lane == 0) lg[w] = s + bg[w];
    __syncthreads();
    if (tid == 0) {
        float mx = lg[0]; int am = 0;
        #pragma unroll
        for (int e = 1; e < E_; e++) if (lg[e] > mx) { mx = lg[e]; am = e; }
        float pr[E_], sum = 0.f;
        #pragma unroll
        for (int e = 0; e < E_; e++) { pr[e] = expf(lg[e] - mx); sum += pr[e]; }
        float inv = 1.f / sum;
        #pragma unroll
        for (int e = 0; e < E_; e++) g_probs[t * E_ + e] = pr[e] * inv;
        g_pmax[t] = pr[am] * inv;
        int pos = atomicAdd(&g_ecount[am], 1);
        g_etok[am * T_ + pos] = t;
    }
}

// ---------------- route_prob_sum (deterministic) ----------------
__global__ void rps_kernel(float* __restrict__ dout, int out_size) {
    int e = blockIdx.x;
    __shared__ float red[256];
    float s = 0.f;
    for (int t = threadIdx.x; t < T_; t += 256) s += g_probs[t * E_ + e];
    red[threadIdx.x] = s; __syncthreads();
    for (int o = 128; o; o >>= 1) { if (threadIdx.x < o) red[threadIdx.x] += red[threadIdx.x+o]; __syncthreads(); }
    if (threadIdx.x == 0 && out_size >= OUT_TOTAL) dout[(size_t)T_ * D_ + E_ + e] = red[0];
}

// ---------------- tail outputs ----------------
__global__ void tail_kernel(float* __restrict__ dout, int out_size) {
    if (out_size < OUT_TOTAL) return;
    int i = blockIdx.x * blockDim.x + threadIdx.x;
    size_t base = (size_t)T_ * D_;
    if (i < E_) dout[base + i] = (float)g_ecount[i];
    if (i == 0) dout[base + 2 * E_] = 0.f;
    if (i < T_) dout[base + 2 * E_ + 1 + i] = g_pmax[i];
}

// ---------------- launch ----------------
extern "C" void kernel_launch(void* const* d_in, const int* in_sizes, int n_in,
                              void* d_out, int out_size) {
    const float* x      = (const float*)d_in[0];
    const float* ln1_g  = (const float*)d_in[1];
    const float* ln1_b  = (const float*)d_in[2];
    const float* ln2_g  = (const float*)d_in[3];
    const float* ln2_b  = (const float*)d_in[4];
    const float* wq     = (const float*)d_in[5];
    const float* bq     = (const float*)d_in[6];
    const float* wk     = (const float*)d_in[7];
    const float* bk     = (const float*)d_in[8];
    const float* wv     = (const float*)d_in[9];
    const float* bv     = (const float*)d_in[10];
    const float* wo     = (const float*)d_in[11];
    const float* bo     = (const float*)d_in[12];
    const float* w_gate = (const float*)d_in[13];
    const float* b_gate = (const float*)d_in[14];
    const float* w1     = (const float*)d_in[15];
    const float* b1     = (const float*)d_in[16];
    const float* w2     = (const float*)d_in[17];
    const float* b2     = (const float*)d_in[18];
    float* out = (float*)d_out;

    float *z1, *qkv, *o, *x2, *z2, *pmaxp;
    __nv_bfloat16 *z2b, *hb;
    int *etok, *ecount;
    cudaGetSymbolAddress((void**)&z1,  g_z1);
    cudaGetSymbolAddress((void**)&qkv, g_qkv);
    cudaGetSymbolAddress((void**)&o,   g_o);
    cudaGetSymbolAddress((void**)&x2,  g_x2);
    cudaGetSymbolAddress((void**)&z2,  g_z2);
    cudaGetSymbolAddress((void**)&z2b, g_z2b);
    cudaGetSymbolAddress((void**)&hb,  g_hb);
    cudaGetSymbolAddress((void**)&etok,   g_etok);
    cudaGetSymbolAddress((void**)&ecount, g_ecount);
    cudaGetSymbolAddress((void**)&pmaxp,  g_pmax);

    cudaFuncSetAttribute(attn_mma, cudaFuncAttributeMaxDynamicSharedMemorySize, ATTN_SMEM);

    init_kernel<<<1, 32>>>();

    // LN1
    ln_kernel<<<T_, 256>>>(x, ln1_g, ln1_b, z1, nullptr);

    // fused QKV projection (tf32 cp.async)
    mma_gemm<4><<<dim3(3072/128, T_/128, 1), 256>>>(
        (const char*)z1, wq, wk, wv, bq, bk, bv,
        nullptr, nullptr, qkv, nullptr, T_, 3072, D_, D_, nullptr, nullptr, 0);

    // attention
    attn_mma<<<dim3(S_/128, B_*H_), 256, ATTN_SMEM>>>(qkv, o);

    // output projection + residual (tf32 cp.async)
    mma_gemm<4><<<dim3(D_/128, T_/128, 1), 256>>>(
        (const char*)o, wo, nullptr, nullptr, bo, nullptr, nullptr,
        x, nullptr, x2, nullptr, T_, D_, D_, D_, nullptr, nullptr, 0);

    // LN2
    ln_kernel<<<T_, 256>>>(x2, ln2_g, ln2_b, z2, z2b);

    // gate + routing
    gate_kernel<<<T_, 256>>>(z2, w_gate, b_gate);

    // MoE FFN (grouped by expert, bf16)
    mma_gemm<2><<<dim3(F_/128, T_/128, E_), 256>>>(
        (const char*)z2b, w1, nullptr, nullptr, b1, nullptr, nullptr,
        nullptr, nullptr, nullptr, hb, T_, F_, F_, D_, etok, ecount, 1);
    mma_gemm<2><<<dim3(D_/128, T_/128, E_), 256>>>(
        (const char*)hb, w2, nullptr, nullptr, b2, nullptr, nullptr,
        x2, pmaxp, out, nullptr, T_, D_, D_, F_, etok, ecount, 0);

    // aux outputs
    rps_kernel<<<E_, 256>>>(out, out_size);
    tail_kernel<<<(T_ + 255) / 256, 256>>>(out, out_size);
}

// round 10
// speedup vs baseline: 1.1473x; 1.0423x over previous
#include <cuda_runtime.h>
#include <cuda_bf16.h>
#include <math.h>
#include <stdint.h>

// Problem dims
#define S_  2048
#define B_  2
#define D_  1024
#define H_  16
#define DK_ 64
#define E_  8
#define F_  4096
#define T_  (S_*B_)          // 4096 tokens
#define OUT_TOTAL (T_*D_ + E_ + E_ + 1 + T_)

// ---------------- scratch (device globals) ----------------
__device__ float g_z1[T_*D_];
__device__ float g_qkv[(size_t)T_*3072];
__device__ __nv_bfloat16 g_kb[T_*D_];    // bf16 K mirror [t][h*64+d]
__device__ float g_o [T_*D_];
__device__ float g_x2[T_*D_];
__device__ float g_z2[T_*D_];
__device__ __nv_bfloat16 g_z2b[T_*D_];
__device__ __nv_bfloat16 g_hb[(size_t)T_*F_];
__device__ float g_probs[T_*E_];
__device__ float g_pmax[T_];
__device__ int   g_etok[E_*T_];
__device__ int   g_ecount[E_];

__device__ __forceinline__ uint32_t f2tf32(float f) {
    uint32_t r; asm("cvt.rna.tf32.f32 %0, %1;" : "=r"(r) : "f"(f)); return r;
}
__device__ __forceinline__ uint32_t packbf(float lo, float hi) {
    __nv_bfloat162 t = __floats2bfloat162_rn(lo, hi);
    return *(uint32_t*)&t;
}
__device__ __forceinline__ float ex2f(float x) {
    float y; asm("ex2.approx.f32 %0, %1;" : "=f"(y) : "f"(x)); return y;
}
__device__ __forceinline__ void mma_bf16(float* c, const uint32_t* a, uint32_t b0, uint32_t b1) {
    asm volatile("mma.sync.aligned.m16n8k16.row.col.f32.bf16.bf16.f32 "
        "{%0,%1,%2,%3}, {%4,%5,%6,%7}, {%8,%9}, {%0,%1,%2,%3};"
        : "+f"(c[0]), "+f"(c[1]), "+f"(c[2]), "+f"(c[3])
        : "r"(a[0]), "r"(a[1]), "r"(a[2]), "r"(a[3]), "r"(b0), "r"(b1));
}
__device__ __forceinline__ void mma_tf32(float* c, const uint32_t* a, uint32_t b0, uint32_t b1) {
    asm volatile("mma.sync.aligned.m16n8k8.row.col.f32.tf32.tf32.f32 "
        "{%0,%1,%2,%3}, {%4,%5,%6,%7}, {%8,%9}, {%0,%1,%2,%3};"
        : "+f"(c[0]), "+f"(c[1]), "+f"(c[2]), "+f"(c[3])
        : "r"(a[0]), "r"(a[1]), "r"(a[2]), "r"(a[3]), "r"(b0), "r"(b1));
}
__device__ __forceinline__ uint32_t lds32(const char* p) {
    return *(const uint32_t*)p;
}
__device__ __forceinline__ uint32_t smem_u32(const void* p) {
    uint32_t a;
    asm("{ .reg .u64 t; cvta.to.shared.u64 t, %1; cvt.u32.u64 %0, t; }" : "=r"(a) : "l"(p));
    return a;
}
__device__ __forceinline__ void cpa16(uint32_t dst, const void* src) {
    asm volatile("cp.async.cg.shared.global [%0], [%1], 16;" :: "r"(dst), "l"(src));
}
#define CP_COMMIT() asm volatile("cp.async.commit_group;" ::: "memory")
#define CP_WAIT0()  asm volatile("cp.async.wait_group 0;" ::: "memory")

// ---------------- init ----------------
__global__ void init_kernel() {
    int i = threadIdx.x;
    if (i < E_) g_ecount[i] = 0;
}

// ---------------- LayerNorm (warp-shuffle reduction) ----------------
__global__ void ln_kernel(const float* __restrict__ x,
                          const float* __restrict__ gam,
                          const float* __restrict__ bet,
                          float* __restrict__ z,
                          __nv_bfloat16* __restrict__ zb) {
    int t = blockIdx.x;
    const float* row = x + (size_t)t * D_;
    __shared__ float wsum[8], wsq[8];
    int tid = threadIdx.x, lane = tid & 31, wid = tid >> 5;
    float s = 0.f, sq = 0.f;
    #pragma unroll
    for (int i = 0; i < 4; i++) {
        float v = row[tid + i * 256];
        s += v; sq += v * v;
    }
    #pragma unroll
    for (int off = 16; off; off >>= 1) {
        s  += __shfl_xor_sync(0xffffffffu, s,  off);
        sq += __shfl_xor_sync(0xffffffffu, sq, off);
    }
    if (lane == 0) { wsum[wid] = s; wsq[wid] = sq; }
    __syncthreads();
    float ts = 0.f, tq = 0.f;
    #pragma unroll
    for (int w = 0; w < 8; w++) { ts += wsum[w]; tq += wsq[w]; }
    float mean = ts * (1.f / D_);
    float var  = tq * (1.f / D_) - mean * mean;
    float inv  = rsqrtf(var + 1e-5f);
    #pragma unroll
    for (int i = 0; i < 4; i++) {
        int c = tid + i * 256;
        float v = (row[c] - mean) * inv * gam[c] + bet[c];
        z[(size_t)t * D_ + c] = v;
        if (zb) zb[(size_t)t * D_ + c] = __float2bfloat16(v);
    }
}

// ---------------- mma.sync GEMM ----------------
#define RB 80   // smem A row bytes
template<int EB>
__global__ void __launch_bounds__(256)
mma_gemm(const char* __restrict__ A,
         const float* __restrict__ B0, const float* __restrict__ B1, const float* __restrict__ B2,
         const float* __restrict__ bias0, const float* __restrict__ bias1, const float* __restrict__ bias2,
         const float* __restrict__ res, const float* __restrict__ rowscale,
         float* __restrict__ Cf, __nv_bfloat16* __restrict__ Cb,
         __nv_bfloat16* __restrict__ kmir,      // bf16 K mirror (QKV mode, part 1)
         int M, int N, int Nb, int K,
         const int* __restrict__ gather, const int* __restrict__ gcount,
         int relu_flag) {
    constexpr int KC = (EB == 4) ? 16 : 32;
    __shared__ __align__(16) char smA[2][128 * RB];
    __shared__ __align__(16) uint32_t smB[2][16 * 136];

    int e  = blockIdx.z;
    int m0 = blockIdx.y * 128, n0 = blockIdx.x * 128;
    const float* Bsrc; const float* bias; int nb0; int part = 0;
    if (B1) {
        part = n0 >> 10; nb0 = n0 & 1023;
        Bsrc = part == 0 ? B0 : (part == 1 ? B1 : B2);
        bias = part == 0 ? bias0 : (part == 1 ? bias1 : bias2);
    } else { Bsrc = B0; bias = bias0; nb0 = n0; }
    const int* glist = nullptr; int mcnt = M;
    if (gather) {
        glist = gather + (size_t)e * T_;
        mcnt  = gcount[e];
        if (m0 >= mcnt) return;
        Bsrc += (size_t)e * K * Nb;
        bias += (size_t)e * Nb;
    }
    int tid = threadIdx.x;
    int wid = tid >> 5, lane = tid & 31;

    int srow = tid >> 2, c4 = tid & 3;
    int rows[2] = { srow, srow + 64 };
    const char* aptr[2]; bool aval[2];
    #pragma unroll
    for (int u = 0; u < 2; u++) {
        int rr = m0 + rows[u]; int tok = rr; aval[u] = true;
        if (gather) { if (rr < mcnt) tok = glist[rr]; else { aval[u] = false; tok = 0; } }
        aptr[u] = A + (size_t)tok * K * EB + c4 * 16;
    }
    const float* bbase = Bsrc + nb0 + lane * 4;

    int wm = wid & 3, wn = wid >> 2;
    int wr = wm * 32, wc = wn * 64;
    int gid = lane >> 2, tig = lane & 3;

    float acc[2][8][4];
    #pragma unroll
    for (int mt = 0; mt < 2; mt++)
        #pragma unroll
        for (int nt = 0; nt < 8; nt++)
            #pragma unroll
            for (int j = 0; j < 4; j++) acc[mt][nt][j] = 0.f;

    int nch = K / KC;

    if (EB == 4) {
        uint32_t sA[2], sB[2];
        sA[0] = smem_u32(&smA[0][0]); sA[1] = smem_u32(&smA[1][0]);
        sB[0] = smem_u32(&smB[0][0]); sB[1] = smem_u32(&smB[1][0]);
        auto prefetch = [&](int i) {
            int buf = i & 1;
            size_t kb = (size_t)i * 64;
            cpa16(sA[buf] + rows[0] * RB + c4 * 16, aptr[0] + kb);
            cpa16(sA[buf] + rows[1] * RB + c4 * 16, aptr[1] + kb);
            int k0 = i * KC;
            cpa16(sB[buf] + (wid * 136 + lane * 4) * 4,       bbase + (size_t)(k0 + wid) * Nb);
            cpa16(sB[buf] + ((wid + 8) * 136 + lane * 4) * 4, bbase + (size_t)(k0 + wid + 8) * Nb);
            CP_COMMIT();
        };
        prefetch(0);
        CP_WAIT0(); __syncthreads();
        for (int i = 0; i < nch; i++) {
            int buf = i & 1;
            bool more = (i + 1 < nch);
            if (more) prefetch(i + 1);
            const uint32_t* bb = smB[buf];
            #pragma unroll
            for (int ks = 0; ks < 2; ks++) {
                uint32_t afr[2][4];
                int kb0 = (ks * 8 + tig) * 4;
                #pragma unroll
                for (int mt = 0; mt < 2; mt++) {
                    const char* ap = &smA[buf][(wr + mt * 16 + gid) * RB + kb0];
                    afr[mt][0] = lds32(ap);
                    afr[mt][1] = lds32(ap + 8 * RB);
                    afr[mt][2] = lds32(ap + 16);
                    afr[mt][3] = lds32(ap + 8 * RB + 16);
                }
                int krow = ks * 8 + tig;
                #pragma unroll
                for (int nt = 0; nt < 8; nt++) {
                    uint32_t b0 = bb[krow * 136 + wc + nt * 8 + gid];
                    uint32_t b1 = bb[(krow + 4) * 136 + wc + nt * 8 + gid];
                    mma_tf32(acc[0][nt], afr[0], b0, b1);
                    mma_tf32(acc[1][nt], afr[1], b0, b1);
                }
            }
            if (more) { CP_WAIT0(); __syncthreads(); }
        }
    } else {
        uint4 ra[2]; float4 rb[4];
        auto loadA = [&](int i) {
            size_t kb = (size_t)i * 64;
            #pragma unroll
            for (int u = 0; u < 2; u++)
                ra[u] = aval[u] ? *(const uint4*)(aptr[u] + kb) : make_uint4(0,0,0,0);
        };
        auto loadB = [&](int i) {
            int k0 = i * KC;
            rb[0] = *(const float4*)(bbase + (size_t)(k0 + 2*wid) * Nb);
            rb[1] = *(const float4*)(bbase + (size_t)(k0 + 2*wid + 1) * Nb);
            rb[2] = *(const float4*)(bbase + (size_t)(k0 + 2*(wid+8)) * Nb);
            rb[3] = *(const float4*)(bbase + (size_t)(k0 + 2*(wid+8) + 1) * Nb);
        };
        auto storeAB = [&](int buf) {
            #pragma unroll
            for (int u = 0; u < 2; u++)
                *(uint4*)&smA[buf][rows[u] * RB + c4 * 16] = ra[u];
            *(uint4*)&smB[buf][wid * 136 + lane * 4] =
                make_uint4(packbf(rb[0].x, rb[1].x), packbf(rb[0].y, rb[1].y),
                           packbf(rb[0].z, rb[1].z), packbf(rb[0].w, rb[1].w));
            *(uint4*)&smB[buf][(wid + 8) * 136 + lane * 4] =
                make_uint4(packbf(rb[2].x, rb[3].x), packbf(rb[2].y, rb[3].y),
                           packbf(rb[2].z, rb[3].z), packbf(rb[2].w, rb[3].w));
        };
        loadA(0); loadB(0); storeAB(0);
        __syncthreads();
        for (int i = 0; i < nch; i++) {
            int buf = i & 1;
            bool more = (i + 1 < nch);
            if (more) { loadA(i + 1); loadB(i + 1); }
            const uint32_t* bb = smB[buf];
            #pragma unroll
            for (int ks = 0; ks < 2; ks++) {
                uint32_t afr[2][4];
                int kb0 = (ks * 16 + tig * 2) * 2;
                #pragma unroll
                for (int mt = 0; mt < 2; mt++) {
                    const char* ap = &smA[buf][(wr + mt * 16 + gid) * RB + kb0];
                    afr[mt][0] = lds32(ap);
                    afr[mt][1] = lds32(ap + 8 * RB);
                    afr[mt][2] = lds32(ap + 16);
                    afr[mt][3] = lds32(ap + 8 * RB + 16);
                }
                int krow = ks * 8 + tig;
                #pragma unroll
                for (int nt = 0; nt < 8; nt++) {
                    uint32_t b0 = bb[krow * 136 + wc + nt * 8 + gid];
                    uint32_t b1 = bb[(krow + 4) * 136 + wc + nt * 8 + gid];
                    mma_bf16(acc[0][nt], afr[0], b0, b1);
                    mma_bf16(acc[1][nt], afr[1], b0, b1);
                }
            }
            if (more) storeAB(buf ^ 1);
            __syncthreads();
        }
    }

    // epilogue
    bool do_kmir = (kmir != nullptr) && (part == 1);
    #pragma unroll
    for (int mt = 0; mt < 2; mt++) {
        #pragma unroll
        for (int half = 0; half < 2; half++) {
            int r = m0 + wr + mt * 16 + gid + half * 8;
            int tok = r; bool valid = true;
            if (gather) { if (r < mcnt) tok = glist[r]; else valid = false; }
            if (!valid) continue;
            float sc = rowscale ? rowscale[tok] : 1.f;
            size_t ob = (size_t)tok * N;
            #pragma unroll
            for (int nt = 0; nt < 8; nt++) {
                int c  = n0 + wc + nt * 8 + tig * 2;
                int cb = nb0 + wc + nt * 8 + tig * 2;
                float v0 = acc[mt][nt][half * 2 + 0] + bias[cb];
                float v1 = acc[mt][nt][half * 2 + 1] + bias[cb + 1];
                if (relu_flag) { v0 = fmaxf(v0, 0.f); v1 = fmaxf(v1, 0.f); }
                v0 *= sc; v1 *= sc;
                if (res) { v0 += res[ob + c]; v1 += res[ob + c + 1]; }
                if (Cb) {
                    Cb[ob + c]     = __float2bfloat16(v0);
                    Cb[ob + c + 1] = __float2bfloat16(v1);
                } else {
                    Cf[ob + c]     = v0;
                    Cf[ob + c + 1] = v1;
                }
                if (do_kmir) {
                    __nv_bfloat162 kp = __floats2bfloat162_rn(v0, v1);
                    *(__nv_bfloat162*)&kmir[(size_t)tok * D_ + cb] = kp;
                }
            }
        }
    }
}

// ---------------- flash attention: bf16 QK^T + tf32 PV, no-max softmax ----------------
#define QS_  68
#define KSW_ 40    // bf16 K tile: 32 data words + 8 pad (stride%32==8, conflict-free)
#define VS_  72
#define ATTN_SMEM ((128*QS_ + 2*64*KSW_ + 2*64*VS_) * 4)
__global__ void __launch_bounds__(256, 2)
attn_mma(const float* __restrict__ qkv, const __nv_bfloat16* __restrict__ kbg,
         float* __restrict__ o) {
    extern __shared__ uint32_t sm[];
    uint32_t* pS = sm;                    // [128][QS_] (Q staging fp32, then P tf32)
    uint32_t* kS = pS + 128 * QS_;        // [2][64][KSW_] bf16-packed
    uint32_t* vS = kS + 2 * 64 * KSW_;    // [2][64][VS_] fp32

    int bh = blockIdx.y;
    int b = bh % B_, h = bh / B_;
    int s0 = blockIdx.x * 128;
    int tid = threadIdx.x, lane = tid & 31, wid = tid >> 5;
    int gid = lane >> 2, tig = lane & 3;
    int wr = wid * 16;
    const float SC2 = 0.125f * 1.44269504f;   // scale * log2(e)

    uint32_t pS_a = smem_u32(pS), kS_a = smem_u32(kS), vS_a = smem_u32(vS);

    // prologue: cp.async Q (fp32) + K(bf16)/V(fp32) tile 0
    {
        int qr = tid >> 1, qseg = tid & 1;
        const float* qp = qkv + (size_t)((s0 + qr) * B_ + b) * 3072 + h * DK_ + qseg * 32;
        #pragma unroll
        for (int j = 0; j < 8; j++)
            cpa16(pS_a + (qr * QS_ + qseg * 32 + j * 4) * 4, qp + j * 4);
    }
    int kr = tid >> 2, kseg = tid & 3;
    auto prefetchKV = [&](int i) {
        int buf = i & 1;
        int t = (i * 64 + kr) * B_ + b;
        const __nv_bfloat16* kp = kbg + (size_t)t * D_ + h * DK_ + kseg * 16;   // 16 bf16 = 32B
        #pragma unroll
        for (int j = 0; j < 2; j++)
            cpa16(kS_a + ((buf * 64 + kr) * KSW_ + kseg * 8 + j * 4) * 4, (const char*)kp + j * 16);
        const float* vp = qkv + (size_t)t * 3072 + 2048 + h * DK_ + kseg * 16;
        #pragma unroll
        for (int j = 0; j < 4; j++)
            cpa16(vS_a + ((buf * 64 + kr) * VS_ + kseg * 16 + j * 4) * 4, vp + j * 4);
        CP_COMMIT();
    };
    prefetchKV(0);
    CP_WAIT0(); __syncthreads();

    // extract Q fragments as bf16 pairs (4 k-chunks of 16)
    uint32_t qfb[4][4];
    #pragma unroll
    for (int kk = 0; kk < 4; kk++) {
        const uint32_t* r0 = &pS[(wr + gid) * QS_ + kk * 16];
        const uint32_t* r1 = &pS[(wr + gid + 8) * QS_ + kk * 16];
        float q00 = __uint_as_float(r0[tig * 2]),     q01 = __uint_as_float(r0[tig * 2 + 1]);
        float q10 = __uint_as_float(r1[tig * 2]),     q11 = __uint_as_float(r1[tig * 2 + 1]);
        float q02 = __uint_as_float(r0[8 + tig * 2]), q03 = __uint_as_float(r0[8 + tig * 2 + 1]);
        float q12 = __uint_as_float(r1[8 + tig * 2]), q13 = __uint_as_float(r1[8 + tig * 2 + 1]);
        qfb[kk][0] = packbf(q00, q01);
        qfb[kk][1] = packbf(q10, q11);
        qfb[kk][2] = packbf(q02, q03);
        qfb[kk][3] = packbf(q12, q13);
    }

    float oacc[8][4];
    #pragma unroll
    for (int dt = 0; dt < 8; dt++)
        #pragma unroll
        for (int j = 0; j < 4; j++) oacc[dt][j] = 0.f;
    float l0 = 0.f, l1 = 0.f;
    uint32_t* pw = pS + wid * 16 * QS_;

    const int NT = S_ / 64;
    for (int i = 0; i < NT; i++) {
        int buf = i & 1;
        bool more = (i + 1 < NT);
        if (more) prefetchKV(i + 1);
        const uint32_t* kb = kS + buf * 64 * KSW_;
        const uint32_t* vb = vS + buf * 64 * VS_;

        // scores 16x64 via bf16 m16n8k16 (4 k-chunks)
        float sc[8][4];
        #pragma unroll
        for (int nt = 0; nt < 8; nt++)
            #pragma unroll
            for (int j = 0; j < 4; j++) sc[nt][j] = 0.f;
        #pragma unroll
        for (int kk = 0; kk < 4; kk++) {
            #pragma unroll
            for (int nt = 0; nt < 8; nt++) {
                const uint32_t* br = &kb[(nt * 8 + gid) * KSW_ + kk * 8 + tig];
                mma_bf16(sc[nt], qfb[kk], br[0], br[4]);
            }
        }

        // no-max softmax: p = 2^(s*SC2)
        #pragma unroll
        for (int nt = 0; nt < 8; nt++) {
            float p0 = ex2f(sc[nt][0] * SC2);
            float p1 = ex2f(sc[nt][1] * SC2);
            float p2 = ex2f(sc[nt][2] * SC2);
            float p3 = ex2f(sc[nt][3] * SC2);
            l0 += p0 + p1; l1 += p2 + p3;
            int c = nt * 8 + tig * 2;
            *(uint2*)&pw[gid * QS_ + c]       = make_uint2(f2tf32(p0), f2tf32(p1));
            *(uint2*)&pw[(gid + 8) * QS_ + c] = make_uint2(f2tf32(p2), f2tf32(p3));
        }
        __syncwarp();

        // P @ V (tf32)
        #pragma unroll
        for (int kk = 0; kk < 8; kk++) {
            uint32_t a[4];
            const uint32_t* ar = &pw[gid * QS_ + kk * 8 + tig];
            a[0] = ar[0]; a[1] = ar[8 * QS_]; a[2] = ar[4]; a[3] = ar[8 * QS_ + 4];
            int krow = kk * 8 + tig;
            #pragma unroll
            for (int dt = 0; dt < 8; dt++) {
                uint32_t b0 = vb[krow * VS_ + dt * 8 + gid];
                uint32_t b1 = vb[(krow + 4) * VS_ + dt * 8 + gid];
                mma_tf32(oacc[dt], a, b0, b1);
            }
        }
        if (more) { CP_WAIT0(); __syncthreads(); }
        else __syncwarp();
    }

    // final l reduction (4 threads per row)
    l0 += __shfl_xor_sync(0xffffffffu, l0, 1);
    l0 += __shfl_xor_sync(0xffffffffu, l0, 2);
    l1 += __shfl_xor_sync(0xffffffffu, l1, 1);
    l1 += __shfl_xor_sync(0xffffffffu, l1, 2);

    // write O
    float inv0 = 1.f / l0, inv1 = 1.f / l1;
    int r0 = s0 + wr + gid, r1 = r0 + 8;
    size_t o0 = (size_t)(r0 * B_ + b) * D_ + h * DK_;
    size_t o1 = (size_t)(r1 * B_ + b) * D_ + h * DK_;
    #pragma unroll
    for (int dt = 0; dt < 8; dt++) {
        int c = dt * 8 + tig * 2;
        o[o0 + c]     = oacc[dt][0] * inv0;
        o[o0 + c + 1] = oacc[dt][1] * inv0;
        o[o1 + c]     = oacc[dt][2] * inv1;
        o[o1 + c + 1] = oacc[dt][3] * inv1;
    }
}

// ---------------- gate / routing ----------------
__global__ void gate_kernel(const float* __restrict__ z,
                            const float* __restrict__ wg,
                            const float* __restrict__ bg) {
    int t = blockIdx.x;
    int tid = threadIdx.x;
    int w = tid >> 5, lane = tid & 31;
    __shared__ float lg[E_];
    const float* row = z + (size_t)t * D_;
    float s = 0.f;
    for (int i = lane; i < D_; i += 32) s += row[i] * wg[i * E_ + w];
    #pragma unroll
    for (int off = 16; off; off >>= 1) s += __shfl_down_sync(0xffffffffu, s, off);
    if (lane == 0) lg[w] = s + bg[w];
    __syncthreads();
    if (tid == 0) {
        float mx = lg[0]; int am = 0;
        #pragma unroll
        for (int e = 1; e < E_; e++) if (lg[e] > mx) { mx = lg[e]; am = e; }
        float pr[E_], sum = 0.f;
        #pragma unroll
        for (int e = 0; e < E_; e++) { pr[e] = expf(lg[e] - mx); sum += pr[e]; }
        float inv = 1.f / sum;
        #pragma unroll
        for (int e = 0; e < E_; e++) g_probs[t * E_ + e] = pr[e] * inv;
        g_pmax[t] = pr[am] * inv;
        int pos = atomicAdd(&g_ecount[am], 1);
        g_etok[am * T_ + pos] = t;
    }
}

// ---------------- route_prob_sum (deterministic) ----------------
__global__ void rps_kernel(float* __restrict__ dout, int out_size) {
    int e = blockIdx.x;
    __shared__ float red[256];
    float s = 0.f;
    for (int t = threadIdx.x; t < T_; t += 256) s += g_probs[t * E_ + e];
    red[threadIdx.x] = s; __syncthreads();
    for (int o = 128; o; o >>= 1) { if (threadIdx.x < o) red[threadIdx.x] += red[threadIdx.x+o]; __syncthreads(); }
    if (threadIdx.x == 0 && out_size >= OUT_TOTAL) dout[(size_t)T_ * D_ + E_ + e] = red[0];
}

// ---------------- tail outputs ----------------
__global__ void tail_kernel(float* __restrict__ dout, int out_size) {
    if (out_size < OUT_TOTAL) return;
    int i = blockIdx.x * blockDim.x + threadIdx.x;
    size_t base = (size_t)T_ * D_;
    if (i < E_) dout[base + i] = (float)g_ecount[i];
    if (i == 0) dout[base + 2 * E_] = 0.f;
    if (i < T_) dout[base + 2 * E_ + 1 + i] = g_pmax[i];
}

// ---------------- launch ----------------
extern "C" void kernel_launch(void* const* d_in, const int* in_sizes, int n_in,
                              void* d_out, int out_size) {
    const float* x      = (const float*)d_in[0];
    const float* ln1_g  = (const float*)d_in[1];
    const float* ln1_b  = (const float*)d_in[2];
    const float* ln2_g  = (const float*)d_in[3];
    const float* ln2_b  = (const float*)d_in[4];
    const float* wq     = (const float*)d_in[5];
    const float* bq     = (const float*)d_in[6];
    const float* wk     = (const float*)d_in[7];
    const float* bk     = (const float*)d_in[8];
    const float* wv     = (const float*)d_in[9];
    const float* bv     = (const float*)d_in[10];
    const float* wo     = (const float*)d_in[11];
    const float* bo     = (const float*)d_in[12];
    const float* w_gate = (const float*)d_in[13];
    const float* b_gate = (const float*)d_in[14];
    const float* w1     = (const float*)d_in[15];
    const float* b1     = (const float*)d_in[16];
    const float* w2     = (const float*)d_in[17];
    const float* b2     = (const float*)d_in[18];
    float* out = (float*)d_out;

    float *z1, *qkv, *o, *x2, *z2, *pmaxp;
    __nv_bfloat16 *z2b, *hb, *kbm;
    int *etok, *ecount;
    cudaGetSymbolAddress((void**)&z1,  g_z1);
    cudaGetSymbolAddress((void**)&qkv, g_qkv);
    cudaGetSymbolAddress((void**)&kbm, g_kb);
    cudaGetSymbolAddress((void**)&o,   g_o);
    cudaGetSymbolAddress((void**)&x2,  g_x2);
    cudaGetSymbolAddress((void**)&z2,  g_z2);
    cudaGetSymbolAddress((void**)&z2b, g_z2b);
    cudaGetSymbolAddress((void**)&hb,  g_hb);
    cudaGetSymbolAddress((void**)&etok,   g_etok);
    cudaGetSymbolAddress((void**)&ecount, g_ecount);
    cudaGetSymbolAddress((void**)&pmaxp,  g_pmax);

    cudaFuncSetAttribute(attn_mma, cudaFuncAttributeMaxDynamicSharedMemorySize, ATTN_SMEM);

    init_kernel<<<1, 32>>>();

    // LN1
    ln_kernel<<<T_, 256>>>(x, ln1_g, ln1_b, z1, nullptr);

    // fused QKV projection (tf32 cp.async) + bf16 K mirror
    mma_gemm<4><<<dim3(3072/128, T_/128, 1), 256>>>(
        (const char*)z1, wq, wk, wv, bq, bk, bv,
        nullptr, nullptr, qkv, nullptr, kbm, T_, 3072, D_, D_, nullptr, nullptr, 0);

    // attention (bf16 QK^T + tf32 PV)
    attn_mma<<<dim3(S_/128, B_*H_), 256, ATTN_SMEM>>>(qkv, kbm, o);

    // output projection + residual (tf32 cp.async)
    mma_gemm<4><<<dim3(D_/128, T_/128, 1), 256>>>(
        (const char*)o, wo, nullptr, nullptr, bo, nullptr, nullptr,
        x, nullptr, x2, nullptr, nullptr, T_, D_, D_, D_, nullptr, nullptr, 0);

    // LN2
    ln_kernel<<<T_, 256>>>(x2, ln2_g, ln2_b, z2, z2b);

    // gate + routing
    gate_kernel<<<T_, 256>>>(z2, w_gate, b_gate);

    // MoE FFN (grouped by expert, bf16)
    mma_gemm<2><<<dim3(F_/128, T_/128, E_), 256>>>(
        (const char*)z2b, w1, nullptr, nullptr, b1, nullptr, nullptr,
        nullptr, nullptr, nullptr, hb, nullptr, T_, F_, F_, D_, etok, ecount, 1);
    mma_gemm<2><<<dim3(D_/128, T_/128, E_), 256>>>(
        (const char*)hb, w2, nullptr, nullptr, b2, nullptr, nullptr,
        x2, pmaxp, out, nullptr, nullptr, T_, D_, D_, F_, etok, ecount, 0);

    // aux outputs
    rps_kernel<<<E_, 256>>>(out, out_size);
    tail_kernel<<<(T_ + 255) / 256, 256>>>(out, out_size);
}

// round 11
// speedup vs baseline: 1.2138x; 1.0579x over previous
#include <cuda_runtime.h>
#include <cuda_bf16.h>
#include <math.h>
#include <stdint.h>

// Problem dims
#define S_  2048
#define B_  2
#define D_  1024
#define H_  16
#define DK_ 64
#define E_  8
#define F_  4096
#define T_  (S_*B_)          // 4096 tokens
#define OUT_TOTAL (T_*D_ + E_ + E_ + 1 + T_)

// ---------------- scratch (device globals) ----------------
__device__ float g_z1[T_*D_];
__device__ float g_qkv[(size_t)T_*3072];
__device__ __nv_bfloat16 g_kb[T_*D_];    // bf16 K mirror [t][h*64+d]
__device__ float g_o [T_*D_];
__device__ float g_x2[T_*D_];
__device__ float g_z2[T_*D_];
__device__ __nv_bfloat16 g_z2b[T_*D_];
__device__ __nv_bfloat16 g_hb[(size_t)T_*F_];
__device__ float g_probs[T_*E_];
__device__ float g_pmax[T_];
__device__ int   g_etok[E_*T_];
__device__ int   g_ecount[E_];

__device__ __forceinline__ uint32_t f2tf32(float f) {
    uint32_t r; asm("cvt.rna.tf32.f32 %0, %1;" : "=r"(r) : "f"(f)); return r;
}
__device__ __forceinline__ uint32_t packbf(float lo, float hi) {
    __nv_bfloat162 t = __floats2bfloat162_rn(lo, hi);
    return *(uint32_t*)&t;
}
__device__ __forceinline__ float ex2f(float x) {
    float y; asm("ex2.approx.f32 %0, %1;" : "=f"(y) : "f"(x)); return y;
}
__device__ __forceinline__ void mma_bf16(float* c, const uint32_t* a, uint32_t b0, uint32_t b1) {
    asm volatile("mma.sync.aligned.m16n8k16.row.col.f32.bf16.bf16.f32 "
        "{%0,%1,%2,%3}, {%4,%5,%6,%7}, {%8,%9}, {%0,%1,%2,%3};"
        : "+f"(c[0]), "+f"(c[1]), "+f"(c[2]), "+f"(c[3])
        : "r"(a[0]), "r"(a[1]), "r"(a[2]), "r"(a[3]), "r"(b0), "r"(b1));
}
__device__ __forceinline__ void mma_tf32(float* c, const uint32_t* a, uint32_t b0, uint32_t b1) {
    asm volatile("mma.sync.aligned.m16n8k8.row.col.f32.tf32.tf32.f32 "
        "{%0,%1,%2,%3}, {%4,%5,%6,%7}, {%8,%9}, {%0,%1,%2,%3};"
        : "+f"(c[0]), "+f"(c[1]), "+f"(c[2]), "+f"(c[3])
        : "r"(a[0]), "r"(a[1]), "r"(a[2]), "r"(a[3]), "r"(b0), "r"(b1));
}
__device__ __forceinline__ uint32_t lds32(const char* p) {
    return *(const uint32_t*)p;
}
__device__ __forceinline__ uint32_t smem_u32(const void* p) {
    uint32_t a;
    asm("{ .reg .u64 t; cvta.to.shared.u64 t, %1; cvt.u32.u64 %0, t; }" : "=r"(a) : "l"(p));
    return a;
}
__device__ __forceinline__ void cpa16(uint32_t dst, const void* src) {
    asm volatile("cp.async.cg.shared.global [%0], [%1], 16;" :: "r"(dst), "l"(src));
}
#define CP_COMMIT() asm volatile("cp.async.commit_group;" ::: "memory")
#define CP_WAIT0()  asm volatile("cp.async.wait_group 0;" ::: "memory")

// ---------------- init ----------------
__global__ void init_kernel() {
    int i = threadIdx.x;
    if (i < E_) g_ecount[i] = 0;
}

// ---------------- LayerNorm (warp-shuffle reduction) ----------------
__global__ void ln_kernel(const float* __restrict__ x,
                          const float* __restrict__ gam,
                          const float* __restrict__ bet,
                          float* __restrict__ z,
                          __nv_bfloat16* __restrict__ zb) {
    int t = blockIdx.x;
    const float* row = x + (size_t)t * D_;
    __shared__ float wsum[8], wsq[8];
    int tid = threadIdx.x, lane = tid & 31, wid = tid >> 5;
    float s = 0.f, sq = 0.f;
    #pragma unroll
    for (int i = 0; i < 4; i++) {
        float v = row[tid + i * 256];
        s += v; sq += v * v;
    }
    #pragma unroll
    for (int off = 16; off; off >>= 1) {
        s  += __shfl_xor_sync(0xffffffffu, s,  off);
        sq += __shfl_xor_sync(0xffffffffu, sq, off);
    }
    if (lane == 0) { wsum[wid] = s; wsq[wid] = sq; }
    __syncthreads();
    float ts = 0.f, tq = 0.f;
    #pragma unroll
    for (int w = 0; w < 8; w++) { ts += wsum[w]; tq += wsq[w]; }
    float mean = ts * (1.f / D_);
    float var  = tq * (1.f / D_) - mean * mean;
    float inv  = rsqrtf(var + 1e-5f);
    #pragma unroll
    for (int i = 0; i < 4; i++) {
        int c = tid + i * 256;
        float v = (row[c] - mean) * inv * gam[c] + bet[c];
        z[(size_t)t * D_ + c] = v;
        if (zb) zb[(size_t)t * D_ + c] = __float2bfloat16(v);
    }
}

// ---------------- mma.sync GEMM (unchanged from R10) ----------------
#define RB 80   // smem A row bytes
template<int EB>
__global__ void __launch_bounds__(256)
mma_gemm(const char* __restrict__ A,
         const float* __restrict__ B0, const float* __restrict__ B1, const float* __restrict__ B2,
         const float* __restrict__ bias0, const float* __restrict__ bias1, const float* __restrict__ bias2,
         const float* __restrict__ res, const float* __restrict__ rowscale,
         float* __restrict__ Cf, __nv_bfloat16* __restrict__ Cb,
         __nv_bfloat16* __restrict__ kmir,
         int M, int N, int Nb, int K,
         const int* __restrict__ gather, const int* __restrict__ gcount,
         int relu_flag) {
    constexpr int KC = (EB == 4) ? 16 : 32;
    __shared__ __align__(16) char smA[2][128 * RB];
    __shared__ __align__(16) uint32_t smB[2][16 * 136];

    int e  = blockIdx.z;
    int m0 = blockIdx.y * 128, n0 = blockIdx.x * 128;
    const float* Bsrc; const float* bias; int nb0; int part = 0;
    if (B1) {
        part = n0 >> 10; nb0 = n0 & 1023;
        Bsrc = part == 0 ? B0 : (part == 1 ? B1 : B2);
        bias = part == 0 ? bias0 : (part == 1 ? bias1 : bias2);
    } else { Bsrc = B0; bias = bias0; nb0 = n0; }
    const int* glist = nullptr; int mcnt = M;
    if (gather) {
        glist = gather + (size_t)e * T_;
        mcnt  = gcount[e];
        if (m0 >= mcnt) return;
        Bsrc += (size_t)e * K * Nb;
        bias += (size_t)e * Nb;
    }
    int tid = threadIdx.x;
    int wid = tid >> 5, lane = tid & 31;

    int srow = tid >> 2, c4 = tid & 3;
    int rows[2] = { srow, srow + 64 };
    const char* aptr[2]; bool aval[2];
    #pragma unroll
    for (int u = 0; u < 2; u++) {
        int rr = m0 + rows[u]; int tok = rr; aval[u] = true;
        if (gather) { if (rr < mcnt) tok = glist[rr]; else { aval[u] = false; tok = 0; } }
        aptr[u] = A + (size_t)tok * K * EB + c4 * 16;
    }
    const float* bbase = Bsrc + nb0 + lane * 4;

    int wm = wid & 3, wn = wid >> 2;
    int wr = wm * 32, wc = wn * 64;
    int gid = lane >> 2, tig = lane & 3;

    float acc[2][8][4];
    #pragma unroll
    for (int mt = 0; mt < 2; mt++)
        #pragma unroll
        for (int nt = 0; nt < 8; nt++)
            #pragma unroll
            for (int j = 0; j < 4; j++) acc[mt][nt][j] = 0.f;

    int nch = K / KC;

    if (EB == 4) {
        uint32_t sA[2], sB[2];
        sA[0] = smem_u32(&smA[0][0]); sA[1] = smem_u32(&smA[1][0]);
        sB[0] = smem_u32(&smB[0][0]); sB[1] = smem_u32(&smB[1][0]);
        auto prefetch = [&](int i) {
            int buf = i & 1;
            size_t kb = (size_t)i * 64;
            cpa16(sA[buf] + rows[0] * RB + c4 * 16, aptr[0] + kb);
            cpa16(sA[buf] + rows[1] * RB + c4 * 16, aptr[1] + kb);
            int k0 = i * KC;
            cpa16(sB[buf] + (wid * 136 + lane * 4) * 4,       bbase + (size_t)(k0 + wid) * Nb);
            cpa16(sB[buf] + ((wid + 8) * 136 + lane * 4) * 4, bbase + (size_t)(k0 + wid + 8) * Nb);
            CP_COMMIT();
        };
        prefetch(0);
        CP_WAIT0(); __syncthreads();
        for (int i = 0; i < nch; i++) {
            int buf = i & 1;
            bool more = (i + 1 < nch);
            if (more) prefetch(i + 1);
            const uint32_t* bb = smB[buf];
            #pragma unroll
            for (int ks = 0; ks < 2; ks++) {
                uint32_t afr[2][4];
                int kb0 = (ks * 8 + tig) * 4;
                #pragma unroll
                for (int mt = 0; mt < 2; mt++) {
                    const char* ap = &smA[buf][(wr + mt * 16 + gid) * RB + kb0];
                    afr[mt][0] = lds32(ap);
                    afr[mt][1] = lds32(ap + 8 * RB);
                    afr[mt][2] = lds32(ap + 16);
                    afr[mt][3] = lds32(ap + 8 * RB + 16);
                }
                int krow = ks * 8 + tig;
                #pragma unroll
                for (int nt = 0; nt < 8; nt++) {
                    uint32_t b0 = bb[krow * 136 + wc + nt * 8 + gid];
                    uint32_t b1 = bb[(krow + 4) * 136 + wc + nt * 8 + gid];
                    mma_tf32(acc[0][nt], afr[0], b0, b1);
                    mma_tf32(acc[1][nt], afr[1], b0, b1);
                }
            }
            if (more) { CP_WAIT0(); __syncthreads(); }
        }
    } else {
        uint4 ra[2]; float4 rb[4];
        auto loadA = [&](int i) {
            size_t kb = (size_t)i * 64;
            #pragma unroll
            for (int u = 0; u < 2; u++)
                ra[u] = aval[u] ? *(const uint4*)(aptr[u] + kb) : make_uint4(0,0,0,0);
        };
        auto loadB = [&](int i) {
            int k0 = i * KC;
            rb[0] = *(const float4*)(bbase + (size_t)(k0 + 2*wid) * Nb);
            rb[1] = *(const float4*)(bbase + (size_t)(k0 + 2*wid + 1) * Nb);
            rb[2] = *(const float4*)(bbase + (size_t)(k0 + 2*(wid+8)) * Nb);
            rb[3] = *(const float4*)(bbase + (size_t)(k0 + 2*(wid+8) + 1) * Nb);
        };
        auto storeAB = [&](int buf) {
            #pragma unroll
            for (int u = 0; u < 2; u++)
                *(uint4*)&smA[buf][rows[u] * RB + c4 * 16] = ra[u];
            *(uint4*)&smB[buf][wid * 136 + lane * 4] =
                make_uint4(packbf(rb[0].x, rb[1].x), packbf(rb[0].y, rb[1].y),
                           packbf(rb[0].z, rb[1].z), packbf(rb[0].w, rb[1].w));
            *(uint4*)&smB[buf][(wid + 8) * 136 + lane * 4] =
                make_uint4(packbf(rb[2].x, rb[3].x), packbf(rb[2].y, rb[3].y),
                           packbf(rb[2].z, rb[3].z), packbf(rb[2].w, rb[3].w));
        };
        loadA(0); loadB(0); storeAB(0);
        __syncthreads();
        for (int i = 0; i < nch; i++) {
            int buf = i & 1;
            bool more = (i + 1 < nch);
            if (more) { loadA(i + 1); loadB(i + 1); }
            const uint32_t* bb = smB[buf];
            #pragma unroll
            for (int ks = 0; ks < 2; ks++) {
                uint32_t afr[2][4];
                int kb0 = (ks * 16 + tig * 2) * 2;
                #pragma unroll
                for (int mt = 0; mt < 2; mt++) {
                    const char* ap = &smA[buf][(wr + mt * 16 + gid) * RB + kb0];
                    afr[mt][0] = lds32(ap);
                    afr[mt][1] = lds32(ap + 8 * RB);
                    afr[mt][2] = lds32(ap + 16);
                    afr[mt][3] = lds32(ap + 8 * RB + 16);
                }
                int krow = ks * 8 + tig;
                #pragma unroll
                for (int nt = 0; nt < 8; nt++) {
                    uint32_t b0 = bb[krow * 136 + wc + nt * 8 + gid];
                    uint32_t b1 = bb[(krow + 4) * 136 + wc + nt * 8 + gid];
                    mma_bf16(acc[0][nt], afr[0], b0, b1);
                    mma_bf16(acc[1][nt], afr[1], b0, b1);
                }
            }
            if (more) storeAB(buf ^ 1);
            __syncthreads();
        }
    }

    // epilogue
    bool do_kmir = (kmir != nullptr) && (part == 1);
    #pragma unroll
    for (int mt = 0; mt < 2; mt++) {
        #pragma unroll
        for (int half = 0; half < 2; half++) {
            int r = m0 + wr + mt * 16 + gid + half * 8;
            int tok = r; bool valid = true;
            if (gather) { if (r < mcnt) tok = glist[r]; else valid = false; }
            if (!valid) continue;
            float sc = rowscale ? rowscale[tok] : 1.f;
            size_t ob = (size_t)tok * N;
            #pragma unroll
            for (int nt = 0; nt < 8; nt++) {
                int c  = n0 + wc + nt * 8 + tig * 2;
                int cb = nb0 + wc + nt * 8 + tig * 2;
                float v0 = acc[mt][nt][half * 2 + 0] + bias[cb];
                float v1 = acc[mt][nt][half * 2 + 1] + bias[cb + 1];
                if (relu_flag) { v0 = fmaxf(v0, 0.f); v1 = fmaxf(v1, 0.f); }
                v0 *= sc; v1 *= sc;
                if (res) { v0 += res[ob + c]; v1 += res[ob + c + 1]; }
                if (Cb) {
                    Cb[ob + c]     = __float2bfloat16(v0);
                    Cb[ob + c + 1] = __float2bfloat16(v1);
                } else {
                    Cf[ob + c]     = v0;
                    Cf[ob + c + 1] = v1;
                }
                if (do_kmir) {
                    __nv_bfloat162 kp = __floats2bfloat162_rn(v0, v1);
                    *(__nv_bfloat162*)&kmir[(size_t)tok * D_ + cb] = kp;
                }
            }
        }
    }
}

// ---------------- flash attention: all-bf16 MMA, no-max softmax ----------------
// Q staging fp32 stride QS_, then reused for P bf16 stride PSW_.
// K bf16 [2][64][KSW_] via cp.async from mirror.
// V bf16 key-pair-packed [2][32][VSW_], register-staged LDG+pack.
#define QS_  68
#define PSW_ 36
#define KSW_ 40
#define VSW_ 76
#define ATTN_SMEM ((128*QS_ + 2*64*KSW_ + 2*32*VSW_) * 4)
__global__ void __launch_bounds__(256, 2)
attn_mma(const float* __restrict__ qkv, const __nv_bfloat16* __restrict__ kbg,
         float* __restrict__ o) {
    extern __shared__ uint32_t sm[];
    uint32_t* pS = sm;                    // [128][QS_] Q fp32, then [128][PSW_] P bf16
    uint32_t* kS = pS + 128 * QS_;        // [2][64][KSW_] bf16
    uint32_t* vS = kS + 2 * 64 * KSW_;    // [2][32][VSW_] bf16 key-pairs

    int bh = blockIdx.y;
    int b = bh % B_, h = bh / B_;
    int s0 = blockIdx.x * 128;
    int tid = threadIdx.x, lane = tid & 31, wid = tid >> 5;
    int gid = lane >> 2, tig = lane & 3;
    int wr = wid * 16;
    const float SC2 = 0.125f * 1.44269504f;   // scale * log2(e)

    uint32_t pS_a = smem_u32(pS), kS_a = smem_u32(kS);

    // prologue: cp.async Q (fp32) + K(bf16) tile 0
    {
        int qr = tid >> 1, qseg = tid & 1;
        const float* qp = qkv + (size_t)((s0 + qr) * B_ + b) * 3072 + h * DK_ + qseg * 32;
        #pragma unroll
        for (int j = 0; j < 8; j++)
            cpa16(pS_a + (qr * QS_ + qseg * 32 + j * 4) * 4, qp + j * 4);
    }
    int kr = tid >> 2, kseg = tid & 3;
    auto prefetchK = [&](int i) {
        int buf = i & 1;
        int t = (i * 64 + kr) * B_ + b;
        const __nv_bfloat16* kp = kbg + (size_t)t * D_ + h * DK_ + kseg * 16;
        #pragma unroll
        for (int j = 0; j < 2; j++)
            cpa16(kS_a + ((buf * 64 + kr) * KSW_ + kseg * 8 + j * 4) * 4, (const char*)kp + j * 16);
        CP_COMMIT();
    };
    // V staging: thread -> key-pair vkp, d-segment vds (8 d values)
    int vkp = tid >> 3, vds = (tid & 7) * 8;
    float4 vreg[4];
    auto loadV = [&](int i) {
        int t0 = (i * 64 + 2 * vkp) * B_ + b;
        const float* vp0 = qkv + (size_t)t0 * 3072 + 2048 + h * DK_ + vds;
        const float* vp1 = vp0 + (size_t)B_ * 3072;
        vreg[0] = *(const float4*)vp0; vreg[1] = *(const float4*)(vp0 + 4);
        vreg[2] = *(const float4*)vp1; vreg[3] = *(const float4*)(vp1 + 4);
    };
    auto storeV = [&](int buf) {
        uint32_t* d = &vS[(buf * 32 + vkp) * VSW_ + vds];
        *(uint4*)d = make_uint4(packbf(vreg[0].x, vreg[2].x), packbf(vreg[0].y, vreg[2].y),
                                packbf(vreg[0].z, vreg[2].z), packbf(vreg[0].w, vreg[2].w));
        *(uint4*)(d + 4) = make_uint4(packbf(vreg[1].x, vreg[3].x), packbf(vreg[1].y, vreg[3].y),
                                      packbf(vreg[1].z, vreg[3].z), packbf(vreg[1].w, vreg[3].w));
    };

    prefetchK(0);
    loadV(0); storeV(0);
    CP_WAIT0(); __syncthreads();

    // extract Q fragments as bf16 pairs (4 k-chunks of 16)
    uint32_t qfb[4][4];
    #pragma unroll
    for (int kk = 0; kk < 4; kk++) {
        const uint32_t* r0 = &pS[(wr + gid) * QS_ + kk * 16];
        const uint32_t* r1 = &pS[(wr + gid + 8) * QS_ + kk * 16];
        float q00 = __uint_as_float(r0[tig * 2]),     q01 = __uint_as_float(r0[tig * 2 + 1]);
        float q10 = __uint_as_float(r1[tig * 2]),     q11 = __uint_as_float(r1[tig * 2 + 1]);
        float q02 = __uint_as_float(r0[8 + tig * 2]), q03 = __uint_as_float(r0[8 + tig * 2 + 1]);
        float q12 = __uint_as_float(r1[8 + tig * 2]), q13 = __uint_as_float(r1[8 + tig * 2 + 1]);
        qfb[kk][0] = packbf(q00, q01);
        qfb[kk][1] = packbf(q10, q11);
        qfb[kk][2] = packbf(q02, q03);
        qfb[kk][3] = packbf(q12, q13);
    }
    __syncthreads();   // P region overlaps other warps' Q rows

    float oacc[8][4];
    #pragma unroll
    for (int dt = 0; dt < 8; dt++)
        #pragma unroll
        for (int j = 0; j < 4; j++) oacc[dt][j] = 0.f;
    float l0 = 0.f, l1 = 0.f;
    uint32_t* pw = pS + wid * 16 * PSW_;

    const int NT = S_ / 64;
    for (int i = 0; i < NT; i++) {
        int buf = i & 1;
        bool more = (i + 1 < NT);
        if (more) { prefetchK(i + 1); loadV(i + 1); }
        const uint32_t* kb = kS + buf * 64 * KSW_;
        const uint32_t* vb = vS + buf * 32 * VSW_;

        // scores 16x64 via bf16 m16n8k16
        float sc[8][4];
        #pragma unroll
        for (int nt = 0; nt < 8; nt++)
            #pragma unroll
            for (int j = 0; j < 4; j++) sc[nt][j] = 0.f;
        #pragma unroll
        for (int kk = 0; kk < 4; kk++) {
            #pragma unroll
            for (int nt = 0; nt < 8; nt++) {
                const uint32_t* br = &kb[(nt * 8 + gid) * KSW_ + kk * 8 + tig];
                mma_bf16(sc[nt], qfb[kk], br[0], br[4]);
            }
        }

        // no-max softmax: p = 2^(s*SC2); write P as bf16 key-pairs
        #pragma unroll
        for (int nt = 0; nt < 8; nt++) {
            float p0 = ex2f(sc[nt][0] * SC2);
            float p1 = ex2f(sc[nt][1] * SC2);
            float p2 = ex2f(sc[nt][2] * SC2);
            float p3 = ex2f(sc[nt][3] * SC2);
            l0 += p0 + p1; l1 += p2 + p3;
            int c2 = nt * 4 + tig;   // key-pair word index
            pw[gid * PSW_ + c2]       = packbf(p0, p1);
            pw[(gid + 8) * PSW_ + c2] = packbf(p2, p3);
        }
        __syncwarp();

        // P @ V (bf16): 4 k-chunks of 16 keys (8 pairs each)
        #pragma unroll
        for (int kk = 0; kk < 4; kk++) {
            uint32_t a[4];
            const uint32_t* ar = &pw[gid * PSW_ + kk * 8 + tig];
            const uint32_t* ar1 = &pw[(gid + 8) * PSW_ + kk * 8 + tig];
            a[0] = ar[0]; a[1] = ar1[0]; a[2] = ar[4]; a[3] = ar1[4];
            #pragma unroll
            for (int dt = 0; dt < 8; dt++) {
                uint32_t b0 = vb[(kk * 8 + tig) * VSW_ + dt * 8 + gid];
                uint32_t b1 = vb[(kk * 8 + tig + 4) * VSW_ + dt * 8 + gid];
                mma_bf16(oacc[dt], a, b0, b1);
            }
        }
        if (more) {
            storeV(buf ^ 1);
            CP_WAIT0(); __syncthreads();
        } else __syncwarp();
    }

    // final l reduction (4 threads per row)
    l0 += __shfl_xor_sync(0xffffffffu, l0, 1);
    l0 += __shfl_xor_sync(0xffffffffu, l0, 2);
    l1 += __shfl_xor_sync(0xffffffffu, l1, 1);
    l1 += __shfl_xor_sync(0xffffffffu, l1, 2);

    // write O
    float inv0 = 1.f / l0, inv1 = 1.f / l1;
    int r0 = s0 + wr + gid, r1 = r0 + 8;
    size_t o0 = (size_t)(r0 * B_ + b) * D_ + h * DK_;
    size_t o1 = (size_t)(r1 * B_ + b) * D_ + h * DK_;
    #pragma unroll
    for (int dt = 0; dt < 8; dt++) {
        int c = dt * 8 + tig * 2;
        o[o0 + c]     = oacc[dt][0] * inv0;
        o[o0 + c + 1] = oacc[dt][1] * inv0;
        o[o1 + c]     = oacc[dt][2] * inv1;
        o[o1 + c + 1] = oacc[dt][3] * inv1;
    }
}

// ---------------- gate / routing ----------------
__global__ void gate_kernel(const float* __restrict__ z,
                            const float* __restrict__ wg,
                            const float* __restrict__ bg) {
    int t = blockIdx.x;
    int tid = threadIdx.x;
    int w = tid >> 5, lane = tid & 31;
    __shared__ float lg[E_];
    const float* row = z + (size_t)t * D_;
    float s = 0.f;
    for (int i = lane; i < D_; i += 32) s += row[i] * wg[i * E_ + w];
    #pragma unroll
    for (int off = 16; off; off >>= 1) s += __shfl_down_sync(0xffffffffu, s, off);
    if (lane == 0) lg[w] = s + bg[w];
    __syncthreads();
    if (tid == 0) {
        float mx = lg[0]; int am = 0;
        #pragma unroll
        for (int e = 1; e < E_; e++) if (lg[e] > mx) { mx = lg[e]; am = e; }
        float pr[E_], sum = 0.f;
        #pragma unroll
        for (int e = 0; e < E_; e++) { pr[e] = expf(lg[e] - mx); sum += pr[e]; }
        float inv = 1.f / sum;
        #pragma unroll
        for (int e = 0; e < E_; e++) g_probs[t * E_ + e] = pr[e] * inv;
        g_pmax[t] = pr[am] * inv;
        int pos = atomicAdd(&g_ecount[am], 1);
        g_etok[am * T_ + pos] = t;
    }
}

// ---------------- route_prob_sum (deterministic) ----------------
__global__ void rps_kernel(float* __restrict__ dout, int out_size) {
    int e = blockIdx.x;
    __shared__ float red[256];
    float s = 0.f;
    for (int t = threadIdx.x; t < T_; t += 256) s += g_probs[t * E_ + e];
    red[threadIdx.x] = s; __syncthreads();
    for (int o = 128; o; o >>= 1) { if (threadIdx.x < o) red[threadIdx.x] += red[threadIdx.x+o]; __syncthreads(); }
    if (threadIdx.x == 0 && out_size >= OUT_TOTAL) dout[(size_t)T_ * D_ + E_ + e] = red[0];
}

// ---------------- tail outputs ----------------
__global__ void tail_kernel(float* __restrict__ dout, int out_size) {
    if (out_size < OUT_TOTAL) return;
    int i = blockIdx.x * blockDim.x + threadIdx.x;
    size_t base = (size_t)T_ * D_;
    if (i < E_) dout[base + i] = (float)g_ecount[i];
    if (i == 0) dout[base + 2 * E_] = 0.f;
    if (i < T_) dout[base + 2 * E_ + 1 + i] = g_pmax[i];
}

// ---------------- launch ----------------
extern "C" void kernel_launch(void* const* d_in, const int* in_sizes, int n_in,
                              void* d_out, int out_size) {
    const float* x      = (const float*)d_in[0];
    const float* ln1_g  = (const float*)d_in[1];
    const float* ln1_b  = (const float*)d_in[2];
    const float* ln2_g  = (const float*)d_in[3];
    const float* ln2_b  = (const float*)d_in[4];
    const float* wq     = (const float*)d_in[5];
    const float* bq     = (const float*)d_in[6];
    const float* wk     = (const float*)d_in[7];
    const float* bk     = (const float*)d_in[8];
    const float* wv     = (const float*)d_in[9];
    const float* bv     = (const float*)d_in[10];
    const float* wo     = (const float*)d_in[11];
    const float* bo     = (const float*)d_in[12];
    const float* w_gate = (const float*)d_in[13];
    const float* b_gate = (const float*)d_in[14];
    const float* w1     = (const float*)d_in[15];
    const float* b1     = (const float*)d_in[16];
    const float* w2     = (const float*)d_in[17];
    const float* b2     = (const float*)d_in[18];
    float* out = (float*)d_out;

    float *z1, *qkv, *o, *x2, *z2, *pmaxp;
    __nv_bfloat16 *z2b, *hb, *kbm;
    int *etok, *ecount;
    cudaGetSymbolAddress((void**)&z1,  g_z1);
    cudaGetSymbolAddress((void**)&qkv, g_qkv);
    cudaGetSymbolAddress((void**)&kbm, g_kb);
    cudaGetSymbolAddress((void**)&o,   g_o);
    cudaGetSymbolAddress((void**)&x2,  g_x2);
    cudaGetSymbolAddress((void**)&z2,  g_z2);
    cudaGetSymbolAddress((void**)&z2b, g_z2b);
    cudaGetSymbolAddress((void**)&hb,  g_hb);
    cudaGetSymbolAddress((void**)&etok,   g_etok);
    cudaGetSymbolAddress((void**)&ecount, g_ecount);
    cudaGetSymbolAddress((void**)&pmaxp,  g_pmax);

    cudaFuncSetAttribute(attn_mma, cudaFuncAttributeMaxDynamicSharedMemorySize, ATTN_SMEM);

    init_kernel<<<1, 32>>>();

    // LN1
    ln_kernel<<<T_, 256>>>(x, ln1_g, ln1_b, z1, nullptr);

    // fused QKV projection (tf32 cp.async) + bf16 K mirror
    mma_gemm<4><<<dim3(3072/128, T_/128, 1), 256>>>(
        (const char*)z1, wq, wk, wv, bq, bk, bv,
        nullptr, nullptr, qkv, nullptr, kbm, T_, 3072, D_, D_, nullptr, nullptr, 0);

    // attention (bf16 QK^T + bf16 PV)
    attn_mma<<<dim3(S_/128, B_*H_), 256, ATTN_SMEM>>>(qkv, kbm, o);

    // output projection + residual (tf32 cp.async)
    mma_gemm<4><<<dim3(D_/128, T_/128, 1), 256>>>(
        (const char*)o, wo, nullptr, nullptr, bo, nullptr, nullptr,
        x, nullptr, x2, nullptr, nullptr, T_, D_, D_, D_, nullptr, nullptr, 0);

    // LN2
    ln_kernel<<<T_, 256>>>(x2, ln2_g, ln2_b, z2, z2b);

    // gate + routing
    gate_kernel<<<T_, 256>>>(z2, w_gate, b_gate);

    // MoE FFN (grouped by expert, bf16)
    mma_gemm<2><<<dim3(F_/128, T_/128, E_), 256>>>(
        (const char*)z2b, w1, nullptr, nullptr, b1, nullptr, nullptr,
        nullptr, nullptr, nullptr, hb, nullptr, T_, F_, F_, D_, etok, ecount, 1);
    mma_gemm<2><<<dim3(D_/128, T_/128, E_), 256>>>(
        (const char*)hb, w2, nullptr, nullptr, b2, nullptr, nullptr,
        x2, pmaxp, out, nullptr, nullptr, T_, D_, D_, F_, etok, ecount, 0);

    // aux outputs
    rps_kernel<<<E_, 256>>>(out, out_size);
    tail_kernel<<<(T_ + 255) / 256, 256>>>(out, out_size);
}

// round 12
// speedup vs baseline: 1.5507x; 1.2776x over previous
#include <cuda_runtime.h>
#include <cuda_bf16.h>
#include <math.h>
#include <stdint.h>

// Problem dims
#define S_  2048
#define B_  2
#define D_  1024
#define H_  16
#define DK_ 64
#define E_  8
#define F_  4096
#define T_  (S_*B_)          // 4096 tokens
#define OUT_TOTAL (T_*D_ + E_ + E_ + 1 + T_)

// ---------------- scratch (device globals) ----------------
__device__ __nv_bfloat16 g_z1b[T_*D_];
__device__ __nv_bfloat16 g_qkvb[(size_t)T_*3072];   // bf16 q|k|v
__device__ float g_o [T_*D_];
__device__ float g_x2[T_*D_];
__device__ float g_z2[T_*D_];
__device__ __nv_bfloat16 g_z2b[T_*D_];
__device__ __nv_bfloat16 g_hb[(size_t)T_*F_];
__device__ float g_probs[T_*E_];
__device__ float g_pmax[T_];
__device__ int   g_etok[E_*T_];
__device__ int   g_ecount[E_];

__device__ __forceinline__ uint32_t f2tf32(float f) {
    uint32_t r; asm("cvt.rna.tf32.f32 %0, %1;" : "=r"(r) : "f"(f)); return r;
}
__device__ __forceinline__ uint32_t packbf(float lo, float hi) {
    __nv_bfloat162 t = __floats2bfloat162_rn(lo, hi);
    return *(uint32_t*)&t;
}
__device__ __forceinline__ uint32_t prmtw(uint32_t a, uint32_t b, uint32_t sel) {
    uint32_t r; asm("prmt.b32 %0, %1, %2, %3;" : "=r"(r) : "r"(a), "r"(b), "r"(sel)); return r;
}
__device__ __forceinline__ float ex2f(float x) {
    float y; asm("ex2.approx.f32 %0, %1;" : "=f"(y) : "f"(x)); return y;
}
__device__ __forceinline__ void mma_bf16(float* c, const uint32_t* a, uint32_t b0, uint32_t b1) {
    asm volatile("mma.sync.aligned.m16n8k16.row.col.f32.bf16.bf16.f32 "
        "{%0,%1,%2,%3}, {%4,%5,%6,%7}, {%8,%9}, {%0,%1,%2,%3};"
        : "+f"(c[0]), "+f"(c[1]), "+f"(c[2]), "+f"(c[3])
        : "r"(a[0]), "r"(a[1]), "r"(a[2]), "r"(a[3]), "r"(b0), "r"(b1));
}
__device__ __forceinline__ void mma_tf32(float* c, const uint32_t* a, uint32_t b0, uint32_t b1) {
    asm volatile("mma.sync.aligned.m16n8k8.row.col.f32.tf32.tf32.f32 "
        "{%0,%1,%2,%3}, {%4,%5,%6,%7}, {%8,%9}, {%0,%1,%2,%3};"
        : "+f"(c[0]), "+f"(c[1]), "+f"(c[2]), "+f"(c[3])
        : "r"(a[0]), "r"(a[1]), "r"(a[2]), "r"(a[3]), "r"(b0), "r"(b1));
}
__device__ __forceinline__ uint32_t lds32(const char* p) {
    return *(const uint32_t*)p;
}
__device__ __forceinline__ uint32_t smem_u32(const void* p) {
    uint32_t a;
    asm("{ .reg .u64 t; cvta.to.shared.u64 t, %1; cvt.u32.u64 %0, t; }" : "=r"(a) : "l"(p));
    return a;
}
__device__ __forceinline__ void cpa16(uint32_t dst, const void* src) {
    asm volatile("cp.async.cg.shared.global [%0], [%1], 16;" :: "r"(dst), "l"(src));
}
#define CP_COMMIT() asm volatile("cp.async.commit_group;" ::: "memory")
#define CP_WAIT0()  asm volatile("cp.async.wait_group 0;" ::: "memory")

// ---------------- init ----------------
__global__ void init_kernel() {
    int i = threadIdx.x;
    if (i < E_) g_ecount[i] = 0;
}

// ---------------- LayerNorm (warp-shuffle reduction; fp32 and/or bf16 out) ----------------
__global__ void ln_kernel(const float* __restrict__ x,
                          const float* __restrict__ gam,
                          const float* __restrict__ bet,
                          float* __restrict__ z,
                          __nv_bfloat16* __restrict__ zb) {
    int t = blockIdx.x;
    const float* row = x + (size_t)t * D_;
    __shared__ float wsum[8], wsq[8];
    int tid = threadIdx.x, lane = tid & 31, wid = tid >> 5;
    float s = 0.f, sq = 0.f;
    #pragma unroll
    for (int i = 0; i < 4; i++) {
        float v = row[tid + i * 256];
        s += v; sq += v * v;
    }
    #pragma unroll
    for (int off = 16; off; off >>= 1) {
        s  += __shfl_xor_sync(0xffffffffu, s,  off);
        sq += __shfl_xor_sync(0xffffffffu, sq, off);
    }
    if (lane == 0) { wsum[wid] = s; wsq[wid] = sq; }
    __syncthreads();
    float ts = 0.f, tq = 0.f;
    #pragma unroll
    for (int w = 0; w < 8; w++) { ts += wsum[w]; tq += wsq[w]; }
    float mean = ts * (1.f / D_);
    float var  = tq * (1.f / D_) - mean * mean;
    float inv  = rsqrtf(var + 1e-5f);
    #pragma unroll
    for (int i = 0; i < 4; i++) {
        int c = tid + i * 256;
        float v = (row[c] - mean) * inv * gam[c] + bet[c];
        if (z)  z[(size_t)t * D_ + c] = v;
        if (zb) zb[(size_t)t * D_ + c] = __float2bfloat16(v);
    }
}

// ---------------- mma.sync GEMM ----------------
#define RB 80   // smem A row bytes
template<int EB>
__global__ void __launch_bounds__(256)
mma_gemm(const char* __restrict__ A,
         const float* __restrict__ B0, const float* __restrict__ B1, const float* __restrict__ B2,
         const float* __restrict__ bias0, const float* __restrict__ bias1, const float* __restrict__ bias2,
         const float* __restrict__ res, const float* __restrict__ rowscale,
         float* __restrict__ Cf, __nv_bfloat16* __restrict__ Cb,
         int M, int N, int Nb, int K,
         const int* __restrict__ gather, const int* __restrict__ gcount,
         int relu_flag) {
    constexpr int KC = (EB == 4) ? 16 : 32;
    __shared__ __align__(16) char smA[2][128 * RB];
    __shared__ __align__(16) uint32_t smB[2][16 * 136];

    int e  = blockIdx.z;
    int m0 = blockIdx.y * 128, n0 = blockIdx.x * 128;
    const float* Bsrc; const float* bias; int nb0;
    if (B1) {
        int part = n0 >> 10; nb0 = n0 & 1023;
        Bsrc = part == 0 ? B0 : (part == 1 ? B1 : B2);
        bias = part == 0 ? bias0 : (part == 1 ? bias1 : bias2);
    } else { Bsrc = B0; bias = bias0; nb0 = n0; }
    const int* glist = nullptr; int mcnt = M;
    if (gather) {
        glist = gather + (size_t)e * T_;
        mcnt  = gcount[e];
        if (m0 >= mcnt) return;
        Bsrc += (size_t)e * K * Nb;
        bias += (size_t)e * Nb;
    }
    int tid = threadIdx.x;
    int wid = tid >> 5, lane = tid & 31;

    int srow = tid >> 2, c4 = tid & 3;
    int rows[2] = { srow, srow + 64 };
    const char* aptr[2]; bool aval[2];
    #pragma unroll
    for (int u = 0; u < 2; u++) {
        int rr = m0 + rows[u]; int tok = rr; aval[u] = true;
        if (gather) { if (rr < mcnt) tok = glist[rr]; else { aval[u] = false; tok = 0; } }
        aptr[u] = A + (size_t)tok * K * EB + c4 * 16;
    }
    const float* bbase = Bsrc + nb0 + lane * 4;

    int wm = wid & 3, wn = wid >> 2;
    int wr = wm * 32, wc = wn * 64;
    int gid = lane >> 2, tig = lane & 3;

    float acc[2][8][4];
    #pragma unroll
    for (int mt = 0; mt < 2; mt++)
        #pragma unroll
        for (int nt = 0; nt < 8; nt++)
            #pragma unroll
            for (int j = 0; j < 4; j++) acc[mt][nt][j] = 0.f;

    int nch = K / KC;

    if (EB == 4) {
        uint32_t sA[2], sB[2];
        sA[0] = smem_u32(&smA[0][0]); sA[1] = smem_u32(&smA[1][0]);
        sB[0] = smem_u32(&smB[0][0]); sB[1] = smem_u32(&smB[1][0]);
        auto prefetch = [&](int i) {
            int buf = i & 1;
            size_t kb = (size_t)i * 64;
            cpa16(sA[buf] + rows[0] * RB + c4 * 16, aptr[0] + kb);
            cpa16(sA[buf] + rows[1] * RB + c4 * 16, aptr[1] + kb);
            int k0 = i * KC;
            cpa16(sB[buf] + (wid * 136 + lane * 4) * 4,       bbase + (size_t)(k0 + wid) * Nb);
            cpa16(sB[buf] + ((wid + 8) * 136 + lane * 4) * 4, bbase + (size_t)(k0 + wid + 8) * Nb);
            CP_COMMIT();
        };
        prefetch(0);
        CP_WAIT0(); __syncthreads();
        for (int i = 0; i < nch; i++) {
            int buf = i & 1;
            bool more = (i + 1 < nch);
            if (more) prefetch(i + 1);
            const uint32_t* bb = smB[buf];
            #pragma unroll
            for (int ks = 0; ks < 2; ks++) {
                uint32_t afr[2][4];
                int kb0 = (ks * 8 + tig) * 4;
                #pragma unroll
                for (int mt = 0; mt < 2; mt++) {
                    const char* ap = &smA[buf][(wr + mt * 16 + gid) * RB + kb0];
                    afr[mt][0] = lds32(ap);
                    afr[mt][1] = lds32(ap + 8 * RB);
                    afr[mt][2] = lds32(ap + 16);
                    afr[mt][3] = lds32(ap + 8 * RB + 16);
                }
                int krow = ks * 8 + tig;
                #pragma unroll
                for (int nt = 0; nt < 8; nt++) {
                    uint32_t b0 = bb[krow * 136 + wc + nt * 8 + gid];
                    uint32_t b1 = bb[(krow + 4) * 136 + wc + nt * 8 + gid];
                    mma_tf32(acc[0][nt], afr[0], b0, b1);
                    mma_tf32(acc[1][nt], afr[1], b0, b1);
                }
            }
            if (more) { CP_WAIT0(); __syncthreads(); }
        }
    } else {
        uint4 ra[2]; float4 rb[4];
        auto loadA = [&](int i) {
            size_t kb = (size_t)i * 64;
            #pragma unroll
            for (int u = 0; u < 2; u++)
                ra[u] = aval[u] ? *(const uint4*)(aptr[u] + kb) : make_uint4(0,0,0,0);
        };
        auto loadB = [&](int i) {
            int k0 = i * KC;
            rb[0] = *(const float4*)(bbase + (size_t)(k0 + 2*wid) * Nb);
            rb[1] = *(const float4*)(bbase + (size_t)(k0 + 2*wid + 1) * Nb);
            rb[2] = *(const float4*)(bbase + (size_t)(k0 + 2*(wid+8)) * Nb);
            rb[3] = *(const float4*)(bbase + (size_t)(k0 + 2*(wid+8) + 1) * Nb);
        };
        auto storeAB = [&](int buf) {
            #pragma unroll
            for (int u = 0; u < 2; u++)
                *(uint4*)&smA[buf][rows[u] * RB + c4 * 16] = ra[u];
            *(uint4*)&smB[buf][wid * 136 + lane * 4] =
                make_uint4(packbf(rb[0].x, rb[1].x), packbf(rb[0].y, rb[1].y),
                           packbf(rb[0].z, rb[1].z), packbf(rb[0].w, rb[1].w));
            *(uint4*)&smB[buf][(wid + 8) * 136 + lane * 4] =
                make_uint4(packbf(rb[2].x, rb[3].x), packbf(rb[2].y, rb[3].y),
                           packbf(rb[2].z, rb[3].z), packbf(rb[2].w, rb[3].w));
        };
        loadA(0); loadB(0); storeAB(0);
        __syncthreads();
        for (int i = 0; i < nch; i++) {
            int buf = i & 1;
            bool more = (i + 1 < nch);
            if (more) { loadA(i + 1); loadB(i + 1); }
            const uint32_t* bb = smB[buf];
            #pragma unroll
            for (int ks = 0; ks < 2; ks++) {
                uint32_t afr[2][4];
                int kb0 = (ks * 16 + tig * 2) * 2;
                #pragma unroll
                for (int mt = 0; mt < 2; mt++) {
                    const char* ap = &smA[buf][(wr + mt * 16 + gid) * RB + kb0];
                    afr[mt][0] = lds32(ap);
                    afr[mt][1] = lds32(ap + 8 * RB);
                    afr[mt][2] = lds32(ap + 16);
                    afr[mt][3] = lds32(ap + 8 * RB + 16);
                }
                int krow = ks * 8 + tig;
                #pragma unroll
                for (int nt = 0; nt < 8; nt++) {
                    uint32_t b0 = bb[krow * 136 + wc + nt * 8 + gid];
                    uint32_t b1 = bb[(krow + 4) * 136 + wc + nt * 8 + gid];
                    mma_bf16(acc[0][nt], afr[0], b0, b1);
                    mma_bf16(acc[1][nt], afr[1], b0, b1);
                }
            }
            if (more) storeAB(buf ^ 1);
            __syncthreads();
        }
    }

    // epilogue
    #pragma unroll
    for (int mt = 0; mt < 2; mt++) {
        #pragma unroll
        for (int half = 0; half < 2; half++) {
            int r = m0 + wr + mt * 16 + gid + half * 8;
            int tok = r; bool valid = true;
            if (gather) { if (r < mcnt) tok = glist[r]; else valid = false; }
            if (!valid) continue;
            float sc = rowscale ? rowscale[tok] : 1.f;
            size_t ob = (size_t)tok * N;
            #pragma unroll
            for (int nt = 0; nt < 8; nt++) {
                int c  = n0 + wc + nt * 8 + tig * 2;
                int cb = nb0 + wc + nt * 8 + tig * 2;
                float v0 = acc[mt][nt][half * 2 + 0] + bias[cb];
                float v1 = acc[mt][nt][half * 2 + 1] + bias[cb + 1];
                if (relu_flag) { v0 = fmaxf(v0, 0.f); v1 = fmaxf(v1, 0.f); }
                v0 *= sc; v1 *= sc;
                if (res) { v0 += res[ob + c]; v1 += res[ob + c + 1]; }
                if (Cb) {
                    *(__nv_bfloat162*)&Cb[ob + c] = __floats2bfloat162_rn(v0, v1);
                } else {
                    Cf[ob + c]     = v0;
                    Cf[ob + c + 1] = v1;
                }
            }
        }
    }
}

// ---------------- flash attention: all-bf16, conflict-free strides ----------------
// Q/K/P stride 36 words (mod32==4 -> 4*gid+tig banks), V stride 72 (mod32==8 -> 8*tig+gid).
// Q staged bf16 (direct fragment loads), region reused for P (same per-warp rows).
#define QKS_ 36
#define VSW_ 72
#define ATTN_SMEM ((128*QKS_ + 2*64*QKS_ + 2*32*VSW_) * 4)
__global__ void __launch_bounds__(256, 2)
attn_mma(const __nv_bfloat16* __restrict__ qkvb, float* __restrict__ o) {
    extern __shared__ uint32_t sm[];
    uint32_t* pS = sm;                    // [128][QKS_] Q bf16 staging, then P bf16
    uint32_t* kS = pS + 128 * QKS_;       // [2][64][QKS_] bf16
    uint32_t* vS = kS + 2 * 64 * QKS_;    // [2][32][VSW_] bf16 key-pairs

    int bh = blockIdx.y;
    int b = bh % B_, h = bh / B_;
    int s0 = blockIdx.x * 128;
    int tid = threadIdx.x, lane = tid & 31, wid = tid >> 5;
    int gid = lane >> 2, tig = lane & 3;
    int wr = wid * 16;
    const float SC2 = 0.125f * 1.44269504f;   // scale * log2(e)

    uint32_t pS_a = smem_u32(pS), kS_a = smem_u32(kS);

    // prologue: cp.async Q bf16 (128 rows x 128B) + K tile 0
    {
        int qr = tid >> 1, qseg = tid & 1;
        const __nv_bfloat16* qp = qkvb + (size_t)((s0 + qr) * B_ + b) * 3072 + h * DK_;
        #pragma unroll
        for (int j = 0; j < 4; j++)
            cpa16(pS_a + (qr * QKS_ + qseg * 16 + j * 4) * 4,
                  (const char*)qp + qseg * 64 + j * 16);
    }
    int kr = tid >> 2, kseg = tid & 3;
    auto prefetchK = [&](int i) {
        int buf = i & 1;
        int t = (i * 64 + kr) * B_ + b;
        const __nv_bfloat16* kp = qkvb + (size_t)t * 3072 + 1024 + h * DK_;
        #pragma unroll
        for (int j = 0; j < 2; j++)
            cpa16(kS_a + ((buf * 64 + kr) * QKS_ + kseg * 8 + j * 4) * 4,
                  (const char*)kp + kseg * 32 + j * 16);
        CP_COMMIT();
    };
    // V staging: thread -> key-pair vkp (0..31), d-segment vds (8 d values)
    int vkp = tid >> 3, vds = (tid & 7) * 8;
    uint4 vr0, vr1;
    auto loadV = [&](int i) {
        int t0 = (i * 64 + 2 * vkp) * B_ + b;
        const __nv_bfloat16* vp0 = qkvb + (size_t)t0 * 3072 + 2048 + h * DK_ + vds;
        vr0 = *(const uint4*)vp0;
        vr1 = *(const uint4*)(vp0 + (size_t)B_ * 3072);
    };
    auto storeV = [&](int buf) {
        uint32_t* d = &vS[(buf * 32 + vkp) * VSW_ + vds];
        *(uint4*)d = make_uint4(prmtw(vr0.x, vr1.x, 0x5410), prmtw(vr0.x, vr1.x, 0x7632),
                                prmtw(vr0.y, vr1.y, 0x5410), prmtw(vr0.y, vr1.y, 0x7632));
        *(uint4*)(d + 4) = make_uint4(prmtw(vr0.z, vr1.z, 0x5410), prmtw(vr0.z, vr1.z, 0x7632),
                                      prmtw(vr0.w, vr1.w, 0x5410), prmtw(vr0.w, vr1.w, 0x7632));
    };

    prefetchK(0);
    loadV(0); storeV(0);
    CP_WAIT0(); __syncthreads();

    // extract Q fragments (direct bf16 words; own warp's rows only)
    uint32_t qfb[4][4];
    #pragma unroll
    for (int kk = 0; kk < 4; kk++) {
        const uint32_t* r0 = &pS[(wr + gid) * QKS_ + kk * 8 + tig];
        const uint32_t* r1 = &pS[(wr + gid + 8) * QKS_ + kk * 8 + tig];
        qfb[kk][0] = r0[0];
        qfb[kk][1] = r1[0];
        qfb[kk][2] = r0[4];
        qfb[kk][3] = r1[4];
    }
    __syncwarp();

    float oacc[8][4];
    #pragma unroll
    for (int dt = 0; dt < 8; dt++)
        #pragma unroll
        for (int j = 0; j < 4; j++) oacc[dt][j] = 0.f;
    float l0 = 0.f, l1 = 0.f;
    uint32_t* pw = pS + wid * 16 * QKS_;

    const int NT = S_ / 64;
    for (int i = 0; i < NT; i++) {
        int buf = i & 1;
        bool more = (i + 1 < NT);
        if (more) { prefetchK(i + 1); loadV(i + 1); }
        const uint32_t* kb = kS + buf * 64 * QKS_;
        const uint32_t* vb = vS + buf * 32 * VSW_;

        // scores 16x64 via bf16 m16n8k16
        float sc[8][4];
        #pragma unroll
        for (int nt = 0; nt < 8; nt++)
            #pragma unroll
            for (int j = 0; j < 4; j++) sc[nt][j] = 0.f;
        #pragma unroll
        for (int kk = 0; kk < 4; kk++) {
            #pragma unroll
            for (int nt = 0; nt < 8; nt++) {
                const uint32_t* br = &kb[(nt * 8 + gid) * QKS_ + kk * 8 + tig];
                mma_bf16(sc[nt], qfb[kk], br[0], br[4]);
            }
        }

        // no-max softmax: p = 2^(s*SC2); write P as bf16 key-pairs
        #pragma unroll
        for (int nt = 0; nt < 8; nt++) {
            float p0 = ex2f(sc[nt][0] * SC2);
            float p1 = ex2f(sc[nt][1] * SC2);
            float p2 = ex2f(sc[nt][2] * SC2);
            float p3 = ex2f(sc[nt][3] * SC2);
            l0 += p0 + p1; l1 += p2 + p3;
            int c2 = nt * 4 + tig;   // key-pair word index
            pw[gid * QKS_ + c2]       = packbf(p0, p1);
            pw[(gid + 8) * QKS_ + c2] = packbf(p2, p3);
        }
        __syncwarp();

        // P @ V (bf16): 4 k-chunks of 16 keys (8 pairs each)
        #pragma unroll
        for (int kk = 0; kk < 4; kk++) {
            uint32_t a[4];
            const uint32_t* ar  = &pw[gid * QKS_ + kk * 8 + tig];
            const uint32_t* ar1 = &pw[(gid + 8) * QKS_ + kk * 8 + tig];
            a[0] = ar[0]; a[1] = ar1[0]; a[2] = ar[4]; a[3] = ar1[4];
            #pragma unroll
            for (int dt = 0; dt < 8; dt++) {
                uint32_t b0 = vb[(kk * 8 + tig) * VSW_ + dt * 8 + gid];
                uint32_t b1 = vb[(kk * 8 + tig + 4) * VSW_ + dt * 8 + gid];
                mma_bf16(oacc[dt], a, b0, b1);
            }
        }
        if (more) {
            storeV(buf ^ 1);
            CP_WAIT0(); __syncthreads();
        } else __syncwarp();
    }

    // final l reduction (4 threads per row)
    l0 += __shfl_xor_sync(0xffffffffu, l0, 1);
    l0 += __shfl_xor_sync(0xffffffffu, l0, 2);
    l1 += __shfl_xor_sync(0xffffffffu, l1, 1);
    l1 += __shfl_xor_sync(0xffffffffu, l1, 2);

    // write O
    float inv0 = 1.f / l0, inv1 = 1.f / l1;
    int r0 = s0 + wr + gid, r1 = r0 + 8;
    size_t o0 = (size_t)(r0 * B_ + b) * D_ + h * DK_;
    size_t o1 = (size_t)(r1 * B_ + b) * D_ + h * DK_;
    #pragma unroll
    for (int dt = 0; dt < 8; dt++) {
        int c = dt * 8 + tig * 2;
        o[o0 + c]     = oacc[dt][0] * inv0;
        o[o0 + c + 1] = oacc[dt][1] * inv0;
        o[o1 + c]     = oacc[dt][2] * inv1;
        o[o1 + c + 1] = oacc[dt][3] * inv1;
    }
}

// ---------------- gate / routing ----------------
__global__ void gate_kernel(const float* __restrict__ z,
                            const float* __restrict__ wg,
                            const float* __restrict__ bg) {
    int t = blockIdx.x;
    int tid = threadIdx.x;
    int w = tid >> 5, lane = tid & 31;
    __shared__ float lg[E_];
    const float* row = z + (size_t)t * D_;
    float s = 0.f;
    for (int i = lane; i < D_; i += 32) s += row[i] * wg[i * E_ + w];
    #pragma unroll
    for (int off = 16; off; off >>= 1) s += __shfl_down_sync(0xffffffffu, s, off);
    if (lane == 0) lg[w] = s + bg[w];
    __syncthreads();
    if (tid == 0) {
        float mx = lg[0]; int am = 0;
        #pragma unroll
        for (int e = 1; e < E_; e++) if (lg[e] > mx) { mx = lg[e]; am = e; }
        float pr[E_], sum = 0.f;
        #pragma unroll
        for (int e = 0; e < E_; e++) { pr[e] = expf(lg[e] - mx); sum += pr[e]; }
        float inv = 1.f / sum;
        #pragma unroll
        for (int e = 0; e < E_; e++) g_probs[t * E_ + e] = pr[e] * inv;
        g_pmax[t] = pr[am] * inv;
        int pos = atomicAdd(&g_ecount[am], 1);
        g_etok[am * T_ + pos] = t;
    }
}

// ---------------- route_prob_sum (deterministic) ----------------
__global__ void rps_kernel(float* __restrict__ dout, int out_size) {
    int e = blockIdx.x;
    __shared__ float red[256];
    float s = 0.f;
    for (int t = threadIdx.x; t < T_; t += 256) s += g_probs[t * E_ + e];
    red[threadIdx.x] = s; __syncthreads();
    for (int o = 128; o; o >>= 1) { if (threadIdx.x < o) red[threadIdx.x] += red[threadIdx.x+o]; __syncthreads(); }
    if (threadIdx.x == 0 && out_size >= OUT_TOTAL) dout[(size_t)T_ * D_ + E_ + e] = red[0];
}

// ---------------- tail outputs ----------------
__global__ void tail_kernel(float* __restrict__ dout, int out_size) {
    if (out_size < OUT_TOTAL) return;
    int i = blockIdx.x * blockDim.x + threadIdx.x;
    size_t base = (size_t)T_ * D_;
    if (i < E_) dout[base + i] = (float)g_ecount[i];
    if (i == 0) dout[base + 2 * E_] = 0.f;
    if (i < T_) dout[base + 2 * E_ + 1 + i] = g_pmax[i];
}

// ---------------- launch ----------------
extern "C" void kernel_launch(void* const* d_in, const int* in_sizes, int n_in,
                              void* d_out, int out_size) {
    const float* x      = (const float*)d_in[0];
    const float* ln1_g  = (const float*)d_in[1];
    const float* ln1_b  = (const float*)d_in[2];
    const float* ln2_g  = (const float*)d_in[3];
    const float* ln2_b  = (const float*)d_in[4];
    const float* wq     = (const float*)d_in[5];
    const float* bq     = (const float*)d_in[6];
    const float* wk     = (const float*)d_in[7];
    const float* bk     = (const float*)d_in[8];
    const float* wv     = (const float*)d_in[9];
    const float* bv     = (const float*)d_in[10];
    const float* wo     = (const float*)d_in[11];
    const float* bo     = (const float*)d_in[12];
    const float* w_gate = (const float*)d_in[13];
    const float* b_gate = (const float*)d_in[14];
    const float* w1     = (const float*)d_in[15];
    const float* b1     = (const float*)d_in[16];
    const float* w2     = (const float*)d_in[17];
    const float* b2     = (const float*)d_in[18];
    float* out = (float*)d_out;

    float *o, *x2, *z2, *pmaxp;
    __nv_bfloat16 *z1b, *qkvb, *z2b, *hb;
    int *etok, *ecount;
    cudaGetSymbolAddress((void**)&z1b,  g_z1b);
    cudaGetSymbolAddress((void**)&qkvb, g_qkvb);
    cudaGetSymbolAddress((void**)&o,    g_o);
    cudaGetSymbolAddress((void**)&x2,   g_x2);
    cudaGetSymbolAddress((void**)&z2,   g_z2);
    cudaGetSymbolAddress((void**)&z2b,  g_z2b);
    cudaGetSymbolAddress((void**)&hb,   g_hb);
    cudaGetSymbolAddress((void**)&etok,   g_etok);
    cudaGetSymbolAddress((void**)&ecount, g_ecount);
    cudaGetSymbolAddress((void**)&pmaxp,  g_pmax);

    cudaFuncSetAttribute(attn_mma, cudaFuncAttributeMaxDynamicSharedMemorySize, ATTN_SMEM);

    init_kernel<<<1, 32>>>();

    // LN1 (bf16 only)
    ln_kernel<<<T_, 256>>>(x, ln1_g, ln1_b, nullptr, z1b);

    // fused QKV projection (bf16), output bf16 qkv
    mma_gemm<2><<<dim3(3072/128, T_/128, 1), 256>>>(
        (const char*)z1b, wq, wk, wv, bq, bk, bv,
        nullptr, nullptr, nullptr, qkvb, T_, 3072, D_, D_, nullptr, nullptr, 0);

    // attention (all-bf16 MMA)
    attn_mma<<<dim3(S_/128, B_*H_), 256, ATTN_SMEM>>>(qkvb, o);

    // output projection + residual (tf32, precision-critical for routing)
    mma_gemm<4><<<dim3(D_/128, T_/128, 1), 256>>>(
        (const char*)o, wo, nullptr, nullptr, bo, nullptr, nullptr,
        x, nullptr, x2, nullptr, T_, D_, D_, D_, nullptr, nullptr, 0);

    // LN2 (fp32 for gate + bf16 for MoE)
    ln_kernel<<<T_, 256>>>(x2, ln2_g, ln2_b, z2, z2b);

    // gate + routing
    gate_kernel<<<T_, 256>>>(z2, w_gate, b_gate);

    // MoE FFN (grouped by expert, bf16)
    mma_gemm<2><<<dim3(F_/128, T_/128, E_), 256>>>(
        (const char*)z2b, w1, nullptr, nullptr, b1, nullptr, nullptr,
        nullptr, nullptr, nullptr, hb, T_, F_, F_, D_, etok, ecount, 1);
    mma_gemm<2><<<dim3(D_/128, T_/128, E_), 256>>>(
        (const char*)hb, w2, nullptr, nullptr, b2, nullptr, nullptr,
        x2, pmaxp, out, nullptr, T_, D_, D_, F_, etok, ecount, 0);

    // aux outputs
    rps_kernel<<<E_, 256>>>(out, out_size);
    tail_kernel<<<(T_ + 255) / 256, 256>>>(out, out_size);
}

// round 13
// speedup vs baseline: 1.6526x; 1.0657x over previous
#include <cuda_runtime.h>
#include <cuda_bf16.h>
#include <math.h>
#include <stdint.h>

// Problem dims
#define S_  2048
#define B_  2
#define D_  1024
#define H_  16
#define DK_ 64
#define E_  8
#define F_  4096
#define T_  (S_*B_)          // 4096 tokens
#define OUT_TOTAL (T_*D_ + E_ + E_ + 1 + T_)

// ---------------- scratch (device globals) ----------------
__device__ __nv_bfloat16 g_z1b[T_*D_];
__device__ __nv_bfloat16 g_qkvb[(size_t)T_*3072];   // bf16 q|k|v
__device__ float g_o [T_*D_];
__device__ float g_x2[T_*D_];
__device__ float g_z2[T_*D_];
__device__ __nv_bfloat16 g_z2b[T_*D_];
__device__ __nv_bfloat16 g_hb[(size_t)T_*F_];
__device__ float g_probs[T_*E_];
__device__ float g_pmax[T_];
__device__ int   g_etok[E_*T_];
__device__ int   g_ecount[E_];

__device__ __forceinline__ uint32_t f2tf32(float f) {
    uint32_t r; asm("cvt.rna.tf32.f32 %0, %1;" : "=r"(r) : "f"(f)); return r;
}
__device__ __forceinline__ uint32_t packbf(float lo, float hi) {
    __nv_bfloat162 t = __floats2bfloat162_rn(lo, hi);
    return *(uint32_t*)&t;
}
__device__ __forceinline__ float ex2f(float x) {
    float y; asm("ex2.approx.f32 %0, %1;" : "=f"(y) : "f"(x)); return y;
}
__device__ __forceinline__ void mma_bf16(float* c, const uint32_t* a, uint32_t b0, uint32_t b1) {
    asm volatile("mma.sync.aligned.m16n8k16.row.col.f32.bf16.bf16.f32 "
        "{%0,%1,%2,%3}, {%4,%5,%6,%7}, {%8,%9}, {%0,%1,%2,%3};"
        : "+f"(c[0]), "+f"(c[1]), "+f"(c[2]), "+f"(c[3])
        : "r"(a[0]), "r"(a[1]), "r"(a[2]), "r"(a[3]), "r"(b0), "r"(b1));
}
__device__ __forceinline__ void mma_tf32(float* c, const uint32_t* a, uint32_t b0, uint32_t b1) {
    asm volatile("mma.sync.aligned.m16n8k8.row.col.f32.tf32.tf32.f32 "
        "{%0,%1,%2,%3}, {%4,%5,%6,%7}, {%8,%9}, {%0,%1,%2,%3};"
        : "+f"(c[0]), "+f"(c[1]), "+f"(c[2]), "+f"(c[3])
        : "r"(a[0]), "r"(a[1]), "r"(a[2]), "r"(a[3]), "r"(b0), "r"(b1));
}
__device__ __forceinline__ void ldsm4(uint32_t* r, uint32_t addr) {
    asm volatile("ldmatrix.sync.aligned.m8n8.x4.shared.b16 {%0,%1,%2,%3}, [%4];"
        : "=r"(r[0]), "=r"(r[1]), "=r"(r[2]), "=r"(r[3]) : "r"(addr));
}
__device__ __forceinline__ void ldsm4t(uint32_t* r, uint32_t addr) {
    asm volatile("ldmatrix.sync.aligned.m8n8.x4.trans.shared.b16 {%0,%1,%2,%3}, [%4];"
        : "=r"(r[0]), "=r"(r[1]), "=r"(r[2]), "=r"(r[3]) : "r"(addr));
}
__device__ __forceinline__ uint32_t lds32(const char* p) {
    return *(const uint32_t*)p;
}
__device__ __forceinline__ uint32_t smem_u32(const void* p) {
    uint32_t a;
    asm("{ .reg .u64 t; cvta.to.shared.u64 t, %1; cvt.u32.u64 %0, t; }" : "=r"(a) : "l"(p));
    return a;
}
__device__ __forceinline__ void cpa16(uint32_t dst, const void* src) {
    asm volatile("cp.async.cg.shared.global [%0], [%1], 16;" :: "r"(dst), "l"(src));
}
__device__ __forceinline__ void cpa16p(uint32_t dst, const void* src, int sz) {
    asm volatile("cp.async.cg.shared.global [%0], [%1], 16, %2;" :: "r"(dst), "l"(src), "r"(sz));
}
#define CP_COMMIT() asm volatile("cp.async.commit_group;" ::: "memory")
#define CP_WAIT0()  asm volatile("cp.async.wait_group 0;" ::: "memory")

// ---------------- init ----------------
__global__ void init_kernel() {
    int i = threadIdx.x;
    if (i < E_) g_ecount[i] = 0;
}

// ---------------- LayerNorm ----------------
__global__ void ln_kernel(const float* __restrict__ x,
                          const float* __restrict__ gam,
                          const float* __restrict__ bet,
                          float* __restrict__ z,
                          __nv_bfloat16* __restrict__ zb) {
    int t = blockIdx.x;
    const float* row = x + (size_t)t * D_;
    __shared__ float wsum[8], wsq[8];
    int tid = threadIdx.x, lane = tid & 31, wid = tid >> 5;
    float s = 0.f, sq = 0.f;
    #pragma unroll
    for (int i = 0; i < 4; i++) {
        float v = row[tid + i * 256];
        s += v; sq += v * v;
    }
    #pragma unroll
    for (int off = 16; off; off >>= 1) {
        s  += __shfl_xor_sync(0xffffffffu, s,  off);
        sq += __shfl_xor_sync(0xffffffffu, sq, off);
    }
    if (lane == 0) { wsum[wid] = s; wsq[wid] = sq; }
    __syncthreads();
    float ts = 0.f, tq = 0.f;
    #pragma unroll
    for (int w = 0; w < 8; w++) { ts += wsum[w]; tq += wsq[w]; }
    float mean = ts * (1.f / D_);
    float var  = tq * (1.f / D_) - mean * mean;
    float inv  = rsqrtf(var + 1e-5f);
    #pragma unroll
    for (int i = 0; i < 4; i++) {
        int c = tid + i * 256;
        float v = (row[c] - mean) * inv * gam[c] + bet[c];
        if (z)  z[(size_t)t * D_ + c] = v;
        if (zb) zb[(size_t)t * D_ + c] = __float2bfloat16(v);
    }
}

// ---------------- mma.sync GEMM ----------------
// EB=4: tf32, cp.async A+B, smB [16][136] words. EB=2: bf16, cp.async A,
// reg-staged plain [32][68] bf16 B words, ldmatrix fragments.
#define RB 80   // smem A row bytes
#define BPW 68  // bf16 B row stride (words)
template<int EB>
__global__ void __launch_bounds__(256)
mma_gemm(const char* __restrict__ A,
         const float* __restrict__ B0, const float* __restrict__ B1, const float* __restrict__ B2,
         const float* __restrict__ bias0, const float* __restrict__ bias1, const float* __restrict__ bias2,
         const float* __restrict__ res, const float* __restrict__ rowscale,
         float* __restrict__ Cf, __nv_bfloat16* __restrict__ Cb,
         int M, int N, int Nb, int K,
         const int* __restrict__ gather, const int* __restrict__ gcount,
         int relu_flag) {
    constexpr int KC = (EB == 4) ? 16 : 32;
    __shared__ __align__(16) char smraw[2 * 128 * RB + 17408];
    char* smA = smraw;
    uint32_t* smB = (uint32_t*)(smraw + 2 * 128 * RB);   // tf32: [2][16][136]; bf16: [2][32][68]

    int e  = blockIdx.z;
    int m0 = blockIdx.y * 128, n0 = blockIdx.x * 128;
    const float* Bsrc; const float* bias; int nb0;
    if (B1) {
        int part = n0 >> 10; nb0 = n0 & 1023;
        Bsrc = part == 0 ? B0 : (part == 1 ? B1 : B2);
        bias = part == 0 ? bias0 : (part == 1 ? bias1 : bias2);
    } else { Bsrc = B0; bias = bias0; nb0 = n0; }
    const int* glist = nullptr; int mcnt = M;
    if (gather) {
        glist = gather + (size_t)e * T_;
        mcnt  = gcount[e];
        if (m0 >= mcnt) return;
        Bsrc += (size_t)e * K * Nb;
        bias += (size_t)e * Nb;
    }
    int tid = threadIdx.x;
    int wid = tid >> 5, lane = tid & 31;

    int srow = tid >> 2, c4 = tid & 3;
    int rows[2] = { srow, srow + 64 };
    const char* aptr[2]; int asz[2];
    #pragma unroll
    for (int u = 0; u < 2; u++) {
        int rr = m0 + rows[u]; int tok = rr; asz[u] = 16;
        if (gather) { if (rr < mcnt) tok = glist[rr]; else { asz[u] = 0; tok = 0; } }
        aptr[u] = A + (size_t)tok * K * EB + c4 * 16;
    }

    int wm = wid & 3, wn = wid >> 2;
    int wr = wm * 32, wc = wn * 64;
    int gid = lane >> 2, tig = lane & 3;

    float acc[2][8][4];
    #pragma unroll
    for (int mt = 0; mt < 2; mt++)
        #pragma unroll
        for (int nt = 0; nt < 8; nt++)
            #pragma unroll
            for (int j = 0; j < 4; j++) acc[mt][nt][j] = 0.f;

    int nch = K / KC;
    uint32_t sA_a = smem_u32(smA), sB_a = smem_u32(smB);

    if (EB == 4) {
        const float* bbase = Bsrc + nb0 + lane * 4;
        auto prefetch = [&](int i) {
            int buf = i & 1;
            size_t kb = (size_t)i * 64;
            cpa16(sA_a + buf * 128 * RB + rows[0] * RB + c4 * 16, aptr[0] + kb);
            cpa16(sA_a + buf * 128 * RB + rows[1] * RB + c4 * 16, aptr[1] + kb);
            int k0 = i * KC;
            uint32_t dB = sB_a + buf * 16 * 136 * 4;
            cpa16(dB + (wid * 136 + lane * 4) * 4,       bbase + (size_t)(k0 + wid) * Nb);
            cpa16(dB + ((wid + 8) * 136 + lane * 4) * 4, bbase + (size_t)(k0 + wid + 8) * Nb);
            CP_COMMIT();
        };
        prefetch(0);
        CP_WAIT0(); __syncthreads();
        for (int i = 0; i < nch; i++) {
            int buf = i & 1;
            bool more = (i + 1 < nch);
            if (more) prefetch(i + 1);
            const uint32_t* bb = smB + buf * 16 * 136;
            const char* ab = smA + buf * 128 * RB;
            #pragma unroll
            for (int ks = 0; ks < 2; ks++) {
                uint32_t afr[2][4];
                int kb0 = (ks * 8 + tig) * 4;
                #pragma unroll
                for (int mt = 0; mt < 2; mt++) {
                    const char* ap = &ab[(wr + mt * 16 + gid) * RB + kb0];
                    afr[mt][0] = lds32(ap);
                    afr[mt][1] = lds32(ap + 8 * RB);
                    afr[mt][2] = lds32(ap + 16);
                    afr[mt][3] = lds32(ap + 8 * RB + 16);
                }
                int krow = ks * 8 + tig;
                #pragma unroll
                for (int nt = 0; nt < 8; nt++) {
                    uint32_t b0 = bb[krow * 136 + wc + nt * 8 + gid];
                    uint32_t b1 = bb[(krow + 4) * 136 + wc + nt * 8 + gid];
                    mma_tf32(acc[0][nt], afr[0], b0, b1);
                    mma_tf32(acc[1][nt], afr[1], b0, b1);
                }
            }
            if (more) { CP_WAIT0(); __syncthreads(); }
        }
    } else {
        // ---- bf16: cp.async A + reg-staged plain-B + ldmatrix fragments ----
        int bk = tid >> 4, bq = (tid & 15) * 4;     // rows bk, bk+16; cols bq, bq+64
        float4 rb[4];
        auto prefetchA = [&](int i) {
            int buf = i & 1;
            size_t kb = (size_t)i * 64;
            cpa16p(sA_a + buf * 128 * RB + rows[0] * RB + c4 * 16, aptr[0] + kb, asz[0]);
            cpa16p(sA_a + buf * 128 * RB + rows[1] * RB + c4 * 16, aptr[1] + kb, asz[1]);
            CP_COMMIT();
        };
        auto loadB = [&](int i) {
            int k0 = i * KC;
            const float* r0 = Bsrc + (size_t)(k0 + bk) * Nb + nb0;
            const float* r1 = Bsrc + (size_t)(k0 + bk + 16) * Nb + nb0;
            rb[0] = *(const float4*)(r0 + bq);
            rb[1] = *(const float4*)(r0 + bq + 64);
            rb[2] = *(const float4*)(r1 + bq);
            rb[3] = *(const float4*)(r1 + bq + 64);
        };
        auto storeB = [&](int buf) {
            uint32_t* d0 = smB + buf * 32 * BPW + bk * BPW;
            uint32_t* d1 = d0 + 16 * BPW;
            *(uint2*)&d0[bq / 2]      = make_uint2(packbf(rb[0].x, rb[0].y), packbf(rb[0].z, rb[0].w));
            *(uint2*)&d0[bq / 2 + 32] = make_uint2(packbf(rb[1].x, rb[1].y), packbf(rb[1].z, rb[1].w));
            *(uint2*)&d1[bq / 2]      = make_uint2(packbf(rb[2].x, rb[2].y), packbf(rb[2].z, rb[2].w));
            *(uint2*)&d1[bq / 2 + 32] = make_uint2(packbf(rb[3].x, rb[3].y), packbf(rb[3].z, rb[3].w));
        };
        // ldmatrix per-lane address components
        int l8 = lane & 7, lh = (lane >> 3) & 1, lq = lane >> 4;
        prefetchA(0); loadB(0); storeB(0);
        CP_WAIT0(); __syncthreads();
        for (int i = 0; i < nch; i++) {
            int buf = i & 1;
            bool more = (i + 1 < nch);
            if (more) { prefetchA(i + 1); loadB(i + 1); }
            uint32_t abase = sA_a + buf * 128 * RB;
            uint32_t bbase2 = sB_a + (buf * 32 * BPW) * 4;
            #pragma unroll
            for (int ks = 0; ks < 2; ks++) {
                uint32_t afr[2][4];
                #pragma unroll
                for (int mt = 0; mt < 2; mt++)
                    ldsm4(afr[mt], abase + (wr + mt * 16 + lh * 8 + l8) * RB + ks * 32 + lq * 16);
                #pragma unroll
                for (int ntp = 0; ntp < 4; ntp++) {
                    uint32_t bb4[4];
                    ldsm4t(bb4, bbase2 + ((ks * 16 + lh * 8 + l8) * BPW) * 4
                                + (wc + (ntp * 2 + lq) * 8) * 2);
                    mma_bf16(acc[0][ntp * 2],     afr[0], bb4[0], bb4[1]);
                    mma_bf16(acc[1][ntp * 2],     afr[1], bb4[0], bb4[1]);
                    mma_bf16(acc[0][ntp * 2 + 1], afr[0], bb4[2], bb4[3]);
                    mma_bf16(acc[1][ntp * 2 + 1], afr[1], bb4[2], bb4[3]);
                }
            }
            if (more) { storeB(buf ^ 1); CP_WAIT0(); __syncthreads(); }
        }
    }

    // epilogue
    #pragma unroll
    for (int mt = 0; mt < 2; mt++) {
        #pragma unroll
        for (int half = 0; half < 2; half++) {
            int r = m0 + wr + mt * 16 + gid + half * 8;
            int tok = r; bool valid = true;
            if (gather) { if (r < mcnt) tok = glist[r]; else valid = false; }
            if (!valid) continue;
            float sc = rowscale ? rowscale[tok] : 1.f;
            size_t ob = (size_t)tok * N;
            #pragma unroll
            for (int nt = 0; nt < 8; nt++) {
                int c  = n0 + wc + nt * 8 + tig * 2;
                int cb = nb0 + wc + nt * 8 + tig * 2;
                float v0 = acc[mt][nt][half * 2 + 0] + bias[cb];
                float v1 = acc[mt][nt][half * 2 + 1] + bias[cb + 1];
                if (relu_flag) { v0 = fmaxf(v0, 0.f); v1 = fmaxf(v1, 0.f); }
                v0 *= sc; v1 *= sc;
                if (res) { v0 += res[ob + c]; v1 += res[ob + c + 1]; }
                if (Cb) {
                    *(__nv_bfloat162*)&Cb[ob + c] = __floats2bfloat162_rn(v0, v1);
                } else {
                    Cf[ob + c]     = v0;
                    Cf[ob + c + 1] = v1;
                }
            }
        }
    }
}

// ---------------- flash attention: all-bf16, ldmatrix fragments ----------------
// Q/K/P/V all stride 36 words. V in natural [key][d] bf16 layout (cp.async),
// B-fragments via ldmatrix (K non-trans on [key][d-pair], V trans on [key][d]).
#define QKS_ 36
#define ATTN_SMEM ((128*QKS_ + 2*64*QKS_ + 2*64*QKS_) * 4)
__global__ void __launch_bounds__(256, 2)
attn_mma(const __nv_bfloat16* __restrict__ qkvb, float* __restrict__ o) {
    extern __shared__ uint32_t sm[];
    uint32_t* pS = sm;                    // [128][QKS_] Q bf16 staging, then P bf16
    uint32_t* kS = pS + 128 * QKS_;       // [2][64][QKS_]
    uint32_t* vS = kS + 2 * 64 * QKS_;    // [2][64][QKS_] natural [key][d]

    int bh = blockIdx.y;
    int b = bh % B_, h = bh / B_;
    int s0 = blockIdx.x * 128;
    int tid = threadIdx.x, lane = tid & 31, wid = tid >> 5;
    int gid = lane >> 2, tig = lane & 3;
    int l8 = lane & 7, lh = (lane >> 3) & 1, lq = lane >> 4;
    int wr = wid * 16;
    const float SC2 = 0.125f * 1.44269504f;

    uint32_t pS_a = smem_u32(pS), kS_a = smem_u32(kS), vS_a = smem_u32(vS);

    // prologue: cp.async Q + K/V tile 0
    {
        int qr = tid >> 1, qseg = tid & 1;
        const __nv_bfloat16* qp = qkvb + (size_t)((s0 + qr) * B_ + b) * 3072 + h * DK_;
        #pragma unroll
        for (int j = 0; j < 4; j++)
            cpa16(pS_a + (qr * QKS_ + qseg * 16 + j * 4) * 4,
                  (const char*)qp + qseg * 64 + j * 16);
    }
    int kr = tid >> 2, kseg = tid & 3;
    auto prefetchKV = [&](int i) {
        int buf = i & 1;
        int t = (i * 64 + kr) * B_ + b;
        const __nv_bfloat16* kp = qkvb + (size_t)t * 3072 + 1024 + h * DK_;
        const __nv_bfloat16* vp = kp + 1024;
        #pragma unroll
        for (int j = 0; j < 2; j++) {
            cpa16(kS_a + ((buf * 64 + kr) * QKS_ + kseg * 8 + j * 4) * 4,
                  (const char*)kp + kseg * 32 + j * 16);
            cpa16(vS_a + ((buf * 64 + kr) * QKS_ + kseg * 8 + j * 4) * 4,
                  (const char*)vp + kseg * 32 + j * 16);
        }
        CP_COMMIT();
    };
    prefetchKV(0);
    CP_WAIT0(); __syncthreads();

    // Q fragments via ldmatrix (own warp rows)
    uint32_t qfb[4][4];
    {
        uint32_t qbase = pS_a + ((wr + lh * 8 + l8) * QKS_) * 4;
        #pragma unroll
        for (int kk = 0; kk < 4; kk++)
            ldsm4(qfb[kk], qbase + (kk * 8 + lq * 4) * 4);
    }
    __syncwarp();

    float oacc[8][4];
    #pragma unroll
    for (int dt = 0; dt < 8; dt++)
        #pragma unroll
        for (int j = 0; j < 4; j++) oacc[dt][j] = 0.f;
    float l0 = 0.f, l1 = 0.f;
    uint32_t* pw = pS + wid * 16 * QKS_;
    uint32_t pw_a = pS_a + (wid * 16 * QKS_) * 4;

    const int NT = S_ / 64;
    for (int i = 0; i < NT; i++) {
        int buf = i & 1;
        bool more = (i + 1 < NT);
        if (more) prefetchKV(i + 1);
        uint32_t kb_a = kS_a + (buf * 64 * QKS_) * 4;
        uint32_t vb_a = vS_a + (buf * 64 * QKS_) * 4;

        // scores 16x64: K fragments via ldmatrix (2 nt per x4)
        float sc[8][4];
        #pragma unroll
        for (int nt = 0; nt < 8; nt++)
            #pragma unroll
            for (int j = 0; j < 4; j++) sc[nt][j] = 0.f;
        #pragma unroll
        for (int kk = 0; kk < 4; kk++) {
            #pragma unroll
            for (int ntp = 0; ntp < 4; ntp++) {
                uint32_t kb4[4];
                ldsm4(kb4, kb_a + (((ntp * 2 + lq) * 8 + l8) * QKS_ + kk * 8 + lh * 4) * 4);
                mma_bf16(sc[ntp * 2],     qfb[kk], kb4[0], kb4[1]);
                mma_bf16(sc[ntp * 2 + 1], qfb[kk], kb4[2], kb4[3]);
            }
        }

        // no-max softmax; write P as bf16 key-pairs
        #pragma unroll
        for (int nt = 0; nt < 8; nt++) {
            float p0 = ex2f(sc[nt][0] * SC2);
            float p1 = ex2f(sc[nt][1] * SC2);
            float p2 = ex2f(sc[nt][2] * SC2);
            float p3 = ex2f(sc[nt][3] * SC2);
            l0 += p0 + p1; l1 += p2 + p3;
            int c2 = nt * 4 + tig;
            pw[gid * QKS_ + c2]       = packbf(p0, p1);
            pw[(gid + 8) * QKS_ + c2] = packbf(p2, p3);
        }
        __syncwarp();

        // P @ V: P via ldmatrix, V via ldmatrix.trans (2 dt per x4)
        #pragma unroll
        for (int kk = 0; kk < 4; kk++) {
            uint32_t pa[4];
            ldsm4(pa, pw_a + ((lh * 8 + l8) * QKS_ + kk * 8 + lq * 4) * 4);
            #pragma unroll
            for (int dtp = 0; dtp < 4; dtp++) {
                uint32_t vb4[4];
                ldsm4t(vb4, vb_a + ((kk * 16 + lh * 8 + l8) * QKS_) * 4 + (dtp * 2 + lq) * 16);
                mma_bf16(oacc[dtp * 2],     pa, vb4[0], vb4[1]);
                mma_bf16(oacc[dtp * 2 + 1], pa, vb4[2], vb4[3]);
            }
        }
        if (more) { CP_WAIT0(); __syncthreads(); }
        else __syncwarp();
    }

    // final l reduction (4 threads per row)
    l0 += __shfl_xor_sync(0xffffffffu, l0, 1);
    l0 += __shfl_xor_sync(0xffffffffu, l0, 2);
    l1 += __shfl_xor_sync(0xffffffffu, l1, 1);
    l1 += __shfl_xor_sync(0xffffffffu, l1, 2);

    // write O
    float inv0 = 1.f / l0, inv1 = 1.f / l1;
    int r0 = s0 + wr + gid, r1 = r0 + 8;
    size_t o0 = (size_t)(r0 * B_ + b) * D_ + h * DK_;
    size_t o1 = (size_t)(r1 * B_ + b) * D_ + h * DK_;
    #pragma unroll
    for (int dt = 0; dt < 8; dt++) {
        int c = dt * 8 + tig * 2;
        o[o0 + c]     = oacc[dt][0] * inv0;
        o[o0 + c + 1] = oacc[dt][1] * inv0;
        o[o1 + c]     = oacc[dt][2] * inv1;
        o[o1 + c + 1] = oacc[dt][3] * inv1;
    }
}

// ---------------- gate / routing ----------------
__global__ void gate_kernel(const float* __restrict__ z,
                            const float* __restrict__ wg,
                            const float* __restrict__ bg) {
    int t = blockIdx.x;
    int tid = threadIdx.x;
    int w = tid >> 5, lane = tid & 31;
    __shared__ float lg[E_];
    const float* row = z + (size_t)t * D_;
    float s = 0.f;
    for (int i = lane; i < D_; i += 32) s += row[i] * wg[i * E_ + w];
    #pragma unroll
    for (int off = 16; off; off >>= 1) s += __shfl_down_sync(0xffffffffu, s, off);
    if (lane == 0) lg[w] = s + bg[w];
    __syncthreads();
    if (tid == 0) {
        float mx = lg[0]; int am = 0;
        #pragma unroll
        for (int e = 1; e < E_; e++) if (lg[e] > mx) { mx = lg[e]; am = e; }
        float pr[E_], sum = 0.f;
        #pragma unroll
        for (int e = 0; e < E_; e++) { pr[e] = expf(lg[e] - mx); sum += pr[e]; }
        float inv = 1.f / sum;
        #pragma unroll
        for (int e = 0; e < E_; e++) g_probs[t * E_ + e] = pr[e] * inv;
        g_pmax[t] = pr[am] * inv;
        int pos = atomicAdd(&g_ecount[am], 1);
        g_etok[am * T_ + pos] = t;
    }
}

// ---------------- route_prob_sum ----------------
__global__ void rps_kernel(float* __restrict__ dout, int out_size) {
    int e = blockIdx.x;
    __shared__ float red[256];
    float s = 0.f;
    for (int t = threadIdx.x; t < T_; t += 256) s += g_probs[t * E_ + e];
    red[threadIdx.x] = s; __syncthreads();
    for (int o = 128; o; o >>= 1) { if (threadIdx.x < o) red[threadIdx.x] += red[threadIdx.x+o]; __syncthreads(); }
    if (threadIdx.x == 0 && out_size >= OUT_TOTAL) dout[(size_t)T_ * D_ + E_ + e] = red[0];
}

// ---------------- tail outputs ----------------
__global__ void tail_kernel(float* __restrict__ dout, int out_size) {
    if (out_size < OUT_TOTAL) return;
    int i = blockIdx.x * blockDim.x + threadIdx.x;
    size_t base = (size_t)T_ * D_;
    if (i < E_) dout[base + i] = (float)g_ecount[i];
    if (i == 0) dout[base + 2 * E_] = 0.f;
    if (i < T_) dout[base + 2 * E_ + 1 + i] = g_pmax[i];
}

// ---------------- launch ----------------
extern "C" void kernel_launch(void* const* d_in, const int* in_sizes, int n_in,
                              void* d_out, int out_size) {
    const float* x      = (const float*)d_in[0];
    const float* ln1_g  = (const float*)d_in[1];
    const float* ln1_b  = (const float*)d_in[2];
    const float* ln2_g  = (const float*)d_in[3];
    const float* ln2_b  = (const float*)d_in[4];
    const float* wq     = (const float*)d_in[5];
    const float* bq     = (const float*)d_in[6];
    const float* wk     = (const float*)d_in[7];
    const float* bk     = (const float*)d_in[8];
    const float* wv     = (const float*)d_in[9];
    const float* bv     = (const float*)d_in[10];
    const float* wo     = (const float*)d_in[11];
    const float* bo     = (const float*)d_in[12];
    const float* w_gate = (const float*)d_in[13];
    const float* b_gate = (const float*)d_in[14];
    const float* w1     = (const float*)d_in[15];
    const float* b1     = (const float*)d_in[16];
    const float* w2     = (const float*)d_in[17];
    const float* b2     = (const float*)d_in[18];
    float* out = (float*)d_out;

    float *o, *x2, *z2, *pmaxp;
    __nv_bfloat16 *z1b, *qkvb, *z2b, *hb;
    int *etok, *ecount;
    cudaGetSymbolAddress((void**)&z1b,  g_z1b);
    cudaGetSymbolAddress((void**)&qkvb, g_qkvb);
    cudaGetSymbolAddress((void**)&o,    g_o);
    cudaGetSymbolAddress((void**)&x2,   g_x2);
    cudaGetSymbolAddress((void**)&z2,   g_z2);
    cudaGetSymbolAddress((void**)&z2b,  g_z2b);
    cudaGetSymbolAddress((void**)&hb,   g_hb);
    cudaGetSymbolAddress((void**)&etok,   g_etok);
    cudaGetSymbolAddress((void**)&ecount, g_ecount);
    cudaGetSymbolAddress((void**)&pmaxp,  g_pmax);

    cudaFuncSetAttribute(attn_mma, cudaFuncAttributeMaxDynamicSharedMemorySize, ATTN_SMEM);

    init_kernel<<<1, 32>>>();

    // LN1 (bf16 only)
    ln_kernel<<<T_, 256>>>(x, ln1_g, ln1_b, nullptr, z1b);

    // fused QKV projection (bf16, ldmatrix)
    mma_gemm<2><<<dim3(3072/128, T_/128, 1), 256>>>(
        (const char*)z1b, wq, wk, wv, bq, bk, bv,
        nullptr, nullptr, nullptr, qkvb, T_, 3072, D_, D_, nullptr, nullptr, 0);

    // attention (all-bf16, ldmatrix)
    attn_mma<<<dim3(S_/128, B_*H_), 256, ATTN_SMEM>>>(qkvb, o);

    // output projection + residual (tf32, precision-critical for routing)
    mma_gemm<4><<<dim3(D_/128, T_/128, 1), 256>>>(
        (const char*)o, wo, nullptr, nullptr, bo, nullptr, nullptr,
        x, nullptr, x2, nullptr, T_, D_, D_, D_, nullptr, nullptr, 0);

    // LN2 (fp32 for gate + bf16 for MoE)
    ln_kernel<<<T_, 256>>>(x2, ln2_g, ln2_b, z2, z2b);

    // gate + routing
    gate_kernel<<<T_, 256>>>(z2, w_gate, b_gate);

    // MoE FFN (grouped by expert, bf16, ldmatrix)
    mma_gemm<2><<<dim3(F_/128, T_/128, E_), 256>>>(
        (const char*)z2b, w1, nullptr, nullptr, b1, nullptr, nullptr,
        nullptr, nullptr, nullptr, hb, T_, F_, F_, D_, etok, ecount, 1);
    mma_gemm<2><<<dim3(D_/128, T_/128, E_), 256>>>(
        (const char*)hb, w2, nullptr, nullptr, b2, nullptr, nullptr,
        x2, pmaxp, out, nullptr, T_, D_, D_, F_, etok, ecount, 0);

    // aux outputs
    rps_kernel<<<E_, 256>>>(out, out_size);
    tail_kernel<<<(T_ + 255) / 256, 256>>>(out, out_size);
}

// round 14
// speedup vs baseline: 1.7213x; 1.0416x over previous
#include <cuda_runtime.h>
#include <cuda_bf16.h>
#include <math.h>
#include <stdint.h>

// Problem dims
#define S_  2048
#define B_  2
#define D_  1024
#define H_  16
#define DK_ 64
#define E_  8
#define F_  4096
#define T_  (S_*B_)          // 4096 tokens
#define OUT_TOTAL (T_*D_ + E_ + E_ + 1 + T_)

// ---------------- scratch (device globals) ----------------
__device__ __nv_bfloat16 g_z1b[T_*D_];
__device__ __nv_bfloat16 g_qkvb[(size_t)T_*3072];   // bf16 q|k|v
__device__ float g_o [T_*D_];
__device__ float g_x2[T_*D_];
__device__ __nv_bfloat16 g_z2b[T_*D_];
__device__ __nv_bfloat16 g_hb[(size_t)T_*F_];
__device__ float g_probs[T_*E_];
__device__ float g_pmax[T_];
__device__ int   g_etok[E_*T_];
__device__ int   g_ecount[E_];

__device__ __forceinline__ uint32_t packbf(float lo, float hi) {
    __nv_bfloat162 t = __floats2bfloat162_rn(lo, hi);
    return *(uint32_t*)&t;
}
__device__ __forceinline__ float ex2f(float x) {
    float y; asm("ex2.approx.f32 %0, %1;" : "=f"(y) : "f"(x)); return y;
}
__device__ __forceinline__ void mma_bf16(float* c, const uint32_t* a, uint32_t b0, uint32_t b1) {
    asm volatile("mma.sync.aligned.m16n8k16.row.col.f32.bf16.bf16.f32 "
        "{%0,%1,%2,%3}, {%4,%5,%6,%7}, {%8,%9}, {%0,%1,%2,%3};"
        : "+f"(c[0]), "+f"(c[1]), "+f"(c[2]), "+f"(c[3])
        : "r"(a[0]), "r"(a[1]), "r"(a[2]), "r"(a[3]), "r"(b0), "r"(b1));
}
__device__ __forceinline__ void mma_tf32(float* c, const uint32_t* a, uint32_t b0, uint32_t b1) {
    asm volatile("mma.sync.aligned.m16n8k8.row.col.f32.tf32.tf32.f32 "
        "{%0,%1,%2,%3}, {%4,%5,%6,%7}, {%8,%9}, {%0,%1,%2,%3};"
        : "+f"(c[0]), "+f"(c[1]), "+f"(c[2]), "+f"(c[3])
        : "r"(a[0]), "r"(a[1]), "r"(a[2]), "r"(a[3]), "r"(b0), "r"(b1));
}
__device__ __forceinline__ void ldsm4(uint32_t* r, uint32_t addr) {
    asm volatile("ldmatrix.sync.aligned.m8n8.x4.shared.b16 {%0,%1,%2,%3}, [%4];"
        : "=r"(r[0]), "=r"(r[1]), "=r"(r[2]), "=r"(r[3]) : "r"(addr));
}
__device__ __forceinline__ void ldsm4t(uint32_t* r, uint32_t addr) {
    asm volatile("ldmatrix.sync.aligned.m8n8.x4.trans.shared.b16 {%0,%1,%2,%3}, [%4];"
        : "=r"(r[0]), "=r"(r[1]), "=r"(r[2]), "=r"(r[3]) : "r"(addr));
}
__device__ __forceinline__ uint32_t lds32(const char* p) {
    return *(const uint32_t*)p;
}
__device__ __forceinline__ uint32_t smem_u32(const void* p) {
    uint32_t a;
    asm("{ .reg .u64 t; cvta.to.shared.u64 t, %1; cvt.u32.u64 %0, t; }" : "=r"(a) : "l"(p));
    return a;
}
__device__ __forceinline__ void cpa16(uint32_t dst, const void* src) {
    asm volatile("cp.async.cg.shared.global [%0], [%1], 16;" :: "r"(dst), "l"(src));
}
__device__ __forceinline__ void cpa16p(uint32_t dst, const void* src, int sz) {
    asm volatile("cp.async.cg.shared.global [%0], [%1], 16, %2;" :: "r"(dst), "l"(src), "r"(sz));
}
#define CP_COMMIT() asm volatile("cp.async.commit_group;" ::: "memory")
#define CP_WAIT0()  asm volatile("cp.async.wait_group 0;" ::: "memory")

// ---------------- init ----------------
__global__ void init_kernel() {
    int i = threadIdx.x;
    if (i < E_) g_ecount[i] = 0;
}

// ---------------- LayerNorm (LN1: bf16 out only) ----------------
__global__ void ln_kernel(const float* __restrict__ x,
                          const float* __restrict__ gam,
                          const float* __restrict__ bet,
                          __nv_bfloat16* __restrict__ zb) {
    int t = blockIdx.x;
    const float* row = x + (size_t)t * D_;
    __shared__ float wsum[8], wsq[8];
    int tid = threadIdx.x, lane = tid & 31, wid = tid >> 5;
    float s = 0.f, sq = 0.f;
    #pragma unroll
    for (int i = 0; i < 4; i++) {
        float v = row[tid + i * 256];
        s += v; sq += v * v;
    }
    #pragma unroll
    for (int off = 16; off; off >>= 1) {
        s  += __shfl_xor_sync(0xffffffffu, s,  off);
        sq += __shfl_xor_sync(0xffffffffu, sq, off);
    }
    if (lane == 0) { wsum[wid] = s; wsq[wid] = sq; }
    __syncthreads();
    float ts = 0.f, tq = 0.f;
    #pragma unroll
    for (int w = 0; w < 8; w++) { ts += wsum[w]; tq += wsq[w]; }
    float mean = ts * (1.f / D_);
    float var  = tq * (1.f / D_) - mean * mean;
    float inv  = rsqrtf(var + 1e-5f);
    #pragma unroll
    for (int i = 0; i < 4; i++) {
        int c = tid + i * 256;
        float v = (row[c] - mean) * inv * gam[c] + bet[c];
        zb[(size_t)t * D_ + c] = __float2bfloat16(v);
    }
}

// ---------------- fused LN2 + gate/routing ----------------
__global__ void ln2_gate_kernel(const float* __restrict__ x,
                                const float* __restrict__ gam,
                                const float* __restrict__ bet,
                                const float* __restrict__ wg,   // [D][E]
                                const float* __restrict__ bg,
                                __nv_bfloat16* __restrict__ zb) {
    int t = blockIdx.x;
    const float* row = x + (size_t)t * D_;
    __shared__ float wsum[8], wsq[8];
    __shared__ float wlog[8][E_];
    int tid = threadIdx.x, lane = tid & 31, wid = tid >> 5;
    float s = 0.f, sq = 0.f;
    float xv[4];
    #pragma unroll
    for (int i = 0; i < 4; i++) {
        xv[i] = row[tid + i * 256];
        s += xv[i]; sq += xv[i] * xv[i];
    }
    #pragma unroll
    for (int off = 16; off; off >>= 1) {
        s  += __shfl_xor_sync(0xffffffffu, s,  off);
        sq += __shfl_xor_sync(0xffffffffu, sq, off);
    }
    if (lane == 0) { wsum[wid] = s; wsq[wid] = sq; }
    __syncthreads();
    float ts = 0.f, tq = 0.f;
    #pragma unroll
    for (int w = 0; w < 8; w++) { ts += wsum[w]; tq += wsq[w]; }
    float mean = ts * (1.f / D_);
    float var  = tq * (1.f / D_) - mean * mean;
    float inv  = rsqrtf(var + 1e-5f);
    float part[E_];
    #pragma unroll
    for (int e = 0; e < E_; e++) part[e] = 0.f;
    #pragma unroll
    for (int i = 0; i < 4; i++) {
        int c = tid + i * 256;
        float v = (xv[i] - mean) * inv * gam[c] + bet[c];
        zb[(size_t)t * D_ + c] = __float2bfloat16(v);
        const float4* wgp = (const float4*)&wg[(size_t)c * E_];
        float4 w0 = wgp[0], w1 = wgp[1];
        part[0] += v * w0.x; part[1] += v * w0.y; part[2] += v * w0.z; part[3] += v * w0.w;
        part[4] += v * w1.x; part[5] += v * w1.y; part[6] += v * w1.z; part[7] += v * w1.w;
    }
    #pragma unroll
    for (int e = 0; e < E_; e++) {
        #pragma unroll
        for (int off = 16; off; off >>= 1)
            part[e] += __shfl_xor_sync(0xffffffffu, part[e], off);
    }
    if (lane == 0) {
        #pragma unroll
        for (int e = 0; e < E_; e++) wlog[wid][e] = part[e];
    }
    __syncthreads();
    if (tid == 0) {
        float lg[E_];
        #pragma unroll
        for (int e = 0; e < E_; e++) {
            float a = bg[e];
            #pragma unroll
            for (int w = 0; w < 8; w++) a += wlog[w][e];
            lg[e] = a;
        }
        float mx = lg[0]; int am = 0;
        #pragma unroll
        for (int e = 1; e < E_; e++) if (lg[e] > mx) { mx = lg[e]; am = e; }
        float pr[E_], sum = 0.f;
        #pragma unroll
        for (int e = 0; e < E_; e++) { pr[e] = expf(lg[e] - mx); sum += pr[e]; }
        float invs = 1.f / sum;
        #pragma unroll
        for (int e = 0; e < E_; e++) g_probs[t * E_ + e] = pr[e] * invs;
        g_pmax[t] = pr[am] * invs;
        int pos = atomicAdd(&g_ecount[am], 1);
        g_etok[am * T_ + pos] = t;
    }
}

// ---------------- mma.sync GEMM (unchanged from R13) ----------------
#define RB 80   // smem A row bytes
#define BPW 68  // bf16 B row stride (words)
template<int EB>
__global__ void __launch_bounds__(256)
mma_gemm(const char* __restrict__ A,
         const float* __restrict__ B0, const float* __restrict__ B1, const float* __restrict__ B2,
         const float* __restrict__ bias0, const float* __restrict__ bias1, const float* __restrict__ bias2,
         const float* __restrict__ res, const float* __restrict__ rowscale,
         float* __restrict__ Cf, __nv_bfloat16* __restrict__ Cb,
         int M, int N, int Nb, int K,
         const int* __restrict__ gather, const int* __restrict__ gcount,
         int relu_flag) {
    constexpr int KC = (EB == 4) ? 16 : 32;
    __shared__ __align__(16) char smraw[2 * 128 * RB + 17408];
    char* smA = smraw;
    uint32_t* smB = (uint32_t*)(smraw + 2 * 128 * RB);

    int e  = blockIdx.z;
    int m0 = blockIdx.y * 128, n0 = blockIdx.x * 128;
    const float* Bsrc; const float* bias; int nb0;
    if (B1) {
        int part = n0 >> 10; nb0 = n0 & 1023;
        Bsrc = part == 0 ? B0 : (part == 1 ? B1 : B2);
        bias = part == 0 ? bias0 : (part == 1 ? bias1 : bias2);
    } else { Bsrc = B0; bias = bias0; nb0 = n0; }
    const int* glist = nullptr; int mcnt = M;
    if (gather) {
        glist = gather + (size_t)e * T_;
        mcnt  = gcount[e];
        if (m0 >= mcnt) return;
        Bsrc += (size_t)e * K * Nb;
        bias += (size_t)e * Nb;
    }
    int tid = threadIdx.x;
    int wid = tid >> 5, lane = tid & 31;

    int srow = tid >> 2, c4 = tid & 3;
    int rows[2] = { srow, srow + 64 };
    const char* aptr[2]; int asz[2];
    #pragma unroll
    for (int u = 0; u < 2; u++) {
        int rr = m0 + rows[u]; int tok = rr; asz[u] = 16;
        if (gather) { if (rr < mcnt) tok = glist[rr]; else { asz[u] = 0; tok = 0; } }
        aptr[u] = A + (size_t)tok * K * EB + c4 * 16;
    }

    int wm = wid & 3, wn = wid >> 2;
    int wr = wm * 32, wc = wn * 64;
    int gid = lane >> 2, tig = lane & 3;

    float acc[2][8][4];
    #pragma unroll
    for (int mt = 0; mt < 2; mt++)
        #pragma unroll
        for (int nt = 0; nt < 8; nt++)
            #pragma unroll
            for (int j = 0; j < 4; j++) acc[mt][nt][j] = 0.f;

    int nch = K / KC;
    uint32_t sA_a = smem_u32(smA), sB_a = smem_u32(smB);

    if (EB == 4) {
        const float* bbase = Bsrc + nb0 + lane * 4;
        auto prefetch = [&](int i) {
            int buf = i & 1;
            size_t kb = (size_t)i * 64;
            cpa16(sA_a + buf * 128 * RB + rows[0] * RB + c4 * 16, aptr[0] + kb);
            cpa16(sA_a + buf * 128 * RB + rows[1] * RB + c4 * 16, aptr[1] + kb);
            int k0 = i * KC;
            uint32_t dB = sB_a + buf * 16 * 136 * 4;
            cpa16(dB + (wid * 136 + lane * 4) * 4,       bbase + (size_t)(k0 + wid) * Nb);
            cpa16(dB + ((wid + 8) * 136 + lane * 4) * 4, bbase + (size_t)(k0 + wid + 8) * Nb);
            CP_COMMIT();
        };
        prefetch(0);
        CP_WAIT0(); __syncthreads();
        for (int i = 0; i < nch; i++) {
            int buf = i & 1;
            bool more = (i + 1 < nch);
            if (more) prefetch(i + 1);
            const uint32_t* bb = smB + buf * 16 * 136;
            const char* ab = smA + buf * 128 * RB;
            #pragma unroll
            for (int ks = 0; ks < 2; ks++) {
                uint32_t afr[2][4];
                int kb0 = (ks * 8 + tig) * 4;
                #pragma unroll
                for (int mt = 0; mt < 2; mt++) {
                    const char* ap = &ab[(wr + mt * 16 + gid) * RB + kb0];
                    afr[mt][0] = lds32(ap);
                    afr[mt][1] = lds32(ap + 8 * RB);
                    afr[mt][2] = lds32(ap + 16);
                    afr[mt][3] = lds32(ap + 8 * RB + 16);
                }
                int krow = ks * 8 + tig;
                #pragma unroll
                for (int nt = 0; nt < 8; nt++) {
                    uint32_t b0 = bb[krow * 136 + wc + nt * 8 + gid];
                    uint32_t b1 = bb[(krow + 4) * 136 + wc + nt * 8 + gid];
                    mma_tf32(acc[0][nt], afr[0], b0, b1);
                    mma_tf32(acc[1][nt], afr[1], b0, b1);
                }
            }
            if (more) { CP_WAIT0(); __syncthreads(); }
        }
    } else {
        int bk = tid >> 4, bq = (tid & 15) * 4;
        float4 rb[4];
        auto prefetchA = [&](int i) {
            int buf = i & 1;
            size_t kb = (size_t)i * 64;
            cpa16p(sA_a + buf * 128 * RB + rows[0] * RB + c4 * 16, aptr[0] + kb, asz[0]);
            cpa16p(sA_a + buf * 128 * RB + rows[1] * RB + c4 * 16, aptr[1] + kb, asz[1]);
            CP_COMMIT();
        };
        auto loadB = [&](int i) {
            int k0 = i * KC;
            const float* r0 = Bsrc + (size_t)(k0 + bk) * Nb + nb0;
            const float* r1 = Bsrc + (size_t)(k0 + bk + 16) * Nb + nb0;
            rb[0] = *(const float4*)(r0 + bq);
            rb[1] = *(const float4*)(r0 + bq + 64);
            rb[2] = *(const float4*)(r1 + bq);
            rb[3] = *(const float4*)(r1 + bq + 64);
        };
        auto storeB = [&](int buf) {
            uint32_t* d0 = smB + buf * 32 * BPW + bk * BPW;
            uint32_t* d1 = d0 + 16 * BPW;
            *(uint2*)&d0[bq / 2]      = make_uint2(packbf(rb[0].x, rb[0].y), packbf(rb[0].z, rb[0].w));
            *(uint2*)&d0[bq / 2 + 32] = make_uint2(packbf(rb[1].x, rb[1].y), packbf(rb[1].z, rb[1].w));
            *(uint2*)&d1[bq / 2]      = make_uint2(packbf(rb[2].x, rb[2].y), packbf(rb[2].z, rb[2].w));
            *(uint2*)&d1[bq / 2 + 32] = make_uint2(packbf(rb[3].x, rb[3].y), packbf(rb[3].z, rb[3].w));
        };
        int l8 = lane & 7, lh = (lane >> 3) & 1, lq = lane >> 4;
        prefetchA(0); loadB(0); storeB(0);
        CP_WAIT0(); __syncthreads();
        for (int i = 0; i < nch; i++) {
            int buf = i & 1;
            bool more = (i + 1 < nch);
            if (more) { prefetchA(i + 1); loadB(i + 1); }
            uint32_t abase = sA_a + buf * 128 * RB;
            uint32_t bbase2 = sB_a + (buf * 32 * BPW) * 4;
            #pragma unroll
            for (int ks = 0; ks < 2; ks++) {
                uint32_t afr[2][4];
                #pragma unroll
                for (int mt = 0; mt < 2; mt++)
                    ldsm4(afr[mt], abase + (wr + mt * 16 + lh * 8 + l8) * RB + ks * 32 + lq * 16);
                #pragma unroll
                for (int ntp = 0; ntp < 4; ntp++) {
                    uint32_t bb4[4];
                    ldsm4t(bb4, bbase2 + ((ks * 16 + lh * 8 + l8) * BPW) * 4
                                + (wc + (ntp * 2 + lq) * 8) * 2);
                    mma_bf16(acc[0][ntp * 2],     afr[0], bb4[0], bb4[1]);
                    mma_bf16(acc[1][ntp * 2],     afr[1], bb4[0], bb4[1]);
                    mma_bf16(acc[0][ntp * 2 + 1], afr[0], bb4[2], bb4[3]);
                    mma_bf16(acc[1][ntp * 2 + 1], afr[1], bb4[2], bb4[3]);
                }
            }
            if (more) { storeB(buf ^ 1); CP_WAIT0(); __syncthreads(); }
        }
    }

    // epilogue
    #pragma unroll
    for (int mt = 0; mt < 2; mt++) {
        #pragma unroll
        for (int half = 0; half < 2; half++) {
            int r = m0 + wr + mt * 16 + gid + half * 8;
            int tok = r; bool valid = true;
            if (gather) { if (r < mcnt) tok = glist[r]; else valid = false; }
            if (!valid) continue;
            float sc = rowscale ? rowscale[tok] : 1.f;
            size_t ob = (size_t)tok * N;
            #pragma unroll
            for (int nt = 0; nt < 8; nt++) {
                int c  = n0 + wc + nt * 8 + tig * 2;
                int cb = nb0 + wc + nt * 8 + tig * 2;
                float v0 = acc[mt][nt][half * 2 + 0] + bias[cb];
                float v1 = acc[mt][nt][half * 2 + 1] + bias[cb + 1];
                if (relu_flag) { v0 = fmaxf(v0, 0.f); v1 = fmaxf(v1, 0.f); }
                v0 *= sc; v1 *= sc;
                if (res) { v0 += res[ob + c]; v1 += res[ob + c + 1]; }
                if (Cb) {
                    *(__nv_bfloat162*)&Cb[ob + c] = __floats2bfloat162_rn(v0, v1);
                } else {
                    Cf[ob + c]     = v0;
                    Cf[ob + c + 1] = v1;
                }
            }
        }
    }
}

// ---------------- flash attention: all-bf16 ldmatrix, 3 CTAs/SM ----------------
// ntp-outer score loop keeps sc live range at 8 regs -> fits 84-reg budget.
#define QKS_ 36
#define ATTN_SMEM ((128*QKS_ + 2*64*QKS_ + 2*64*QKS_) * 4)
__global__ void __launch_bounds__(256, 3)
attn_mma(const __nv_bfloat16* __restrict__ qkvb, float* __restrict__ o) {
    extern __shared__ uint32_t sm[];
    uint32_t* pS = sm;                    // [128][QKS_] Q bf16 staging, then P bf16
    uint32_t* kS = pS + 128 * QKS_;       // [2][64][QKS_]
    uint32_t* vS = kS + 2 * 64 * QKS_;    // [2][64][QKS_] natural [key][d]

    int bh = blockIdx.y;
    int b = bh % B_, h = bh / B_;
    int s0 = blockIdx.x * 128;
    int tid = threadIdx.x, lane = tid & 31, wid = tid >> 5;
    int gid = lane >> 2, tig = lane & 3;
    int l8 = lane & 7, lh = (lane >> 3) & 1, lq = lane >> 4;
    int wr = wid * 16;
    const float SC2 = 0.125f * 1.44269504f;

    uint32_t pS_a = smem_u32(pS), kS_a = smem_u32(kS), vS_a = smem_u32(vS);

    // prologue: cp.async Q + K/V tile 0
    {
        int qr = tid >> 1, qseg = tid & 1;
        const __nv_bfloat16* qp = qkvb + (size_t)((s0 + qr) * B_ + b) * 3072 + h * DK_;
        #pragma unroll
        for (int j = 0; j < 4; j++)
            cpa16(pS_a + (qr * QKS_ + qseg * 16 + j * 4) * 4,
                  (const char*)qp + qseg * 64 + j * 16);
    }
    int kr = tid >> 2, kseg = tid & 3;
    auto prefetchKV = [&](int i) {
        int buf = i & 1;
        int t = (i * 64 + kr) * B_ + b;
        const __nv_bfloat16* kp = qkvb + (size_t)t * 3072 + 1024 + h * DK_;
        const __nv_bfloat16* vp = kp + 1024;
        #pragma unroll
        for (int j = 0; j < 2; j++) {
            cpa16(kS_a + ((buf * 64 + kr) * QKS_ + kseg * 8 + j * 4) * 4,
                  (const char*)kp + kseg * 32 + j * 16);
            cpa16(vS_a + ((buf * 64 + kr) * QKS_ + kseg * 8 + j * 4) * 4,
                  (const char*)vp + kseg * 32 + j * 16);
        }
        CP_COMMIT();
    };
    prefetchKV(0);
    CP_WAIT0(); __syncthreads();

    // Q fragments via ldmatrix (own warp rows)
    uint32_t qfb[4][4];
    {
        uint32_t qbase = pS_a + ((wr + lh * 8 + l8) * QKS_) * 4;
        #pragma unroll
        for (int kk = 0; kk < 4; kk++)
            ldsm4(qfb[kk], qbase + (kk * 8 + lq * 4) * 4);
    }
    __syncwarp();

    float oacc[8][4];
    #pragma unroll
    for (int dt = 0; dt < 8; dt++)
        #pragma unroll
        for (int j = 0; j < 4; j++) oacc[dt][j] = 0.f;
    float l0 = 0.f, l1 = 0.f;
    uint32_t* pw = pS + wid * 16 * QKS_;
    uint32_t pw_a = pS_a + (wid * 16 * QKS_) * 4;

    const int NT = S_ / 64;
    for (int i = 0; i < NT; i++) {
        int buf = i & 1;
        bool more = (i + 1 < NT);
        if (more) prefetchKV(i + 1);
        uint32_t kb_a = kS_a + (buf * 64 * QKS_) * 4;
        uint32_t vb_a = vS_a + (buf * 64 * QKS_) * 4;

        // scores: ntp-outer (sc live range = 8 regs), exp + P-store per group
        #pragma unroll
        for (int ntp = 0; ntp < 4; ntp++) {
            float sc2[2][4];
            #pragma unroll
            for (int j = 0; j < 4; j++) { sc2[0][j] = 0.f; sc2[1][j] = 0.f; }
            #pragma unroll
            for (int kk = 0; kk < 4; kk++) {
                uint32_t kb4[4];
                ldsm4(kb4, kb_a + (((ntp * 2 + lq) * 8 + l8) * QKS_ + kk * 8 + lh * 4) * 4);
                mma_bf16(sc2[0], qfb[kk], kb4[0], kb4[1]);
                mma_bf16(sc2[1], qfb[kk], kb4[2], kb4[3]);
            }
            #pragma unroll
            for (int u = 0; u < 2; u++) {
                int nt = ntp * 2 + u;
                float p0 = ex2f(sc2[u][0] * SC2);
                float p1 = ex2f(sc2[u][1] * SC2);
                float p2 = ex2f(sc2[u][2] * SC2);
                float p3 = ex2f(sc2[u][3] * SC2);
                l0 += p0 + p1; l1 += p2 + p3;
                int c2 = nt * 4 + tig;
                pw[gid * QKS_ + c2]       = packbf(p0, p1);
                pw[(gid + 8) * QKS_ + c2] = packbf(p2, p3);
            }
        }
        __syncwarp();

        // P @ V: P via ldmatrix, V via ldmatrix.trans
        #pragma unroll
        for (int kk = 0; kk < 4; kk++) {
            uint32_t pa[4];
            ldsm4(pa, pw_a + ((lh * 8 + l8) * QKS_ + kk * 8 + lq * 4) * 4);
            #pragma unroll
            for (int dtp = 0; dtp < 4; dtp++) {
                uint32_t vb4[4];
                ldsm4t(vb4, vb_a + ((kk * 16 + lh * 8 + l8) * QKS_) * 4 + (dtp * 2 + lq) * 16);
                mma_bf16(oacc[dtp * 2],     pa, vb4[0], vb4[1]);
                mma_bf16(oacc[dtp * 2 + 1], pa, vb4[2], vb4[3]);
            }
        }
        if (more) { CP_WAIT0(); __syncthreads(); }
        else __syncwarp();
    }

    // final l reduction (4 threads per row)
    l0 += __shfl_xor_sync(0xffffffffu, l0, 1);
    l0 += __shfl_xor_sync(0xffffffffu, l0, 2);
    l1 += __shfl_xor_sync(0xffffffffu, l1, 1);
    l1 += __shfl_xor_sync(0xffffffffu, l1, 2);

    // write O
    float inv0 = 1.f / l0, inv1 = 1.f / l1;
    int r0 = s0 + wr + gid, r1 = r0 + 8;
    size_t o0 = (size_t)(r0 * B_ + b) * D_ + h * DK_;
    size_t o1 = (size_t)(r1 * B_ + b) * D_ + h * DK_;
    #pragma unroll
    for (int dt = 0; dt < 8; dt++) {
        int c = dt * 8 + tig * 2;
        o[o0 + c]     = oacc[dt][0] * inv0;
        o[o0 + c + 1] = oacc[dt][1] * inv0;
        o[o1 + c]     = oacc[dt][2] * inv1;
        o[o1 + c + 1] = oacc[dt][3] * inv1;
    }
}

// ---------------- route_prob_sum ----------------
__global__ void rps_kernel(float* __restrict__ dout, int out_size) {
    int e = blockIdx.x;
    __shared__ float red[256];
    float s = 0.f;
    for (int t = threadIdx.x; t < T_; t += 256) s += g_probs[t * E_ + e];
    red[threadIdx.x] = s; __syncthreads();
    for (int o = 128; o; o >>= 1) { if (threadIdx.x < o) red[threadIdx.x] += red[threadIdx.x+o]; __syncthreads(); }
    if (threadIdx.x == 0 && out_size >= OUT_TOTAL) dout[(size_t)T_ * D_ + E_ + e] = red[0];
}

// ---------------- tail outputs ----------------
__global__ void tail_kernel(float* __restrict__ dout, int out_size) {
    if (out_size < OUT_TOTAL) return;
    int i = blockIdx.x * blockDim.x + threadIdx.x;
    size_t base = (size_t)T_ * D_;
    if (i < E_) dout[base + i] = (float)g_ecount[i];
    if (i == 0) dout[base + 2 * E_] = 0.f;
    if (i < T_) dout[base + 2 * E_ + 1 + i] = g_pmax[i];
}

// ---------------- launch ----------------
extern "C" void kernel_launch(void* const* d_in, const int* in_sizes, int n_in,
                              void* d_out, int out_size) {
    const float* x      = (const float*)d_in[0];
    const float* ln1_g  = (const float*)d_in[1];
    const float* ln1_b  = (const float*)d_in[2];
    const float* ln2_g  = (const float*)d_in[3];
    const float* ln2_b  = (const float*)d_in[4];
    const float* wq     = (const float*)d_in[5];
    const float* bq     = (const float*)d_in[6];
    const float* wk     = (const float*)d_in[7];
    const float* bk     = (const float*)d_in[8];
    const float* wv     = (const float*)d_in[9];
    const float* bv     = (const float*)d_in[10];
    const float* wo     = (const float*)d_in[11];
    const float* bo     = (const float*)d_in[12];
    const float* w_gate = (const float*)d_in[13];
    const float* b_gate = (const float*)d_in[14];
    const float* w1     = (const float*)d_in[15];
    const float* b1     = (const float*)d_in[16];
    const float* w2     = (const float*)d_in[17];
    const float* b2     = (const float*)d_in[18];
    float* out = (float*)d_out;

    float *o, *x2, *pmaxp;
    __nv_bfloat16 *z1b, *qkvb, *z2b, *hb;
    int *etok, *ecount;
    cudaGetSymbolAddress((void**)&z1b,  g_z1b);
    cudaGetSymbolAddress((void**)&qkvb, g_qkvb);
    cudaGetSymbolAddress((void**)&o,    g_o);
    cudaGetSymbolAddress((void**)&x2,   g_x2);
    cudaGetSymbolAddress((void**)&z2b,  g_z2b);
    cudaGetSymbolAddress((void**)&hb,   g_hb);
    cudaGetSymbolAddress((void**)&etok,   g_etok);
    cudaGetSymbolAddress((void**)&ecount, g_ecount);
    cudaGetSymbolAddress((void**)&pmaxp,  g_pmax);

    cudaFuncSetAttribute(attn_mma, cudaFuncAttributeMaxDynamicSharedMemorySize, ATTN_SMEM);

    init_kernel<<<1, 32>>>();

    // LN1 (bf16 only)
    ln_kernel<<<T_, 256>>>(x, ln1_g, ln1_b, z1b);

    // fused QKV projection (bf16, ldmatrix)
    mma_gemm<2><<<dim3(3072/128, T_/128, 1), 256>>>(
        (const char*)z1b, wq, wk, wv, bq, bk, bv,
        nullptr, nullptr, nullptr, qkvb, T_, 3072, D_, D_, nullptr, nullptr, 0);

    // attention (all-bf16, ldmatrix, 3 CTA/SM)
    attn_mma<<<dim3(S_/128, B_*H_), 256, ATTN_SMEM>>>(qkvb, o);

    // output projection + residual (tf32, precision-critical for routing)
    mma_gemm<4><<<dim3(D_/128, T_/128, 1), 256>>>(
        (const char*)o, wo, nullptr, nullptr, bo, nullptr, nullptr,
        x, nullptr, x2, nullptr, T_, D_, D_, D_, nullptr, nullptr, 0);

    // fused LN2 + gate/routing
    ln2_gate_kernel<<<T_, 256>>>(x2, ln2_g, ln2_b, w_gate, b_gate, z2b);

    // MoE FFN (grouped by expert, bf16, ldmatrix)
    mma_gemm<2><<<dim3(F_/128, T_/128, E_), 256>>>(
        (const char*)z2b, w1, nullptr, nullptr, b1, nullptr, nullptr,
        nullptr, nullptr, nullptr, hb, T_, F_, F_, D_, etok, ecount, 1);
    mma_gemm<2><<<dim3(D_/128, T_/128, E_), 256>>>(
        (const char*)hb, w2, nullptr, nullptr, b2, nullptr, nullptr,
        x2, pmaxp, out, nullptr, T_, D_, D_, F_, etok, ecount, 0);

    // aux outputs
    rps_kernel<<<E_, 256>>>(out, out_size);
    tail_kernel<<<(T_ + 255) / 256, 256>>>(out, out_size);
}

// round 15
// speedup vs baseline: 1.7615x; 1.0233x over previous
#include <cuda_runtime.h>
#include <cuda_bf16.h>
#include <math.h>
#include <stdint.h>

// Problem dims
#define S_  2048
#define B_  2
#define D_  1024
#define H_  16
#define DK_ 64
#define E_  8
#define F_  4096
#define T_  (S_*B_)          // 4096 tokens
#define OUT_TOTAL (T_*D_ + E_ + E_ + 1 + T_)

// ---------------- scratch (device globals) ----------------
__device__ __nv_bfloat16 g_z1b[T_*D_];
__device__ __nv_bfloat16 g_qkvb[(size_t)T_*3072];   // bf16 q|k|v
__device__ float g_o [T_*D_];
__device__ float g_x2[T_*D_];
__device__ __nv_bfloat16 g_z2b[T_*D_];
__device__ __nv_bfloat16 g_hb[(size_t)T_*F_];
__device__ float g_probs[T_*E_];
__device__ float g_pmax[T_];
__device__ int   g_etok[E_*T_];
__device__ int   g_ecount[E_];

__device__ __forceinline__ uint32_t packbf(float lo, float hi) {
    __nv_bfloat162 t = __floats2bfloat162_rn(lo, hi);
    return *(uint32_t*)&t;
}
__device__ __forceinline__ float ex2f(float x) {
    float y; asm("ex2.approx.f32 %0, %1;" : "=f"(y) : "f"(x)); return y;
}
__device__ __forceinline__ void mma_bf16(float* c, const uint32_t* a, uint32_t b0, uint32_t b1) {
    asm volatile("mma.sync.aligned.m16n8k16.row.col.f32.bf16.bf16.f32 "
        "{%0,%1,%2,%3}, {%4,%5,%6,%7}, {%8,%9}, {%0,%1,%2,%3};"
        : "+f"(c[0]), "+f"(c[1]), "+f"(c[2]), "+f"(c[3])
        : "r"(a[0]), "r"(a[1]), "r"(a[2]), "r"(a[3]), "r"(b0), "r"(b1));
}
__device__ __forceinline__ void mma_tf32(float* c, const uint32_t* a, uint32_t b0, uint32_t b1) {
    asm volatile("mma.sync.aligned.m16n8k8.row.col.f32.tf32.tf32.f32 "
        "{%0,%1,%2,%3}, {%4,%5,%6,%7}, {%8,%9}, {%0,%1,%2,%3};"
        : "+f"(c[0]), "+f"(c[1]), "+f"(c[2]), "+f"(c[3])
        : "r"(a[0]), "r"(a[1]), "r"(a[2]), "r"(a[3]), "r"(b0), "r"(b1));
}
__device__ __forceinline__ void ldsm4(uint32_t* r, uint32_t addr) {
    asm volatile("ldmatrix.sync.aligned.m8n8.x4.shared.b16 {%0,%1,%2,%3}, [%4];"
        : "=r"(r[0]), "=r"(r[1]), "=r"(r[2]), "=r"(r[3]) : "r"(addr));
}
__device__ __forceinline__ void ldsm4t(uint32_t* r, uint32_t addr) {
    asm volatile("ldmatrix.sync.aligned.m8n8.x4.trans.shared.b16 {%0,%1,%2,%3}, [%4];"
        : "=r"(r[0]), "=r"(r[1]), "=r"(r[2]), "=r"(r[3]) : "r"(addr));
}
__device__ __forceinline__ uint32_t lds32(const char* p) {
    return *(const uint32_t*)p;
}
__device__ __forceinline__ uint32_t smem_u32(const void* p) {
    uint32_t a;
    asm("{ .reg .u64 t; cvta.to.shared.u64 t, %1; cvt.u32.u64 %0, t; }" : "=r"(a) : "l"(p));
    return a;
}
__device__ __forceinline__ void cpa16(uint32_t dst, const void* src) {
    asm volatile("cp.async.cg.shared.global [%0], [%1], 16;" :: "r"(dst), "l"(src));
}
__device__ __forceinline__ void cpa16p(uint32_t dst, const void* src, int sz) {
    asm volatile("cp.async.cg.shared.global [%0], [%1], 16, %2;" :: "r"(dst), "l"(src), "r"(sz));
}
#define CP_COMMIT() asm volatile("cp.async.commit_group;" ::: "memory")
#define CP_WAIT0()  asm volatile("cp.async.wait_group 0;" ::: "memory")

// ---------------- init ----------------
__global__ void init_kernel() {
    int i = threadIdx.x;
    if (i < E_) g_ecount[i] = 0;
}

// ---------------- LayerNorm (LN1: bf16 out only) ----------------
__global__ void ln_kernel(const float* __restrict__ x,
                          const float* __restrict__ gam,
                          const float* __restrict__ bet,
                          __nv_bfloat16* __restrict__ zb) {
    int t = blockIdx.x;
    const float* row = x + (size_t)t * D_;
    __shared__ float wsum[8], wsq[8];
    int tid = threadIdx.x, lane = tid & 31, wid = tid >> 5;
    float s = 0.f, sq = 0.f;
    #pragma unroll
    for (int i = 0; i < 4; i++) {
        float v = row[tid + i * 256];
        s += v; sq += v * v;
    }
    #pragma unroll
    for (int off = 16; off; off >>= 1) {
        s  += __shfl_xor_sync(0xffffffffu, s,  off);
        sq += __shfl_xor_sync(0xffffffffu, sq, off);
    }
    if (lane == 0) { wsum[wid] = s; wsq[wid] = sq; }
    __syncthreads();
    float ts = 0.f, tq = 0.f;
    #pragma unroll
    for (int w = 0; w < 8; w++) { ts += wsum[w]; tq += wsq[w]; }
    float mean = ts * (1.f / D_);
    float var  = tq * (1.f / D_) - mean * mean;
    float inv  = rsqrtf(var + 1e-5f);
    #pragma unroll
    for (int i = 0; i < 4; i++) {
        int c = tid + i * 256;
        float v = (row[c] - mean) * inv * gam[c] + bet[c];
        zb[(size_t)t * D_ + c] = __float2bfloat16(v);
    }
}

// ---------------- fused LN2 + gate/routing ----------------
__global__ void ln2_gate_kernel(const float* __restrict__ x,
                                const float* __restrict__ gam,
                                const float* __restrict__ bet,
                                const float* __restrict__ wg,
                                const float* __restrict__ bg,
                                __nv_bfloat16* __restrict__ zb) {
    int t = blockIdx.x;
    const float* row = x + (size_t)t * D_;
    __shared__ float wsum[8], wsq[8];
    __shared__ float wlog[8][E_];
    int tid = threadIdx.x, lane = tid & 31, wid = tid >> 5;
    float s = 0.f, sq = 0.f;
    float xv[4];
    #pragma unroll
    for (int i = 0; i < 4; i++) {
        xv[i] = row[tid + i * 256];
        s += xv[i]; sq += xv[i] * xv[i];
    }
    #pragma unroll
    for (int off = 16; off; off >>= 1) {
        s  += __shfl_xor_sync(0xffffffffu, s,  off);
        sq += __shfl_xor_sync(0xffffffffu, sq, off);
    }
    if (lane == 0) { wsum[wid] = s; wsq[wid] = sq; }
    __syncthreads();
    float ts = 0.f, tq = 0.f;
    #pragma unroll
    for (int w = 0; w < 8; w++) { ts += wsum[w]; tq += wsq[w]; }
    float mean = ts * (1.f / D_);
    float var  = tq * (1.f / D_) - mean * mean;
    float inv  = rsqrtf(var + 1e-5f);
    float part[E_];
    #pragma unroll
    for (int e = 0; e < E_; e++) part[e] = 0.f;
    #pragma unroll
    for (int i = 0; i < 4; i++) {
        int c = tid + i * 256;
        float v = (xv[i] - mean) * inv * gam[c] + bet[c];
        zb[(size_t)t * D_ + c] = __float2bfloat16(v);
        const float4* wgp = (const float4*)&wg[(size_t)c * E_];
        float4 w0 = wgp[0], w1 = wgp[1];
        part[0] += v * w0.x; part[1] += v * w0.y; part[2] += v * w0.z; part[3] += v * w0.w;
        part[4] += v * w1.x; part[5] += v * w1.y; part[6] += v * w1.z; part[7] += v * w1.w;
    }
    #pragma unroll
    for (int e = 0; e < E_; e++) {
        #pragma unroll
        for (int off = 16; off; off >>= 1)
            part[e] += __shfl_xor_sync(0xffffffffu, part[e], off);
    }
    if (lane == 0) {
        #pragma unroll
        for (int e = 0; e < E_; e++) wlog[wid][e] = part[e];
    }
    __syncthreads();
    if (tid == 0) {
        float lg[E_];
        #pragma unroll
        for (int e = 0; e < E_; e++) {
            float a = bg[e];
            #pragma unroll
            for (int w = 0; w < 8; w++) a += wlog[w][e];
            lg[e] = a;
        }
        float mx = lg[0]; int am = 0;
        #pragma unroll
        for (int e = 1; e < E_; e++) if (lg[e] > mx) { mx = lg[e]; am = e; }
        float pr[E_], sum = 0.f;
        #pragma unroll
        for (int e = 0; e < E_; e++) { pr[e] = expf(lg[e] - mx); sum += pr[e]; }
        float invs = 1.f / sum;
        #pragma unroll
        for (int e = 0; e < E_; e++) g_probs[t * E_ + e] = pr[e] * invs;
        g_pmax[t] = pr[am] * invs;
        int pos = atomicAdd(&g_ecount[am], 1);
        g_etok[am * T_ + pos] = t;
    }
}

// ---------------- mma.sync GEMM (unchanged from R14) ----------------
#define RB 80   // smem A row bytes
#define BPW 68  // bf16 B row stride (words)
template<int EB>
__global__ void __launch_bounds__(256)
mma_gemm(const char* __restrict__ A,
         const float* __restrict__ B0, const float* __restrict__ B1, const float* __restrict__ B2,
         const float* __restrict__ bias0, const float* __restrict__ bias1, const float* __restrict__ bias2,
         const float* __restrict__ res, const float* __restrict__ rowscale,
         float* __restrict__ Cf, __nv_bfloat16* __restrict__ Cb,
         int M, int N, int Nb, int K,
         const int* __restrict__ gather, const int* __restrict__ gcount,
         int relu_flag) {
    constexpr int KC = (EB == 4) ? 16 : 32;
    __shared__ __align__(16) char smraw[2 * 128 * RB + 17408];
    char* smA = smraw;
    uint32_t* smB = (uint32_t*)(smraw + 2 * 128 * RB);

    int e  = blockIdx.z;
    int m0 = blockIdx.y * 128, n0 = blockIdx.x * 128;
    const float* Bsrc; const float* bias; int nb0;
    if (B1) {
        int part = n0 >> 10; nb0 = n0 & 1023;
        Bsrc = part == 0 ? B0 : (part == 1 ? B1 : B2);
        bias = part == 0 ? bias0 : (part == 1 ? bias1 : bias2);
    } else { Bsrc = B0; bias = bias0; nb0 = n0; }
    const int* glist = nullptr; int mcnt = M;
    if (gather) {
        glist = gather + (size_t)e * T_;
        mcnt  = gcount[e];
        if (m0 >= mcnt) return;
        Bsrc += (size_t)e * K * Nb;
        bias += (size_t)e * Nb;
    }
    int tid = threadIdx.x;
    int wid = tid >> 5, lane = tid & 31;

    int srow = tid >> 2, c4 = tid & 3;
    int rows[2] = { srow, srow + 64 };
    const char* aptr[2]; int asz[2];
    #pragma unroll
    for (int u = 0; u < 2; u++) {
        int rr = m0 + rows[u]; int tok = rr; asz[u] = 16;
        if (gather) { if (rr < mcnt) tok = glist[rr]; else { asz[u] = 0; tok = 0; } }
        aptr[u] = A + (size_t)tok * K * EB + c4 * 16;
    }

    int wm = wid & 3, wn = wid >> 2;
    int wr = wm * 32, wc = wn * 64;
    int gid = lane >> 2, tig = lane & 3;

    float acc[2][8][4];
    #pragma unroll
    for (int mt = 0; mt < 2; mt++)
        #pragma unroll
        for (int nt = 0; nt < 8; nt++)
            #pragma unroll
            for (int j = 0; j < 4; j++) acc[mt][nt][j] = 0.f;

    int nch = K / KC;
    uint32_t sA_a = smem_u32(smA), sB_a = smem_u32(smB);

    if (EB == 4) {
        const float* bbase = Bsrc + nb0 + lane * 4;
        auto prefetch = [&](int i) {
            int buf = i & 1;
            size_t kb = (size_t)i * 64;
            cpa16(sA_a + buf * 128 * RB + rows[0] * RB + c4 * 16, aptr[0] + kb);
            cpa16(sA_a + buf * 128 * RB + rows[1] * RB + c4 * 16, aptr[1] + kb);
            int k0 = i * KC;
            uint32_t dB = sB_a + buf * 16 * 136 * 4;
            cpa16(dB + (wid * 136 + lane * 4) * 4,       bbase + (size_t)(k0 + wid) * Nb);
            cpa16(dB + ((wid + 8) * 136 + lane * 4) * 4, bbase + (size_t)(k0 + wid + 8) * Nb);
            CP_COMMIT();
        };
        prefetch(0);
        CP_WAIT0(); __syncthreads();
        for (int i = 0; i < nch; i++) {
            int buf = i & 1;
            bool more = (i + 1 < nch);
            if (more) prefetch(i + 1);
            const uint32_t* bb = smB + buf * 16 * 136;
            const char* ab = smA + buf * 128 * RB;
            #pragma unroll
            for (int ks = 0; ks < 2; ks++) {
                uint32_t afr[2][4];
                int kb0 = (ks * 8 + tig) * 4;
                #pragma unroll
                for (int mt = 0; mt < 2; mt++) {
                    const char* ap = &ab[(wr + mt * 16 + gid) * RB + kb0];
                    afr[mt][0] = lds32(ap);
                    afr[mt][1] = lds32(ap + 8 * RB);
                    afr[mt][2] = lds32(ap + 16);
                    afr[mt][3] = lds32(ap + 8 * RB + 16);
                }
                int krow = ks * 8 + tig;
                #pragma unroll
                for (int nt = 0; nt < 8; nt++) {
                    uint32_t b0 = bb[krow * 136 + wc + nt * 8 + gid];
                    uint32_t b1 = bb[(krow + 4) * 136 + wc + nt * 8 + gid];
                    mma_tf32(acc[0][nt], afr[0], b0, b1);
                    mma_tf32(acc[1][nt], afr[1], b0, b1);
                }
            }
            if (more) { CP_WAIT0(); __syncthreads(); }
        }
    } else {
        int bk = tid >> 4, bq = (tid & 15) * 4;
        float4 rb[4];
        auto prefetchA = [&](int i) {
            int buf = i & 1;
            size_t kb = (size_t)i * 64;
            cpa16p(sA_a + buf * 128 * RB + rows[0] * RB + c4 * 16, aptr[0] + kb, asz[0]);
            cpa16p(sA_a + buf * 128 * RB + rows[1] * RB + c4 * 16, aptr[1] + kb, asz[1]);
            CP_COMMIT();
        };
        auto loadB = [&](int i) {
            int k0 = i * KC;
            const float* r0 = Bsrc + (size_t)(k0 + bk) * Nb + nb0;
            const float* r1 = Bsrc + (size_t)(k0 + bk + 16) * Nb + nb0;
            rb[0] = *(const float4*)(r0 + bq);
            rb[1] = *(const float4*)(r0 + bq + 64);
            rb[2] = *(const float4*)(r1 + bq);
            rb[3] = *(const float4*)(r1 + bq + 64);
        };
        auto storeB = [&](int buf) {
            uint32_t* d0 = smB + buf * 32 * BPW + bk * BPW;
            uint32_t* d1 = d0 + 16 * BPW;
            *(uint2*)&d0[bq / 2]      = make_uint2(packbf(rb[0].x, rb[0].y), packbf(rb[0].z, rb[0].w));
            *(uint2*)&d0[bq / 2 + 32] = make_uint2(packbf(rb[1].x, rb[1].y), packbf(rb[1].z, rb[1].w));
            *(uint2*)&d1[bq / 2]      = make_uint2(packbf(rb[2].x, rb[2].y), packbf(rb[2].z, rb[2].w));
            *(uint2*)&d1[bq / 2 + 32] = make_uint2(packbf(rb[3].x, rb[3].y), packbf(rb[3].z, rb[3].w));
        };
        int l8 = lane & 7, lh = (lane >> 3) & 1, lq = lane >> 4;
        prefetchA(0); loadB(0); storeB(0);
        CP_WAIT0(); __syncthreads();
        for (int i = 0; i < nch; i++) {
            int buf = i & 1;
            bool more = (i + 1 < nch);
            if (more) { prefetchA(i + 1); loadB(i + 1); }
            uint32_t abase = sA_a + buf * 128 * RB;
            uint32_t bbase2 = sB_a + (buf * 32 * BPW) * 4;
            #pragma unroll
            for (int ks = 0; ks < 2; ks++) {
                uint32_t afr[2][4];
                #pragma unroll
                for (int mt = 0; mt < 2; mt++)
                    ldsm4(afr[mt], abase + (wr + mt * 16 + lh * 8 + l8) * RB + ks * 32 + lq * 16);
                #pragma unroll
                for (int ntp = 0; ntp < 4; ntp++) {
                    uint32_t bb4[4];
                    ldsm4t(bb4, bbase2 + ((ks * 16 + lh * 8 + l8) * BPW) * 4
                                + (wc + (ntp * 2 + lq) * 8) * 2);
                    mma_bf16(acc[0][ntp * 2],     afr[0], bb4[0], bb4[1]);
                    mma_bf16(acc[1][ntp * 2],     afr[1], bb4[0], bb4[1]);
                    mma_bf16(acc[0][ntp * 2 + 1], afr[0], bb4[2], bb4[3]);
                    mma_bf16(acc[1][ntp * 2 + 1], afr[1], bb4[2], bb4[3]);
                }
            }
            if (more) { storeB(buf ^ 1); CP_WAIT0(); __syncthreads(); }
        }
    }

    // epilogue
    #pragma unroll
    for (int mt = 0; mt < 2; mt++) {
        #pragma unroll
        for (int half = 0; half < 2; half++) {
            int r = m0 + wr + mt * 16 + gid + half * 8;
            int tok = r; bool valid = true;
            if (gather) { if (r < mcnt) tok = glist[r]; else valid = false; }
            if (!valid) continue;
            float sc = rowscale ? rowscale[tok] : 1.f;
            size_t ob = (size_t)tok * N;
            #pragma unroll
            for (int nt = 0; nt < 8; nt++) {
                int c  = n0 + wc + nt * 8 + tig * 2;
                int cb = nb0 + wc + nt * 8 + tig * 2;
                float v0 = acc[mt][nt][half * 2 + 0] + bias[cb];
                float v1 = acc[mt][nt][half * 2 + 1] + bias[cb + 1];
                if (relu_flag) { v0 = fmaxf(v0, 0.f); v1 = fmaxf(v1, 0.f); }
                v0 *= sc; v1 *= sc;
                if (res) { v0 += res[ob + c]; v1 += res[ob + c + 1]; }
                if (Cb) {
                    *(__nv_bfloat162*)&Cb[ob + c] = __floats2bfloat162_rn(v0, v1);
                } else {
                    Cf[ob + c]     = v0;
                    Cf[ob + c + 1] = v1;
                }
            }
        }
    }
}

// ---------------- flash attention: Q-tile 256, all-bf16 ldmatrix ----------------
// 8 warps; each warp owns rows {wid*16..} and {128+wid*16..} (mt=0,1).
// K/V fragments loaded once per tile, reused for both row blocks.
#define QKS_ 36
#define ATTN_SMEM ((256*QKS_ + 2*64*QKS_ + 2*64*QKS_) * 4)
__global__ void __launch_bounds__(256, 2)
attn_mma(const __nv_bfloat16* __restrict__ qkvb, float* __restrict__ o) {
    extern __shared__ uint32_t sm[];
    uint32_t* pS = sm;                    // [256][QKS_] Q bf16 staging, then P bf16
    uint32_t* kS = pS + 256 * QKS_;       // [2][64][QKS_]
    uint32_t* vS = kS + 2 * 64 * QKS_;    // [2][64][QKS_] natural [key][d]

    int bh = blockIdx.y;
    int b = bh % B_, h = bh / B_;
    int s0 = blockIdx.x * 256;
    int tid = threadIdx.x, lane = tid & 31, wid = tid >> 5;
    int gid = lane >> 2, tig = lane & 3;
    int l8 = lane & 7, lh = (lane >> 3) & 1, lq = lane >> 4;
    int wr = wid * 16;
    const float SC2 = 0.125f * 1.44269504f;

    uint32_t pS_a = smem_u32(pS), kS_a = smem_u32(kS), vS_a = smem_u32(vS);

    // prologue: cp.async Q (256 rows, 1 thread/row) + K/V tile 0
    {
        const __nv_bfloat16* qp = qkvb + (size_t)((s0 + tid) * B_ + b) * 3072 + h * DK_;
        #pragma unroll
        for (int j = 0; j < 8; j++)
            cpa16(pS_a + (tid * QKS_ + j * 4) * 4, (const char*)qp + j * 16);
    }
    int kr = tid >> 2, kseg = tid & 3;
    auto prefetchKV = [&](int i) {
        int buf = i & 1;
        int t = (i * 64 + kr) * B_ + b;
        const __nv_bfloat16* kp = qkvb + (size_t)t * 3072 + 1024 + h * DK_;
        const __nv_bfloat16* vp = kp + 1024;
        #pragma unroll
        for (int j = 0; j < 2; j++) {
            cpa16(kS_a + ((buf * 64 + kr) * QKS_ + kseg * 8 + j * 4) * 4,
                  (const char*)kp + kseg * 32 + j * 16);
            cpa16(vS_a + ((buf * 64 + kr) * QKS_ + kseg * 8 + j * 4) * 4,
                  (const char*)vp + kseg * 32 + j * 16);
        }
        CP_COMMIT();
    };
    prefetchKV(0);
    CP_WAIT0(); __syncthreads();

    // Q fragments for both row blocks
    uint32_t qfb[2][4][4];
    #pragma unroll
    for (int mt = 0; mt < 2; mt++) {
        uint32_t qbase = pS_a + ((mt * 128 + wr + lh * 8 + l8) * QKS_) * 4;
        #pragma unroll
        for (int kk = 0; kk < 4; kk++)
            ldsm4(qfb[mt][kk], qbase + (kk * 8 + lq * 4) * 4);
    }
    __syncwarp();

    float oacc[2][8][4];
    #pragma unroll
    for (int mt = 0; mt < 2; mt++)
        #pragma unroll
        for (int dt = 0; dt < 8; dt++)
            #pragma unroll
            for (int j = 0; j < 4; j++) oacc[mt][dt][j] = 0.f;
    float lsum[2][2] = {{0.f, 0.f}, {0.f, 0.f}};
    uint32_t pw_a[2];
    uint32_t* pw[2];
    #pragma unroll
    for (int mt = 0; mt < 2; mt++) {
        pw[mt] = pS + (mt * 128 + wr) * QKS_;
        pw_a[mt] = pS_a + ((mt * 128 + wr) * QKS_) * 4;
    }

    const int NT = S_ / 64;
    for (int i = 0; i < NT; i++) {
        int buf = i & 1;
        bool more = (i + 1 < NT);
        if (more) prefetchKV(i + 1);
        uint32_t kb_a = kS_a + (buf * 64 * QKS_) * 4;
        uint32_t vb_a = vS_a + (buf * 64 * QKS_) * 4;

        // scores: ntp-outer; K fragment shared across both row blocks
        #pragma unroll
        for (int ntp = 0; ntp < 4; ntp++) {
            float sc2[2][2][4];
            #pragma unroll
            for (int mt = 0; mt < 2; mt++)
                #pragma unroll
                for (int j = 0; j < 4; j++) { sc2[mt][0][j] = 0.f; sc2[mt][1][j] = 0.f; }
            #pragma unroll
            for (int kk = 0; kk < 4; kk++) {
                uint32_t kb4[4];
                ldsm4(kb4, kb_a + (((ntp * 2 + lq) * 8 + l8) * QKS_ + kk * 8 + lh * 4) * 4);
                #pragma unroll
                for (int mt = 0; mt < 2; mt++) {
                    mma_bf16(sc2[mt][0], qfb[mt][kk], kb4[0], kb4[1]);
                    mma_bf16(sc2[mt][1], qfb[mt][kk], kb4[2], kb4[3]);
                }
            }
            #pragma unroll
            for (int mt = 0; mt < 2; mt++) {
                #pragma unroll
                for (int u = 0; u < 2; u++) {
                    int nt = ntp * 2 + u;
                    float p0 = ex2f(sc2[mt][u][0] * SC2);
                    float p1 = ex2f(sc2[mt][u][1] * SC2);
                    float p2 = ex2f(sc2[mt][u][2] * SC2);
                    float p3 = ex2f(sc2[mt][u][3] * SC2);
                    lsum[mt][0] += p0 + p1; lsum[mt][1] += p2 + p3;
                    int c2 = nt * 4 + tig;
                    pw[mt][gid * QKS_ + c2]       = packbf(p0, p1);
                    pw[mt][(gid + 8) * QKS_ + c2] = packbf(p2, p3);
                }
            }
        }
        __syncwarp();

        // P @ V: V fragment shared across both row blocks
        #pragma unroll
        for (int kk = 0; kk < 4; kk++) {
            uint32_t pa[2][4];
            #pragma unroll
            for (int mt = 0; mt < 2; mt++)
                ldsm4(pa[mt], pw_a[mt] + ((lh * 8 + l8) * QKS_ + kk * 8 + lq * 4) * 4);
            #pragma unroll
            for (int dtp = 0; dtp < 4; dtp++) {
                uint32_t vb4[4];
                ldsm4t(vb4, vb_a + ((kk * 16 + lh * 8 + l8) * QKS_) * 4 + (dtp * 2 + lq) * 16);
                #pragma unroll
                for (int mt = 0; mt < 2; mt++) {
                    mma_bf16(oacc[mt][dtp * 2],     pa[mt], vb4[0], vb4[1]);
                    mma_bf16(oacc[mt][dtp * 2 + 1], pa[mt], vb4[2], vb4[3]);
                }
            }
        }
        if (more) { CP_WAIT0(); __syncthreads(); }
        else __syncwarp();
    }

    // final l reduction + write O
    #pragma unroll
    for (int mt = 0; mt < 2; mt++) {
        float l0 = lsum[mt][0], l1 = lsum[mt][1];
        l0 += __shfl_xor_sync(0xffffffffu, l0, 1);
        l0 += __shfl_xor_sync(0xffffffffu, l0, 2);
        l1 += __shfl_xor_sync(0xffffffffu, l1, 1);
        l1 += __shfl_xor_sync(0xffffffffu, l1, 2);
        float inv0 = 1.f / l0, inv1 = 1.f / l1;
        int r0 = s0 + mt * 128 + wr + gid, r1 = r0 + 8;
        size_t o0 = (size_t)(r0 * B_ + b) * D_ + h * DK_;
        size_t o1 = (size_t)(r1 * B_ + b) * D_ + h * DK_;
        #pragma unroll
        for (int dt = 0; dt < 8; dt++) {
            int c = dt * 8 + tig * 2;
            o[o0 + c]     = oacc[mt][dt][0] * inv0;
            o[o0 + c + 1] = oacc[mt][dt][1] * inv0;
            o[o1 + c]     = oacc[mt][dt][2] * inv1;
            o[o1 + c + 1] = oacc[mt][dt][3] * inv1;
        }
    }
}

// ---------------- route_prob_sum ----------------
__global__ void rps_kernel(float* __restrict__ dout, int out_size) {
    int e = blockIdx.x;
    __shared__ float red[256];
    float s = 0.f;
    for (int t = threadIdx.x; t < T_; t += 256) s += g_probs[t * E_ + e];
    red[threadIdx.x] = s; __syncthreads();
    for (int o = 128; o; o >>= 1) { if (threadIdx.x < o) red[threadIdx.x] += red[threadIdx.x+o]; __syncthreads(); }
    if (threadIdx.x == 0 && out_size >= OUT_TOTAL) dout[(size_t)T_ * D_ + E_ + e] = red[0];
}

// ---------------- tail outputs ----------------
__global__ void tail_kernel(float* __restrict__ dout, int out_size) {
    if (out_size < OUT_TOTAL) return;
    int i = blockIdx.x * blockDim.x + threadIdx.x;
    size_t base = (size_t)T_ * D_;
    if (i < E_) dout[base + i] = (float)g_ecount[i];
    if (i == 0) dout[base + 2 * E_] = 0.f;
    if (i < T_) dout[base + 2 * E_ + 1 + i] = g_pmax[i];
}

// ---------------- launch ----------------
extern "C" void kernel_launch(void* const* d_in, const int* in_sizes, int n_in,
                              void* d_out, int out_size) {
    const float* x      = (const float*)d_in[0];
    const float* ln1_g  = (const float*)d_in[1];
    const float* ln1_b  = (const float*)d_in[2];
    const float* ln2_g  = (const float*)d_in[3];
    const float* ln2_b  = (const float*)d_in[4];
    const float* wq     = (const float*)d_in[5];
    const float* bq     = (const float*)d_in[6];
    const float* wk     = (const float*)d_in[7];
    const float* bk     = (const float*)d_in[8];
    const float* wv     = (const float*)d_in[9];
    const float* bv     = (const float*)d_in[10];
    const float* wo     = (const float*)d_in[11];
    const float* bo     = (const float*)d_in[12];
    const float* w_gate = (const float*)d_in[13];
    const float* b_gate = (const float*)d_in[14];
    const float* w1     = (const float*)d_in[15];
    const float* b1     = (const float*)d_in[16];
    const float* w2     = (const float*)d_in[17];
    const float* b2     = (const float*)d_in[18];
    float* out = (float*)d_out;

    float *o, *x2, *pmaxp;
    __nv_bfloat16 *z1b, *qkvb, *z2b, *hb;
    int *etok, *ecount;
    cudaGetSymbolAddress((void**)&z1b,  g_z1b);
    cudaGetSymbolAddress((void**)&qkvb, g_qkvb);
    cudaGetSymbolAddress((void**)&o,    g_o);
    cudaGetSymbolAddress((void**)&x2,   g_x2);
    cudaGetSymbolAddress((void**)&z2b,  g_z2b);
    cudaGetSymbolAddress((void**)&hb,   g_hb);
    cudaGetSymbolAddress((void**)&etok,   g_etok);
    cudaGetSymbolAddress((void**)&ecount, g_ecount);
    cudaGetSymbolAddress((void**)&pmaxp,  g_pmax);

    cudaFuncSetAttribute(attn_mma, cudaFuncAttributeMaxDynamicSharedMemorySize, ATTN_SMEM);

    init_kernel<<<1, 32>>>();

    // LN1 (bf16 only)
    ln_kernel<<<T_, 256>>>(x, ln1_g, ln1_b, z1b);

    // fused QKV projection (bf16, ldmatrix)
    mma_gemm<2><<<dim3(3072/128, T_/128, 1), 256>>>(
        (const char*)z1b, wq, wk, wv, bq, bk, bv,
        nullptr, nullptr, nullptr, qkvb, T_, 3072, D_, D_, nullptr, nullptr, 0);

    // attention (Q-tile 256, all-bf16, ldmatrix)
    attn_mma<<<dim3(S_/256, B_*H_), 256, ATTN_SMEM>>>(qkvb, o);

    // output projection + residual (tf32, precision-critical for routing)
    mma_gemm<4><<<dim3(D_/128, T_/128, 1), 256>>>(
        (const char*)o, wo, nullptr, nullptr, bo, nullptr, nullptr,
        x, nullptr, x2, nullptr, T_, D_, D_, D_, nullptr, nullptr, 0);

    // fused LN2 + gate/routing
    ln2_gate_kernel<<<T_, 256>>>(x2, ln2_g, ln2_b, w_gate, b_gate, z2b);

    // MoE FFN (grouped by expert, bf16, ldmatrix)
    mma_gemm<2><<<dim3(F_/128, T_/128, E_), 256>>>(
        (const char*)z2b, w1, nullptr, nullptr, b1, nullptr, nullptr,
        nullptr, nullptr, nullptr, hb, T_, F_, F_, D_, etok, ecount, 1);
    mma_gemm<2><<<dim3(D_/128, T_/128, E_), 256>>>(
        (const char*)hb, w2, nullptr, nullptr, b2, nullptr, nullptr,
        x2, pmaxp, out, nullptr, T_, D_, D_, F_, etok, ecount, 0);

    // aux outputs
    rps_kernel<<<E_, 256>>>(out, out_size);
    tail_kernel<<<(T_ + 255) / 256, 256>>>(out, out_size);
}